// round 1
// baseline (speedup 1.0000x reference)
#include <cuda_runtime.h>
#include <math.h>

// Problem constants
#define BATCH 8
#define CH    192          // C
#define QKVC  576          // 3C
#define HH    128
#define WW2   128
#define HW    16384
#define HEADS 4
#define CPH   48           // C / HEADS

// ---------------- scratch (static device memory; no allocs) ----------------
__device__ float g_qkv0[(size_t)BATCH * QKVC * HW];   // after 1x1 conv
__device__ float g_qkv1[(size_t)BATCH * QKVC * HW];   // after depthwise conv
__device__ float g_ctx [(size_t)BATCH * CH   * HW];   // attention output
__device__ float g_sumsq[BATCH * 2 * CH];             // q: [0,192), k: [192,384) per batch
__device__ float g_S[BATCH * HEADS * CPH * CPH];      // raw dot products
__device__ float g_A[BATCH * HEADS * CPH * CPH];      // softmax result
__device__ float g_temp[BATCH * HEADS];

// ---------------- packed fp32x2 helpers (Blackwell FFMA2) ----------------
__device__ __forceinline__ unsigned long long ffma2(unsigned long long a,
                                                    unsigned long long b,
                                                    unsigned long long c) {
    unsigned long long d;
    asm("fma.rn.f32x2 %0, %1, %2, %3;" : "=l"(d) : "l"(a), "l"(b), "l"(c));
    return d;
}
__device__ __forceinline__ unsigned long long pack2(float lo, float hi) {
    unsigned long long d;
    asm("mov.b64 %0, {%1, %2};" : "=l"(d) : "f"(lo), "f"(hi));
    return d;
}
__device__ __forceinline__ float2 unpack2(unsigned long long v) {
    float2 r;
    asm("mov.b64 {%0, %1}, %2;" : "=f"(r.x), "=f"(r.y) : "l"(v));
    return r;
}

// ---------------- kernel 0: texture mean -> temps, zero accumulators --------
__global__ void prep_kernel(const float* __restrict__ mask,
                            const float* __restrict__ det,
                            const float* __restrict__ smo) {
    int t = threadIdx.x;
    for (int i = t; i < BATCH * HEADS * CPH * CPH; i += 256) g_S[i] = 0.f;
    for (int i = t; i < BATCH * 2 * CH; i += 256) g_sumsq[i] = 0.f;

    __shared__ float red[256];
    for (int b = 0; b < BATCH; b++) {
        float s = 0.f;
        for (int i = t; i < HW; i += 256) s += mask[(size_t)b * HW + i];
        red[t] = s;
        __syncthreads();
        for (int o = 128; o > 0; o >>= 1) {
            if (t < o) red[t] += red[t + o];
            __syncthreads();
        }
        if (t < HEADS) {
            float tl = red[0] / (float)HW;
            g_temp[b * HEADS + t] = det[t] * tl + smo[t] * (1.f - tl);
        }
        __syncthreads();
    }
}

// ---------------- 1x1 conv as batched GEMM: Y[b,m,n] = sum_k W[m,k] X[b,k,n] + bias[m]
// K = 192 fixed. Tiles 64x64, BK=32, 256 threads, 4x4 micro-tile via f32x2.
__global__ void __launch_bounds__(256) gemm1x1(const float* __restrict__ X,
                                               const float* __restrict__ W,
                                               const float* __restrict__ bias,
                                               float* __restrict__ Y, int M) {
    __shared__ __align__(16) float ws[32][64];
    __shared__ __align__(16) float xs[32][64];
    const int b  = blockIdx.z;
    const int m0 = blockIdx.y * 64;
    const int n0 = blockIdx.x * 64;
    const int t  = threadIdx.x;
    const int tx = t & 15, ty = t >> 4;
    const float* Xb = X + (size_t)b * CH * HW;

    unsigned long long acc[4][2];
#pragma unroll
    for (int i = 0; i < 4; i++) { acc[i][0] = 0ull; acc[i][1] = 0ull; }

    for (int k0 = 0; k0 < CH; k0 += 32) {
        __syncthreads();
#pragma unroll
        for (int i = 0; i < 8; i++) {
            int e = t + i * 256;
            ws[e & 31][e >> 5] = W[(size_t)(m0 + (e >> 5)) * CH + k0 + (e & 31)];
            xs[e >> 6][e & 63] = Xb[(size_t)(k0 + (e >> 6)) * HW + n0 + (e & 63)];
        }
        __syncthreads();
#pragma unroll
        for (int kk = 0; kk < 32; kk++) {
            float4 a4 = *(const float4*)&ws[kk][ty * 4];
            union { float4 f; unsigned long long u[2]; } bu;
            bu.f = *(const float4*)&xs[kk][tx * 4];
            float av[4] = {a4.x, a4.y, a4.z, a4.w};
#pragma unroll
            for (int i = 0; i < 4; i++) {
                unsigned long long a2 = pack2(av[i], av[i]);
                acc[i][0] = ffma2(a2, bu.u[0], acc[i][0]);
                acc[i][1] = ffma2(a2, bu.u[1], acc[i][1]);
            }
        }
    }
#pragma unroll
    for (int i = 0; i < 4; i++) {
        int m = m0 + ty * 4 + i;
        float bs = bias[m];
        float2 lo = unpack2(acc[i][0]);
        float2 hi = unpack2(acc[i][1]);
        float4 o = make_float4(lo.x + bs, lo.y + bs, hi.x + bs, hi.y + bs);
        *(float4*)&Y[((size_t)b * M + m) * HW + n0 + tx * 4] = o;
    }
}

// ---------------- 3x3 depthwise conv (groups = 576), fused q/k sum-of-squares
__global__ void __launch_bounds__(256) dwconv_kernel(const float* __restrict__ in,
                                                     const float* __restrict__ w,
                                                     const float* __restrict__ bias) {
    const int b  = blockIdx.z;
    const int ch = blockIdx.y;
    const int p  = blockIdx.x * 256 + threadIdx.x;   // 0..16383
    const int hh = p >> 7, ww = p & 127;
    const float* src = in + ((size_t)b * QKVC + ch) * HW;

    float wv[9];
#pragma unroll
    for (int i = 0; i < 9; i++) wv[i] = w[ch * 9 + i];

    float acc = bias[ch];
#pragma unroll
    for (int dy = -1; dy <= 1; dy++) {
        int y = hh + dy;
        if (y < 0 || y > 127) continue;
#pragma unroll
        for (int dx = -1; dx <= 1; dx++) {
            int x2 = ww + dx;
            if (x2 < 0 || x2 > 127) continue;
            acc += wv[(dy + 1) * 3 + (dx + 1)] * src[y * 128 + x2];
        }
    }
    g_qkv1[((size_t)b * QKVC + ch) * HW + p] = acc;

    if (ch < 2 * CH) {   // q or k channel: accumulate sum of squares
        __shared__ float red[256];
        red[threadIdx.x] = acc * acc;
        __syncthreads();
        for (int o = 128; o > 0; o >>= 1) {
            if (threadIdx.x < o) red[threadIdx.x] += red[threadIdx.x + o];
            __syncthreads();
        }
        if (threadIdx.x == 0) atomicAdd(&g_sumsq[b * 2 * CH + ch], red[0]);
    }
}

// ---------------- attention scores: S[bh,c,d] += sum_n q[c,n] k[d,n] (split-K)
__global__ void __launch_bounds__(256) attn_acc_kernel() {
    const int bh = blockIdx.y;                 // b*4 + h
    const int b = bh >> 2, h = bh & 3;
    const int n0 = blockIdx.x * 512;
    __shared__ float qs[CPH][65];
    __shared__ float ks[CPH][65];
    const int t = threadIdx.x;
    const int tx = t & 15, ty = t >> 4;        // 16x16 threads, 3x3 micro

    float acc[3][3] = {};
    const float* qbase = g_qkv1 + ((size_t)b * QKVC + h * CPH) * HW;
    const float* kbase = qbase + (size_t)CH * HW;

    for (int nn = 0; nn < 512; nn += 64) {
        __syncthreads();
        for (int e = t; e < CPH * 64; e += 256) {
            int r = e >> 6, c = e & 63;
            qs[r][c] = qbase[(size_t)r * HW + n0 + nn + c];
            ks[r][c] = kbase[(size_t)r * HW + n0 + nn + c];
        }
        __syncthreads();
#pragma unroll 8
        for (int j = 0; j < 64; j++) {
            float qv[3], kv[3];
#pragma unroll
            for (int i = 0; i < 3; i++) { qv[i] = qs[ty * 3 + i][j]; kv[i] = ks[tx * 3 + i][j]; }
#pragma unroll
            for (int i = 0; i < 3; i++)
#pragma unroll
                for (int jj = 0; jj < 3; jj++) acc[i][jj] += qv[i] * kv[jj];
        }
    }
    float* Sb = g_S + (size_t)bh * CPH * CPH;
#pragma unroll
    for (int i = 0; i < 3; i++)
#pragma unroll
        for (int jj = 0; jj < 3; jj++)
            atomicAdd(&Sb[(ty * 3 + i) * CPH + tx * 3 + jj], acc[i][jj]);
}

// ---------------- softmax over d, with L2-norm and temperature scaling folded in
__global__ void softmax_kernel() {
    const int bh = blockIdx.x;
    const int b = bh >> 2, h = bh & 3;
    const int r = threadIdx.x;
    if (r >= CPH) return;
    const float temp = g_temp[bh];
    const float invq = 1.f / fmaxf(sqrtf(g_sumsq[b * 2 * CH + h * CPH + r]), 1e-12f);
    const float* Srow = g_S + (size_t)bh * CPH * CPH + r * CPH;

    float vals[CPH];
    float mx = -1e30f;
#pragma unroll
    for (int d = 0; d < CPH; d++) {
        float invk = 1.f / fmaxf(sqrtf(g_sumsq[b * 2 * CH + CH + h * CPH + d]), 1e-12f);
        float v = Srow[d] * invq * invk * temp;
        vals[d] = v;
        mx = fmaxf(mx, v);
    }
    float sum = 0.f;
#pragma unroll
    for (int d = 0; d < CPH; d++) { vals[d] = expf(vals[d] - mx); sum += vals[d]; }
    float inv = 1.f / sum;
    float* Arow = g_A + (size_t)bh * CPH * CPH + r * CPH;
#pragma unroll
    for (int d = 0; d < CPH; d++) Arow[d] = vals[d] * inv;
}

// ---------------- ctx[b, h*48+c, n] = s(b,n) * sum_d A[c,d] v[d,n]
// s(b,n) = 1 + clip(tb) * mask[b,n]  (v-scale commutes out of the contraction)
__global__ void __launch_bounds__(256) out_attn_kernel(const float* __restrict__ mask,
                                                       const float* __restrict__ tbp) {
    const int bh = blockIdx.y;
    const int b = bh >> 2, h = bh & 3;
    const int tx = threadIdx.x & 63;           // 64 n-groups (4 pixels each)
    const int ty = threadIdx.x >> 6;           // 4 c-groups (12 channels each)
    const int n = blockIdx.x * 256 + tx * 4;

    __shared__ float As[CPH][49];
    for (int e = threadIdx.x; e < CPH * CPH; e += 256)
        As[e / CPH][e % CPH] = g_A[(size_t)bh * CPH * CPH + e];
    __syncthreads();

    const float* vbase = g_qkv1 + ((size_t)b * QKVC + 2 * CH + h * CPH) * HW;
    float acc[12][4] = {};
#pragma unroll 4
    for (int d = 0; d < CPH; d++) {
        float4 v4 = *(const float4*)&vbase[(size_t)d * HW + n];
#pragma unroll
        for (int ci = 0; ci < 12; ci++) {
            float a = As[ty * 12 + ci][d];
            acc[ci][0] += a * v4.x; acc[ci][1] += a * v4.y;
            acc[ci][2] += a * v4.z; acc[ci][3] += a * v4.w;
        }
    }
    const float tb = fminf(fmaxf(*tbp, 0.1f), 0.5f);
    float4 m4 = *(const float4*)&mask[(size_t)b * HW + n];
    float s0 = 1.f + m4.x * tb, s1 = 1.f + m4.y * tb;
    float s2 = 1.f + m4.z * tb, s3 = 1.f + m4.w * tb;

    float* cbase = g_ctx + ((size_t)b * CH + h * CPH + ty * 12) * HW + n;
#pragma unroll
    for (int ci = 0; ci < 12; ci++) {
        float4 o = make_float4(acc[ci][0] * s0, acc[ci][1] * s1,
                               acc[ci][2] * s2, acc[ci][3] * s3);
        *(float4*)&cbase[(size_t)ci * HW] = o;
    }
}

// ---------------- host launcher ----------------
extern "C" void kernel_launch(void* const* d_in, const int* in_sizes, int n_in,
                              void* d_out, int out_size) {
    const float* x    = (const float*)d_in[0];
    const float* mask = (const float*)d_in[1];
    const float* qkvw = (const float*)d_in[2];
    const float* qkvb = (const float*)d_in[3];
    const float* dww  = (const float*)d_in[4];
    const float* dwb  = (const float*)d_in[5];
    const float* outw = (const float*)d_in[6];
    const float* outb = (const float*)d_in[7];
    const float* det  = (const float*)d_in[8];
    const float* smo  = (const float*)d_in[9];
    const float* tbp  = (const float*)d_in[10];
    float* y = (float*)d_out;

    void *p_qkv0 = nullptr, *p_ctx = nullptr;
    cudaGetSymbolAddress(&p_qkv0, g_qkv0);
    cudaGetSymbolAddress(&p_ctx, g_ctx);

    prep_kernel<<<1, 256>>>(mask, det, smo);
    // 1x1 qkv conv: [576,192] x [192,16384] per batch
    gemm1x1<<<dim3(HW / 64, QKVC / 64, BATCH), 256>>>(x, qkvw, qkvb, (float*)p_qkv0, QKVC);
    // 3x3 depthwise (+ fused q/k sum-of-squares)
    dwconv_kernel<<<dim3(HW / 256, QKVC, BATCH), 256>>>((const float*)p_qkv0, dww, dwb);
    // channel attention scores (split-K over 32 chunks)
    attn_acc_kernel<<<dim3(32, BATCH * HEADS), 256>>>();
    // normalization + temperature + softmax (48x48 per b,h)
    softmax_kernel<<<BATCH * HEADS, 64>>>();
    // attention output with fused texture-boost v-scaling
    out_attn_kernel<<<dim3(HW / 256, BATCH * HEADS), 256>>>(mask, tbp);
    // final 1x1 projection: [192,192] x [192,16384] per batch
    gemm1x1<<<dim3(HW / 64, CH / 64, BATCH), 256>>>((const float*)p_ctx, outw, outb, y, CH);
}

// round 3
// speedup vs baseline: 2.7422x; 2.7422x over previous
#include <cuda_runtime.h>
#include <cuda_bf16.h>
#include <math.h>
#include <stdint.h>

// Problem constants
#define BATCH 8
#define CH    192
#define QKVC  576
#define HW    16384
#define HEADS 4
#define CPH   48
#define GK    384          // split-bf16 K: 192 hi | 192 lo

// ---------------- scratch (static device memory; no allocs) ----------------
__device__ float g_qkv0[(size_t)BATCH * QKVC * HW];   // after 1x1 conv
__device__ float g_qkv1[(size_t)BATCH * QKVC * HW];   // after depthwise conv
__device__ float g_ctx [(size_t)BATCH * CH   * HW];   // attention output
__device__ float g_sumsq[BATCH * 2 * CH];
__device__ float g_S[BATCH * HEADS * CPH * CPH];
__device__ float g_A[BATCH * HEADS * CPH * CPH];
__device__ float g_temp[BATCH * HEADS];
// bf16 hi/lo staging, 16B-aligned via uint4 backing
__device__ uint4 g_xb4[(size_t)BATCH * HW * GK * 2 / 16];   // [B][HW][384] bf16
__device__ uint4 g_wb4[(size_t)(QKVC + 64) * GK * 2 / 16];  // [576(+pad)][384] bf16
__device__ uint4 g_wb24[(size_t)(CH + 64) * GK * 2 / 16];   // [192(+pad)][384] bf16

// ---------------- helpers ----------------
__device__ __forceinline__ uint32_t smem_u32(const void* p) {
    uint32_t a;
    asm("{ .reg .u64 t; cvta.to.shared.u64 t, %1; cvt.u32.u64 %0, t; }" : "=r"(a) : "l"(p));
    return a;
}
#define SWZ(off) ((off) ^ (((off) >> 3) & 0x70))

__device__ __forceinline__ void cp16(uint32_t dst, const void* src, int srcsz) {
    asm volatile("cp.async.cg.shared.global [%0], [%1], 16, %2;"
                 :: "r"(dst), "l"(src), "r"(srcsz) : "memory");
}
#define CP_COMMIT() asm volatile("cp.async.commit_group;" ::: "memory")

#define LDSM4(r0, r1, r2, r3, addr)                                            \
    asm volatile("ldmatrix.sync.aligned.m8n8.x4.shared.b16 {%0,%1,%2,%3}, [%4];" \
                 : "=r"(r0), "=r"(r1), "=r"(r2), "=r"(r3) : "r"(addr))

#define MMA16816(c, a, b0, b1)                                                 \
    asm volatile("mma.sync.aligned.m16n8k16.row.col.f32.bf16.bf16.f32 "        \
                 "{%0,%1,%2,%3},{%4,%5,%6,%7},{%8,%9},{%0,%1,%2,%3};"          \
                 : "+f"((c)[0]), "+f"((c)[1]), "+f"((c)[2]), "+f"((c)[3])      \
                 : "r"((a)[0]), "r"((a)[1]), "r"((a)[2]), "r"((a)[3]),         \
                   "r"(b0), "r"(b1))

// ---------------- kernel 0: texture mean -> temps, zero accumulators --------
__global__ void prep_kernel(const float* __restrict__ mask,
                            const float* __restrict__ det,
                            const float* __restrict__ smo) {
    int t = threadIdx.x;
    for (int i = t; i < BATCH * HEADS * CPH * CPH; i += 256) g_S[i] = 0.f;
    for (int i = t; i < BATCH * 2 * CH; i += 256) g_sumsq[i] = 0.f;

    __shared__ float red[256];
    for (int b = 0; b < BATCH; b++) {
        float s = 0.f;
        for (int i = t; i < HW; i += 256) s += mask[(size_t)b * HW + i];
        red[t] = s;
        __syncthreads();
        for (int o = 128; o > 0; o >>= 1) {
            if (t < o) red[t] += red[t + o];
            __syncthreads();
        }
        if (t < HEADS) {
            float tl = red[0] / (float)HW;
            g_temp[b * HEADS + t] = det[t] * tl + smo[t] * (1.f - tl);
        }
        __syncthreads();
    }
}

// ---------------- fp32 -> bf16 hi/lo weight convert: W[M,192] -> Wb[M,384]
__global__ void convert_w(const float* __restrict__ W, __nv_bfloat16* __restrict__ Wb) {
    int m = blockIdx.x, k = threadIdx.x;   // 192 threads
    float f = W[(size_t)m * CH + k];
    __nv_bfloat16 hi = __float2bfloat16_rn(f);
    float fr = f - __bfloat162float(hi);
    Wb[(size_t)m * GK + k] = hi;
    Wb[(size_t)m * GK + 192 + k] = __float2bfloat16_rn(fr);
}

// ---------------- fp32 [B,192,HW] -> transposed bf16 hi/lo [B,HW,384]
__global__ void __launch_bounds__(256) convert_hilo(const float* __restrict__ X,
                                                    __nv_bfloat16* __restrict__ Xb) {
    __shared__ float tile[96][65];
    const int b = blockIdx.y, n0 = blockIdx.x * 64, t = threadIdx.x;
    for (int phase = 0; phase < 2; phase++) {
        __syncthreads();
#pragma unroll
        for (int i = 0; i < 24; i++) {
            int idx = t + i * 256;
            tile[idx >> 6][idx & 63] =
                X[((size_t)b * CH + phase * 96 + (idx >> 6)) * HW + n0 + (idx & 63)];
        }
        __syncthreads();
        int n = t & 63, part = t >> 6;
        __nv_bfloat16* rowp = Xb + ((size_t)b * HW + n0 + n) * GK;
#pragma unroll
        for (int g2 = 0; g2 < 3; g2++) {
            __align__(16) __nv_bfloat16 h8[8];
            __align__(16) __nv_bfloat16 l8[8];
#pragma unroll
            for (int j = 0; j < 8; j++) {
                int k = part * 24 + g2 * 8 + j;
                float f = tile[k][n];
                __nv_bfloat16 hi = __float2bfloat16_rn(f);
                h8[j] = hi;
                l8[j] = __float2bfloat16_rn(f - __bfloat162float(hi));
            }
            *(uint4*)(rowp + phase * 96 + part * 24 + g2 * 8) = *(const uint4*)h8;
            *(uint4*)(rowp + 192 + phase * 96 + part * 24 + g2 * 8) = *(const uint4*)l8;
        }
    }
}

// ---------------- split-bf16 GEMM via mma.sync: Y[b,m,n] = W·X + bias
// A = Wb [Mtot,384] k-major, fully smem-resident (6 chunks of 128x128B)
// B = Xb [B][HW,384] k-major, chunks double-buffered via cp.async
// 9 chunk-pairs: (Ahi_j,Bhi_j), (Alo_j,Bhi_j), (Ahi_j,Blo_j)
#define SM_A 0
#define SM_B (6 * 16384)
#define SMEM_GEMM (1024 + SM_B + 2 * 32768)

__global__ void __launch_bounds__(256, 1)
gemm_mma(const __nv_bfloat16* __restrict__ Xb, const __nv_bfloat16* __restrict__ Wb,
         const float* __restrict__ bias, float* __restrict__ Y, int Mtot) {
    extern __shared__ __align__(16) char smraw[];
    uint32_t sbr = smem_u32(smraw);
    uint32_t sb = (sbr + 1023) & ~1023u;
    const int t = threadIdx.x;
    const int warp = t >> 5, lane = t & 31;
    const int wm = warp >> 2, wn = warp & 3;      // 2 x 4 warps, 64x64 each
    const int b = blockIdx.z;
    const int M0 = blockIdx.x * 128;              // m fastest -> B-tile L2 reuse
    const int N0 = blockIdx.y * 256;

    // A: all 6 chunks (96KB). 6144 16B units -> 24 per thread. Zero-pad m>=Mtot.
#pragma unroll
    for (int i = 0; i < 24; i++) {
        int u = t + i * 256;
        int ca = u >> 10, v = u & 1023;
        int row = v >> 3, q = v & 7;
        const void* src = Wb + (size_t)(M0 + row) * GK + ca * 64 + q * 8;
        cp16(sb + SM_A + ca * 16384 + SWZ(row * 128 + q * 16), src,
             (M0 + row < Mtot) ? 16 : 0);
    }
    const __nv_bfloat16* xbase = Xb + ((size_t)b * HW + N0) * GK;
    // B chunk 0 into buf 0 (same group as A)
#pragma unroll
    for (int i = 0; i < 8; i++) {
        int u = t + i * 256;
        int row = u >> 3, q = u & 7;
        cp16(sb + SM_B + SWZ(row * 128 + q * 16), xbase + (size_t)row * GK + q * 8, 16);
    }
    CP_COMMIT();
    // B chunk 1 into buf 1
#pragma unroll
    for (int i = 0; i < 8; i++) {
        int u = t + i * 256;
        int row = u >> 3, q = u & 7;
        cp16(sb + SM_B + 32768 + SWZ(row * 128 + q * 16),
             xbase + (size_t)row * GK + 64 + q * 8, 16);
    }
    CP_COMMIT();

    float acc[4][8][4];
#pragma unroll
    for (int i = 0; i < 4; i++)
#pragma unroll
        for (int j = 0; j < 8; j++)
#pragma unroll
            for (int k = 0; k < 4; k++) acc[i][j][k] = 0.f;

    for (int bi = 0; bi < 6; bi++) {
        if (bi < 5) asm volatile("cp.async.wait_group 1;" ::: "memory");
        else        asm volatile("cp.async.wait_group 0;" ::: "memory");
        __syncthreads();

        const uint32_t bbuf = sb + SM_B + (uint32_t)(bi & 1) * 32768;
        const int na = (bi < 3) ? 2 : 1;
        for (int ai = 0; ai < na; ai++) {
            const int ca = (bi < 3) ? (bi + ai * 3) : (bi - 3);
            const uint32_t abuf = sb + SM_A + (uint32_t)ca * 16384;
#pragma unroll
            for (int kk = 0; kk < 4; kk++) {
                uint32_t af[4][4];
#pragma unroll
                for (int mf = 0; mf < 4; mf++) {
                    int row = wm * 64 + mf * 16 + (lane & 7) + ((lane & 8) ? 8 : 0);
                    int cb = kk * 32 + ((lane & 16) ? 16 : 0);
                    LDSM4(af[mf][0], af[mf][1], af[mf][2], af[mf][3],
                          abuf + SWZ(row * 128 + cb));
                }
#pragma unroll
                for (int nf2 = 0; nf2 < 4; nf2++) {
                    int row = wn * 64 + nf2 * 16 + (lane & 7) + ((lane & 16) ? 8 : 0);
                    int cb = kk * 32 + ((lane & 8) ? 16 : 0);
                    uint32_t b0, b1, b2, b3;
                    LDSM4(b0, b1, b2, b3, bbuf + SWZ(row * 128 + cb));
#pragma unroll
                    for (int mf = 0; mf < 4; mf++) {
                        MMA16816(acc[mf][nf2 * 2 + 0], af[mf], b0, b1);
                        MMA16816(acc[mf][nf2 * 2 + 1], af[mf], b2, b3);
                    }
                }
            }
        }
        __syncthreads();   // done reading buf (bi&1) before overwriting it
        if (bi + 2 < 6) {
            const int c = bi + 2;
#pragma unroll
            for (int i = 0; i < 8; i++) {
                int u = t + i * 256;
                int row = u >> 3, q = u & 7;
                cp16(sb + SM_B + (uint32_t)(c & 1) * 32768 + SWZ(row * 128 + q * 16),
                     xbase + (size_t)row * GK + c * 64 + q * 8, 16);
            }
            CP_COMMIT();
        }
    }

    // Epilogue: direct float2 stores (8 rows x 32B sectors per instruction)
    const int g = lane >> 2, tg = lane & 3;
#pragma unroll
    for (int mf = 0; mf < 4; mf++) {
#pragma unroll
        for (int half = 0; half < 2; half++) {
            int m = M0 + wm * 64 + mf * 16 + g + half * 8;
            if (m < Mtot) {
                float bs = bias[m];
                float* yrow = Y + ((size_t)b * Mtot + m) * HW + N0 + wn * 64 + tg * 2;
#pragma unroll
                for (int nf = 0; nf < 8; nf++) {
                    float2 v = make_float2(acc[mf][nf][half * 2 + 0] + bs,
                                           acc[mf][nf][half * 2 + 1] + bs);
                    *(float2*)(yrow + nf * 8) = v;
                }
            }
        }
    }
}

// ---------------- 3x3 depthwise conv (groups=576), 8 outputs/thread, fused q/k sumsq
__global__ void __launch_bounds__(256) dwconv_kernel(const float* __restrict__ in,
                                                     const float* __restrict__ w,
                                                     const float* __restrict__ bias) {
    const int b = blockIdx.z, ch = blockIdx.y;
    const int t = threadIdx.x;
    const int p0 = blockIdx.x * 2048 + t * 8;
    const int hh = p0 >> 7, x0 = p0 & 127;
    const float* src = in + ((size_t)b * QKVC + ch) * HW;

    float wv[9];
#pragma unroll
    for (int i = 0; i < 9; i++) wv[i] = w[ch * 9 + i];
    const float bsv = bias[ch];

    float R[3][16];
#pragma unroll
    for (int dy = 0; dy < 3; dy++) {
        int y = hh + dy - 1;
        bool yv = (y >= 0 && y < 128);
        const float* row = src + y * 128;
        float4 v;
        v = (yv && x0 >= 4) ? *(const float4*)(row + x0 - 4) : make_float4(0, 0, 0, 0);
        R[dy][0] = v.x; R[dy][1] = v.y; R[dy][2] = v.z; R[dy][3] = v.w;
        v = yv ? *(const float4*)(row + x0) : make_float4(0, 0, 0, 0);
        R[dy][4] = v.x; R[dy][5] = v.y; R[dy][6] = v.z; R[dy][7] = v.w;
        v = yv ? *(const float4*)(row + x0 + 4) : make_float4(0, 0, 0, 0);
        R[dy][8] = v.x; R[dy][9] = v.y; R[dy][10] = v.z; R[dy][11] = v.w;
        v = (yv && x0 + 8 < 128) ? *(const float4*)(row + x0 + 8) : make_float4(0, 0, 0, 0);
        R[dy][12] = v.x; R[dy][13] = v.y; R[dy][14] = v.z; R[dy][15] = v.w;
    }
    float o[8], ss = 0.f;
#pragma unroll
    for (int i = 0; i < 8; i++) {
        float a = bsv;
#pragma unroll
        for (int dy = 0; dy < 3; dy++)
            a += wv[dy * 3 + 0] * R[dy][3 + i] + wv[dy * 3 + 1] * R[dy][4 + i] +
                 wv[dy * 3 + 2] * R[dy][5 + i];
        o[i] = a; ss += a * a;
    }
    float* dst = g_qkv1 + ((size_t)b * QKVC + ch) * HW + p0;
    *(float4*)dst = make_float4(o[0], o[1], o[2], o[3]);
    *(float4*)(dst + 4) = make_float4(o[4], o[5], o[6], o[7]);

    if (ch < 2 * CH) {
        __shared__ float red[256];
        red[t] = ss;
        __syncthreads();
        for (int off = 128; off > 0; off >>= 1) {
            if (t < off) red[t] += red[t + off];
            __syncthreads();
        }
        if (t == 0) atomicAdd(&g_sumsq[b * 2 * CH + ch], red[0]);
    }
}

// ---------------- attention scores: S[bh,c,d] += sum_n q[c,n] k[d,n] (split-K)
__global__ void __launch_bounds__(256) attn_acc_kernel() {
    const int bh = blockIdx.y;
    const int b = bh >> 2, h = bh & 3;
    const int n0 = blockIdx.x * 512;
    __shared__ float qs[CPH][65];
    __shared__ float ks[CPH][65];
    const int t = threadIdx.x;
    const int tx = t & 15, ty = t >> 4;

    float acc[3][3] = {};
    const float* qbase = g_qkv1 + ((size_t)b * QKVC + h * CPH) * HW;
    const float* kbase = qbase + (size_t)CH * HW;

    for (int nn = 0; nn < 512; nn += 64) {
        __syncthreads();
        for (int e = t; e < CPH * 64; e += 256) {
            int r = e >> 6, c = e & 63;
            qs[r][c] = qbase[(size_t)r * HW + n0 + nn + c];
            ks[r][c] = kbase[(size_t)r * HW + n0 + nn + c];
        }
        __syncthreads();
#pragma unroll 8
        for (int j = 0; j < 64; j++) {
            float qv[3], kv[3];
#pragma unroll
            for (int i = 0; i < 3; i++) { qv[i] = qs[ty * 3 + i][j]; kv[i] = ks[tx * 3 + i][j]; }
#pragma unroll
            for (int i = 0; i < 3; i++)
#pragma unroll
                for (int jj = 0; jj < 3; jj++) acc[i][jj] += qv[i] * kv[jj];
        }
    }
    float* Sb = g_S + (size_t)bh * CPH * CPH;
#pragma unroll
    for (int i = 0; i < 3; i++)
#pragma unroll
        for (int jj = 0; jj < 3; jj++)
            atomicAdd(&Sb[(ty * 3 + i) * CPH + tx * 3 + jj], acc[i][jj]);
}

// ---------------- softmax with L2-norm + temperature folded in
__global__ void softmax_kernel() {
    const int bh = blockIdx.x;
    const int b = bh >> 2, h = bh & 3;
    const int r = threadIdx.x;
    if (r >= CPH) return;
    const float temp = g_temp[bh];
    const float invq = 1.f / fmaxf(sqrtf(g_sumsq[b * 2 * CH + h * CPH + r]), 1e-12f);
    const float* Srow = g_S + (size_t)bh * CPH * CPH + r * CPH;

    float vals[CPH];
    float mx = -1e30f;
#pragma unroll
    for (int d = 0; d < CPH; d++) {
        float invk = 1.f / fmaxf(sqrtf(g_sumsq[b * 2 * CH + CH + h * CPH + d]), 1e-12f);
        float v = Srow[d] * invq * invk * temp;
        vals[d] = v;
        mx = fmaxf(mx, v);
    }
    float sum = 0.f;
#pragma unroll
    for (int d = 0; d < CPH; d++) { vals[d] = expf(vals[d] - mx); sum += vals[d]; }
    float inv = 1.f / sum;
    float* Arow = g_A + (size_t)bh * CPH * CPH + r * CPH;
#pragma unroll
    for (int d = 0; d < CPH; d++) Arow[d] = vals[d] * inv;
}

// ---------------- ctx = s(n) * (A @ v), s(n) = 1 + clip(tb)*mask
__global__ void __launch_bounds__(256) out_attn_kernel(const float* __restrict__ mask,
                                                       const float* __restrict__ tbp) {
    const int bh = blockIdx.y;
    const int b = bh >> 2, h = bh & 3;
    const int tx = threadIdx.x & 63;
    const int ty = threadIdx.x >> 6;
    const int n = blockIdx.x * 256 + tx * 4;

    __shared__ float As[CPH][49];
    for (int e = threadIdx.x; e < CPH * CPH; e += 256)
        As[e / CPH][e % CPH] = g_A[(size_t)bh * CPH * CPH + e];
    __syncthreads();

    const float* vbase = g_qkv1 + ((size_t)b * QKVC + 2 * CH + h * CPH) * HW;
    float acc[12][4] = {};
#pragma unroll 4
    for (int d = 0; d < CPH; d++) {
        float4 v4 = *(const float4*)&vbase[(size_t)d * HW + n];
#pragma unroll
        for (int ci = 0; ci < 12; ci++) {
            float a = As[ty * 12 + ci][d];
            acc[ci][0] += a * v4.x; acc[ci][1] += a * v4.y;
            acc[ci][2] += a * v4.z; acc[ci][3] += a * v4.w;
        }
    }
    const float tb = fminf(fmaxf(*tbp, 0.1f), 0.5f);
    float4 m4 = *(const float4*)&mask[(size_t)b * HW + n];
    float s0 = 1.f + m4.x * tb, s1 = 1.f + m4.y * tb;
    float s2 = 1.f + m4.z * tb, s3 = 1.f + m4.w * tb;

    float* cbase = g_ctx + ((size_t)b * CH + h * CPH + ty * 12) * HW + n;
#pragma unroll
    for (int ci = 0; ci < 12; ci++) {
        float4 o = make_float4(acc[ci][0] * s0, acc[ci][1] * s1,
                               acc[ci][2] * s2, acc[ci][3] * s3);
        *(float4*)&cbase[(size_t)ci * HW] = o;
    }
}

// ---------------- host launcher ----------------
extern "C" void kernel_launch(void* const* d_in, const int* in_sizes, int n_in,
                              void* d_out, int out_size) {
    const float* x    = (const float*)d_in[0];
    const float* mask = (const float*)d_in[1];
    const float* qkvw = (const float*)d_in[2];
    const float* qkvb = (const float*)d_in[3];
    const float* dww  = (const float*)d_in[4];
    const float* dwb  = (const float*)d_in[5];
    const float* outw = (const float*)d_in[6];
    const float* outb = (const float*)d_in[7];
    const float* det  = (const float*)d_in[8];
    const float* smo  = (const float*)d_in[9];
    const float* tbp  = (const float*)d_in[10];
    float* y = (float*)d_out;

    void *p_qkv0 = nullptr, *p_ctx = nullptr, *p_xb = nullptr, *p_wb = nullptr, *p_wb2 = nullptr;
    cudaGetSymbolAddress(&p_qkv0, g_qkv0);
    cudaGetSymbolAddress(&p_ctx, g_ctx);
    cudaGetSymbolAddress(&p_xb, g_xb4);
    cudaGetSymbolAddress(&p_wb, g_wb4);
    cudaGetSymbolAddress(&p_wb2, g_wb24);

    cudaFuncSetAttribute(gemm_mma, cudaFuncAttributeMaxDynamicSharedMemorySize, SMEM_GEMM);

    prep_kernel<<<1, 256>>>(mask, det, smo);
    convert_w<<<QKVC, 192>>>(qkvw, (__nv_bfloat16*)p_wb);
    convert_w<<<CH, 192>>>(outw, (__nv_bfloat16*)p_wb2);
    convert_hilo<<<dim3(HW / 64, BATCH), 256>>>(x, (__nv_bfloat16*)p_xb);
    // qkv 1x1 conv: split-bf16 mma.sync GEMM (m-tiles 5, last partial masked)
    gemm_mma<<<dim3(5, HW / 256, BATCH), 256, SMEM_GEMM>>>(
        (const __nv_bfloat16*)p_xb, (const __nv_bfloat16*)p_wb, qkvb, (float*)p_qkv0, QKVC);
    // 3x3 depthwise (+ fused q/k sum-of-squares)
    dwconv_kernel<<<dim3(HW / 2048, QKVC, BATCH), 256>>>((const float*)p_qkv0, dww, dwb);
    // channel attention scores
    attn_acc_kernel<<<dim3(32, BATCH * HEADS), 256>>>();
    softmax_kernel<<<BATCH * HEADS, 64>>>();
    out_attn_kernel<<<dim3(HW / 256, BATCH * HEADS), 256>>>(mask, tbp);
    // final 1x1 projection
    convert_hilo<<<dim3(HW / 64, BATCH), 256>>>((const float*)p_ctx, (__nv_bfloat16*)p_xb);
    gemm_mma<<<dim3(2, HW / 256, BATCH), 256, SMEM_GEMM>>>(
        (const __nv_bfloat16*)p_xb, (const __nv_bfloat16*)p_wb2, outb, y, CH);
}

// round 4
// speedup vs baseline: 2.9899x; 1.0903x over previous
#include <cuda_runtime.h>
#include <cuda_bf16.h>
#include <math.h>
#include <stdint.h>

// Problem constants
#define BATCH 8
#define CH    192
#define QKVC  576
#define HW    16384
#define HEADS 4
#define CPH   48
#define GK    384          // split-bf16 K: 192 hi | 192 lo

// ---------------- scratch (static device memory; no allocs) ----------------
__device__ float g_qkv0[(size_t)BATCH * QKVC * HW];   // after 1x1 conv
__device__ float g_qkv1[(size_t)BATCH * QKVC * HW];   // after depthwise conv
__device__ float g_sumsq[BATCH * 2 * CH];
__device__ float g_S[BATCH * HEADS * CPH * CPH];
__device__ float g_A[BATCH * HEADS * CPH * CPH];
__device__ float g_temp[BATCH * HEADS];
// bf16 hi/lo staging, 16B-aligned via uint4 backing
__device__ uint4 g_xb4[(size_t)BATCH * HW * GK * 2 / 16];   // [B][HW][384] bf16
__device__ uint4 g_wb4[(size_t)(QKVC + 64) * GK * 2 / 16];  // [576(+pad)][384] bf16
__device__ uint4 g_wb24[(size_t)(CH + 64) * GK * 2 / 16];   // [192(+pad)][384] bf16

// ---------------- helpers ----------------
__device__ __forceinline__ uint32_t smem_u32(const void* p) {
    uint32_t a;
    asm("{ .reg .u64 t; cvta.to.shared.u64 t, %1; cvt.u32.u64 %0, t; }" : "=r"(a) : "l"(p));
    return a;
}
#define SWZ(off) ((off) ^ (((off) >> 3) & 0x70))

__device__ __forceinline__ void cp16(uint32_t dst, const void* src, int srcsz) {
    asm volatile("cp.async.cg.shared.global [%0], [%1], 16, %2;"
                 :: "r"(dst), "l"(src), "r"(srcsz) : "memory");
}
#define CP_COMMIT() asm volatile("cp.async.commit_group;" ::: "memory")

#define LDSM4(r0, r1, r2, r3, addr)                                            \
    asm volatile("ldmatrix.sync.aligned.m8n8.x4.shared.b16 {%0,%1,%2,%3}, [%4];" \
                 : "=r"(r0), "=r"(r1), "=r"(r2), "=r"(r3) : "r"(addr))

#define MMA16816(c, a, b0, b1)                                                 \
    asm volatile("mma.sync.aligned.m16n8k16.row.col.f32.bf16.bf16.f32 "        \
                 "{%0,%1,%2,%3},{%4,%5,%6,%7},{%8,%9},{%0,%1,%2,%3};"          \
                 : "+f"((c)[0]), "+f"((c)[1]), "+f"((c)[2]), "+f"((c)[3])      \
                 : "r"((a)[0]), "r"((a)[1]), "r"((a)[2]), "r"((a)[3]),         \
                   "r"(b0), "r"(b1))

// ---------------- kernel 0: per-batch texture mean -> temps, zero accums ----
__global__ void prep_kernel(const float* __restrict__ mask,
                            const float* __restrict__ det,
                            const float* __restrict__ smo) {
    const int b = blockIdx.x, t = threadIdx.x;
    for (int i = t; i < HEADS * CPH * CPH; i += 256) g_S[b * HEADS * CPH * CPH + i] = 0.f;
    for (int i = t; i < 2 * CH; i += 256) g_sumsq[b * 2 * CH + i] = 0.f;

    __shared__ float red[256];
    const float4* m4 = (const float4*)(mask + (size_t)b * HW);
    float s = 0.f;
    for (int i = t; i < HW / 4; i += 256) {
        float4 v = m4[i];
        s += v.x + v.y + v.z + v.w;
    }
    red[t] = s;
    __syncthreads();
    for (int o = 128; o > 0; o >>= 1) {
        if (t < o) red[t] += red[t + o];
        __syncthreads();
    }
    if (t < HEADS) {
        float tl = red[0] / (float)HW;
        g_temp[b * HEADS + t] = det[t] * tl + smo[t] * (1.f - tl);
    }
}

// ---------------- fp32 -> bf16 hi/lo weight convert: W[M,192] -> Wb[M,384]
__global__ void convert_w(const float* __restrict__ W, __nv_bfloat16* __restrict__ Wb) {
    int m = blockIdx.x, k = threadIdx.x;   // 192 threads
    float f = W[(size_t)m * CH + k];
    __nv_bfloat16 hi = __float2bfloat16_rn(f);
    float fr = f - __bfloat162float(hi);
    Wb[(size_t)m * GK + k] = hi;
    Wb[(size_t)m * GK + 192 + k] = __float2bfloat16_rn(fr);
}

// ---------------- fp32 [B,192,HW] -> transposed bf16 hi/lo [B,HW,384]
__global__ void __launch_bounds__(256) convert_hilo(const float* __restrict__ X,
                                                    __nv_bfloat16* __restrict__ Xb) {
    __shared__ float tile[96][65];
    const int b = blockIdx.y, n0 = blockIdx.x * 64, t = threadIdx.x;
    for (int phase = 0; phase < 2; phase++) {
        __syncthreads();
#pragma unroll
        for (int i = 0; i < 24; i++) {
            int idx = t + i * 256;
            tile[idx >> 6][idx & 63] =
                X[((size_t)b * CH + phase * 96 + (idx >> 6)) * HW + n0 + (idx & 63)];
        }
        __syncthreads();
        int n = t & 63, part = t >> 6;
        __nv_bfloat16* rowp = Xb + ((size_t)b * HW + n0 + n) * GK;
#pragma unroll
        for (int g2 = 0; g2 < 3; g2++) {
            __align__(16) __nv_bfloat16 h8[8];
            __align__(16) __nv_bfloat16 l8[8];
#pragma unroll
            for (int j = 0; j < 8; j++) {
                int k = part * 24 + g2 * 8 + j;
                float f = tile[k][n];
                __nv_bfloat16 hi = __float2bfloat16_rn(f);
                h8[j] = hi;
                l8[j] = __float2bfloat16_rn(f - __bfloat162float(hi));
            }
            *(uint4*)(rowp + phase * 96 + part * 24 + g2 * 8) = *(const uint4*)h8;
            *(uint4*)(rowp + 192 + phase * 96 + part * 24 + g2 * 8) = *(const uint4*)l8;
        }
    }
}

// ---------------- split-bf16 GEMM via mma.sync: Y[b,m,n] = W·X + bias
#define SM_A 0
#define SM_B (6 * 16384)
#define SMEM_GEMM (1024 + SM_B + 2 * 32768)

__global__ void __launch_bounds__(256, 1)
gemm_mma(const __nv_bfloat16* __restrict__ Xb, const __nv_bfloat16* __restrict__ Wb,
         const float* __restrict__ bias, float* __restrict__ Y, int Mtot) {
    extern __shared__ __align__(16) char smraw[];
    uint32_t sbr = smem_u32(smraw);
    uint32_t sb = (sbr + 1023) & ~1023u;
    const int t = threadIdx.x;
    const int warp = t >> 5, lane = t & 31;
    const int wm = warp >> 2, wn = warp & 3;      // 2 x 4 warps, 64x64 each
    const int b = blockIdx.z;
    const int M0 = blockIdx.x * 128;              // m fastest -> B-tile L2 reuse
    const int N0 = blockIdx.y * 256;

    // A: all 6 chunks (96KB). Zero-pad m>=Mtot.
#pragma unroll
    for (int i = 0; i < 24; i++) {
        int u = t + i * 256;
        int ca = u >> 10, v = u & 1023;
        int row = v >> 3, q = v & 7;
        const void* src = Wb + (size_t)(M0 + row) * GK + ca * 64 + q * 8;
        cp16(sb + SM_A + ca * 16384 + SWZ(row * 128 + q * 16), src,
             (M0 + row < Mtot) ? 16 : 0);
    }
    const __nv_bfloat16* xbase = Xb + ((size_t)b * HW + N0) * GK;
#pragma unroll
    for (int i = 0; i < 8; i++) {
        int u = t + i * 256;
        int row = u >> 3, q = u & 7;
        cp16(sb + SM_B + SWZ(row * 128 + q * 16), xbase + (size_t)row * GK + q * 8, 16);
    }
    CP_COMMIT();
#pragma unroll
    for (int i = 0; i < 8; i++) {
        int u = t + i * 256;
        int row = u >> 3, q = u & 7;
        cp16(sb + SM_B + 32768 + SWZ(row * 128 + q * 16),
             xbase + (size_t)row * GK + 64 + q * 8, 16);
    }
    CP_COMMIT();

    float acc[4][8][4];
#pragma unroll
    for (int i = 0; i < 4; i++)
#pragma unroll
        for (int j = 0; j < 8; j++)
#pragma unroll
            for (int k = 0; k < 4; k++) acc[i][j][k] = 0.f;

    for (int bi = 0; bi < 6; bi++) {
        if (bi < 5) asm volatile("cp.async.wait_group 1;" ::: "memory");
        else        asm volatile("cp.async.wait_group 0;" ::: "memory");
        __syncthreads();

        const uint32_t bbuf = sb + SM_B + (uint32_t)(bi & 1) * 32768;
        const int na = (bi < 3) ? 2 : 1;
        for (int ai = 0; ai < na; ai++) {
            const int ca = (bi < 3) ? (bi + ai * 3) : (bi - 3);
            const uint32_t abuf = sb + SM_A + (uint32_t)ca * 16384;
#pragma unroll
            for (int kk = 0; kk < 4; kk++) {
                uint32_t af[4][4];
#pragma unroll
                for (int mf = 0; mf < 4; mf++) {
                    int row = wm * 64 + mf * 16 + (lane & 7) + ((lane & 8) ? 8 : 0);
                    int cb = kk * 32 + ((lane & 16) ? 16 : 0);
                    LDSM4(af[mf][0], af[mf][1], af[mf][2], af[mf][3],
                          abuf + SWZ(row * 128 + cb));
                }
#pragma unroll
                for (int nf2 = 0; nf2 < 4; nf2++) {
                    int row = wn * 64 + nf2 * 16 + (lane & 7) + ((lane & 16) ? 8 : 0);
                    int cb = kk * 32 + ((lane & 8) ? 16 : 0);
                    uint32_t b0, b1, b2, b3;
                    LDSM4(b0, b1, b2, b3, bbuf + SWZ(row * 128 + cb));
#pragma unroll
                    for (int mf = 0; mf < 4; mf++) {
                        MMA16816(acc[mf][nf2 * 2 + 0], af[mf], b0, b1);
                        MMA16816(acc[mf][nf2 * 2 + 1], af[mf], b2, b3);
                    }
                }
            }
        }
        __syncthreads();
        if (bi + 2 < 6) {
            const int c = bi + 2;
#pragma unroll
            for (int i = 0; i < 8; i++) {
                int u = t + i * 256;
                int row = u >> 3, q = u & 7;
                cp16(sb + SM_B + (uint32_t)(c & 1) * 32768 + SWZ(row * 128 + q * 16),
                     xbase + (size_t)row * GK + c * 64 + q * 8, 16);
            }
            CP_COMMIT();
        }
    }

    const int g = lane >> 2, tg = lane & 3;
#pragma unroll
    for (int mf = 0; mf < 4; mf++) {
#pragma unroll
        for (int half = 0; half < 2; half++) {
            int m = M0 + wm * 64 + mf * 16 + g + half * 8;
            if (m < Mtot) {
                float bs = bias[m];
                float* yrow = Y + ((size_t)b * Mtot + m) * HW + N0 + wn * 64 + tg * 2;
#pragma unroll
                for (int nf = 0; nf < 8; nf++) {
                    float2 v = make_float2(acc[mf][nf][half * 2 + 0] + bs,
                                           acc[mf][nf][half * 2 + 1] + bs);
                    *(float2*)(yrow + nf * 8) = v;
                }
            }
        }
    }
}

// ---------------- 3x3 depthwise conv (groups=576), 8 outputs/thread, fused q/k sumsq
__global__ void __launch_bounds__(256) dwconv_kernel(const float* __restrict__ in,
                                                     const float* __restrict__ w,
                                                     const float* __restrict__ bias) {
    const int b = blockIdx.z, ch = blockIdx.y;
    const int t = threadIdx.x;
    const int p0 = blockIdx.x * 2048 + t * 8;
    const int hh = p0 >> 7, x0 = p0 & 127;
    const float* src = in + ((size_t)b * QKVC + ch) * HW;

    float wv[9];
#pragma unroll
    for (int i = 0; i < 9; i++) wv[i] = w[ch * 9 + i];
    const float bsv = bias[ch];

    float R[3][16];
#pragma unroll
    for (int dy = 0; dy < 3; dy++) {
        int y = hh + dy - 1;
        bool yv = (y >= 0 && y < 128);
        const float* row = src + y * 128;
        float4 v;
        v = (yv && x0 >= 4) ? *(const float4*)(row + x0 - 4) : make_float4(0, 0, 0, 0);
        R[dy][0] = v.x; R[dy][1] = v.y; R[dy][2] = v.z; R[dy][3] = v.w;
        v = yv ? *(const float4*)(row + x0) : make_float4(0, 0, 0, 0);
        R[dy][4] = v.x; R[dy][5] = v.y; R[dy][6] = v.z; R[dy][7] = v.w;
        v = yv ? *(const float4*)(row + x0 + 4) : make_float4(0, 0, 0, 0);
        R[dy][8] = v.x; R[dy][9] = v.y; R[dy][10] = v.z; R[dy][11] = v.w;
        v = (yv && x0 + 8 < 128) ? *(const float4*)(row + x0 + 8) : make_float4(0, 0, 0, 0);
        R[dy][12] = v.x; R[dy][13] = v.y; R[dy][14] = v.z; R[dy][15] = v.w;
    }
    float o[8], ss = 0.f;
#pragma unroll
    for (int i = 0; i < 8; i++) {
        float a = bsv;
#pragma unroll
        for (int dy = 0; dy < 3; dy++)
            a += wv[dy * 3 + 0] * R[dy][3 + i] + wv[dy * 3 + 1] * R[dy][4 + i] +
                 wv[dy * 3 + 2] * R[dy][5 + i];
        o[i] = a; ss += a * a;
    }
    float* dst = g_qkv1 + ((size_t)b * QKVC + ch) * HW + p0;
    *(float4*)dst = make_float4(o[0], o[1], o[2], o[3]);
    *(float4*)(dst + 4) = make_float4(o[4], o[5], o[6], o[7]);

    if (ch < 2 * CH) {
        __shared__ float red[256];
        red[t] = ss;
        __syncthreads();
        for (int off = 128; off > 0; off >>= 1) {
            if (t < off) red[t] += red[t + off];
            __syncthreads();
        }
        if (t == 0) atomicAdd(&g_sumsq[b * 2 * CH + ch], red[0]);
    }
}

// ---------------- attention scores: S[bh,c,d] += sum_n q[c,n] k[d,n] (split-K)
__global__ void __launch_bounds__(256) attn_acc_kernel() {
    const int bh = blockIdx.y;
    const int b = bh >> 2, h = bh & 3;
    const int n0 = blockIdx.x * 512;
    __shared__ __align__(16) float qs[CPH][68];
    __shared__ __align__(16) float ks[CPH][68];
    const int t = threadIdx.x;
    const int tx = t & 15, ty = t >> 4;

    float acc[3][3] = {};
    const float* qbase = g_qkv1 + ((size_t)b * QKVC + h * CPH) * HW;
    const float* kbase = qbase + (size_t)CH * HW;

    for (int nn = 0; nn < 512; nn += 64) {
        __syncthreads();
#pragma unroll
        for (int e = t; e < 768; e += 256) {      // 48 rows x 16 float4
            int r = e >> 4, c = (e & 15) * 4;
            *(float4*)&qs[r][c] = *(const float4*)&qbase[(size_t)r * HW + n0 + nn + c];
            *(float4*)&ks[r][c] = *(const float4*)&kbase[(size_t)r * HW + n0 + nn + c];
        }
        __syncthreads();
#pragma unroll 4
        for (int j = 0; j < 64; j += 4) {
            float4 qv[3], kv[3];
#pragma unroll
            for (int i = 0; i < 3; i++) {
                qv[i] = *(const float4*)&qs[ty * 3 + i][j];
                kv[i] = *(const float4*)&ks[tx * 3 + i][j];
            }
#pragma unroll
            for (int i = 0; i < 3; i++)
#pragma unroll
                for (int jj = 0; jj < 3; jj++)
                    acc[i][jj] += qv[i].x * kv[jj].x + qv[i].y * kv[jj].y +
                                  qv[i].z * kv[jj].z + qv[i].w * kv[jj].w;
        }
    }
    float* Sb = g_S + (size_t)bh * CPH * CPH;
#pragma unroll
    for (int i = 0; i < 3; i++)
#pragma unroll
        for (int jj = 0; jj < 3; jj++)
            atomicAdd(&Sb[(ty * 3 + i) * CPH + tx * 3 + jj], acc[i][jj]);
}

// ---------------- softmax with L2-norm + temperature folded in
__global__ void softmax_kernel() {
    const int bh = blockIdx.x;
    const int b = bh >> 2, h = bh & 3;
    const int r = threadIdx.x;
    if (r >= CPH) return;
    const float temp = g_temp[bh];
    const float invq = 1.f / fmaxf(sqrtf(g_sumsq[b * 2 * CH + h * CPH + r]), 1e-12f);
    const float* Srow = g_S + (size_t)bh * CPH * CPH + r * CPH;

    float vals[CPH];
    float mx = -1e30f;
#pragma unroll
    for (int d = 0; d < CPH; d++) {
        float invk = 1.f / fmaxf(sqrtf(g_sumsq[b * 2 * CH + CH + h * CPH + d]), 1e-12f);
        float v = Srow[d] * invq * invk * temp;
        vals[d] = v;
        mx = fmaxf(mx, v);
    }
    float sum = 0.f;
#pragma unroll
    for (int d = 0; d < CPH; d++) { vals[d] = expf(vals[d] - mx); sum += vals[d]; }
    float inv = 1.f / sum;
    float* Arow = g_A + (size_t)bh * CPH * CPH + r * CPH;
#pragma unroll
    for (int d = 0; d < CPH; d++) Arow[d] = vals[d] * inv;
}

// ---------------- fused: ctx = s(n) * (A @ v) -> bf16 hi/lo directly into Xb
// Xb row layout per pixel n: [192 hi | 192 lo], this block fills channels
// [h*48 + ty*12, +12) of both halves.
__global__ void __launch_bounds__(256) out_attn_kernel(const float* __restrict__ mask,
                                                       const float* __restrict__ tbp,
                                                       __nv_bfloat16* __restrict__ Xb) {
    const int bh = blockIdx.y;
    const int b = bh >> 2, h = bh & 3;
    const int tx = threadIdx.x & 63;
    const int ty = threadIdx.x >> 6;
    const int n = blockIdx.x * 256 + tx * 4;

    __shared__ float As[CPH][49];
    for (int e = threadIdx.x; e < CPH * CPH; e += 256)
        As[e / CPH][e % CPH] = g_A[(size_t)bh * CPH * CPH + e];
    __syncthreads();

    const float* vbase = g_qkv1 + ((size_t)b * QKVC + 2 * CH + h * CPH) * HW;
    float acc[12][4] = {};
#pragma unroll 4
    for (int d = 0; d < CPH; d++) {
        float4 v4 = *(const float4*)&vbase[(size_t)d * HW + n];
#pragma unroll
        for (int ci = 0; ci < 12; ci++) {
            float a = As[ty * 12 + ci][d];
            acc[ci][0] += a * v4.x; acc[ci][1] += a * v4.y;
            acc[ci][2] += a * v4.z; acc[ci][3] += a * v4.w;
        }
    }
    const float tb = fminf(fmaxf(*tbp, 0.1f), 0.5f);
    float4 m4 = *(const float4*)&mask[(size_t)b * HW + n];
    float sp[4] = {1.f + m4.x * tb, 1.f + m4.y * tb, 1.f + m4.z * tb, 1.f + m4.w * tb};

#pragma unroll
    for (int p = 0; p < 4; p++) {
        __align__(8) __nv_bfloat16 h12[12];
        __align__(8) __nv_bfloat16 l12[12];
#pragma unroll
        for (int ci = 0; ci < 12; ci++) {
            float f = acc[ci][p] * sp[p];
            __nv_bfloat16 hi = __float2bfloat16_rn(f);
            h12[ci] = hi;
            l12[ci] = __float2bfloat16_rn(f - __bfloat162float(hi));
        }
        __nv_bfloat16* dst = Xb + ((size_t)b * HW + n + p) * GK + h * 48 + ty * 12;
#pragma unroll
        for (int u = 0; u < 3; u++) ((uint2*)dst)[u] = ((const uint2*)h12)[u];
        __nv_bfloat16* dstL = dst + 192;
#pragma unroll
        for (int u = 0; u < 3; u++) ((uint2*)dstL)[u] = ((const uint2*)l12)[u];
    }
}

// ---------------- host launcher ----------------
extern "C" void kernel_launch(void* const* d_in, const int* in_sizes, int n_in,
                              void* d_out, int out_size) {
    const float* x    = (const float*)d_in[0];
    const float* mask = (const float*)d_in[1];
    const float* qkvw = (const float*)d_in[2];
    const float* qkvb = (const float*)d_in[3];
    const float* dww  = (const float*)d_in[4];
    const float* dwb  = (const float*)d_in[5];
    const float* outw = (const float*)d_in[6];
    const float* outb = (const float*)d_in[7];
    const float* det  = (const float*)d_in[8];
    const float* smo  = (const float*)d_in[9];
    const float* tbp  = (const float*)d_in[10];
    float* y = (float*)d_out;

    void *p_qkv0 = nullptr, *p_xb = nullptr, *p_wb = nullptr, *p_wb2 = nullptr;
    cudaGetSymbolAddress(&p_qkv0, g_qkv0);
    cudaGetSymbolAddress(&p_xb, g_xb4);
    cudaGetSymbolAddress(&p_wb, g_wb4);
    cudaGetSymbolAddress(&p_wb2, g_wb24);

    cudaFuncSetAttribute(gemm_mma, cudaFuncAttributeMaxDynamicSharedMemorySize, SMEM_GEMM);

    prep_kernel<<<BATCH, 256>>>(mask, det, smo);
    convert_w<<<QKVC, 192>>>(qkvw, (__nv_bfloat16*)p_wb);
    convert_w<<<CH, 192>>>(outw, (__nv_bfloat16*)p_wb2);
    convert_hilo<<<dim3(HW / 64, BATCH), 256>>>(x, (__nv_bfloat16*)p_xb);
    // qkv 1x1 conv: split-bf16 mma.sync GEMM
    gemm_mma<<<dim3(5, HW / 256, BATCH), 256, SMEM_GEMM>>>(
        (const __nv_bfloat16*)p_xb, (const __nv_bfloat16*)p_wb, qkvb, (float*)p_qkv0, QKVC);
    // 3x3 depthwise (+ fused q/k sum-of-squares)
    dwconv_kernel<<<dim3(HW / 2048, QKVC, BATCH), 256>>>((const float*)p_qkv0, dww, dwb);
    // channel attention scores
    attn_acc_kernel<<<dim3(32, BATCH * HEADS), 256>>>();
    softmax_kernel<<<BATCH * HEADS, 64>>>();
    // attention output, fused v-scale + bf16 hi/lo conversion into Xb
    out_attn_kernel<<<dim3(HW / 256, BATCH * HEADS), 256>>>(mask, tbp, (__nv_bfloat16*)p_xb);
    // final 1x1 projection
    gemm_mma<<<dim3(2, HW / 256, BATCH), 256, SMEM_GEMM>>>(
        (const __nv_bfloat16*)p_xb, (const __nv_bfloat16*)p_wb2, outb, y, CH);
}

// round 5
// speedup vs baseline: 3.5097x; 1.1739x over previous
#include <cuda_runtime.h>
#include <cuda_fp16.h>
#include <math.h>
#include <stdint.h>

// Problem constants
#define BATCH 8
#define CH    192
#define QKVC  576
#define HW    16384
#define HEADS 4
#define CPH   48
#define WGK   384          // weight split-fp16 K: 192 hi | 192 lo

// ---------------- scratch (static device memory; no allocs) ----------------
__device__ float g_qkv0[(size_t)BATCH * QKVC * HW];   // after 1x1 conv
__device__ float g_qkv1[(size_t)BATCH * QKVC * HW];   // after depthwise conv
__device__ float g_sumsq[BATCH * 2 * CH];
__device__ float g_S[BATCH * HEADS * CPH * CPH];
__device__ float g_A[BATCH * HEADS * CPH * CPH];
__device__ float g_temp[BATCH * HEADS];
// fp16 staging, 16B-aligned via uint4 backing
__device__ uint4 g_xf4[(size_t)BATCH * HW * 192 * 2 / 16];    // [B][HW][192] fp16
__device__ uint4 g_wb4[(size_t)(QKVC + 64) * WGK * 2 / 16];   // [576(+pad)][384] fp16
__device__ uint4 g_wb24[(size_t)(CH + 64) * WGK * 2 / 16];    // [192(+pad)][384] fp16

// ---------------- helpers ----------------
__device__ __forceinline__ uint32_t smem_u32(const void* p) {
    uint32_t a;
    asm("{ .reg .u64 t; cvta.to.shared.u64 t, %1; cvt.u32.u64 %0, t; }" : "=r"(a) : "l"(p));
    return a;
}
#define SWZ(off) ((off) ^ (((off) >> 3) & 0x70))

__device__ __forceinline__ void cp16(uint32_t dst, const void* src, int srcsz) {
    asm volatile("cp.async.cg.shared.global [%0], [%1], 16, %2;"
                 :: "r"(dst), "l"(src), "r"(srcsz) : "memory");
}
#define CP_COMMIT() asm volatile("cp.async.commit_group;" ::: "memory")

#define LDSM4(r0, r1, r2, r3, addr)                                            \
    asm volatile("ldmatrix.sync.aligned.m8n8.x4.shared.b16 {%0,%1,%2,%3}, [%4];" \
                 : "=r"(r0), "=r"(r1), "=r"(r2), "=r"(r3) : "r"(addr))

#define MMA16816(c, a, b0, b1)                                                 \
    asm volatile("mma.sync.aligned.m16n8k16.row.col.f32.f16.f16.f32 "          \
                 "{%0,%1,%2,%3},{%4,%5,%6,%7},{%8,%9},{%0,%1,%2,%3};"          \
                 : "+f"((c)[0]), "+f"((c)[1]), "+f"((c)[2]), "+f"((c)[3])      \
                 : "r"((a)[0]), "r"((a)[1]), "r"((a)[2]), "r"((a)[3]),         \
                   "r"(b0), "r"(b1))

// ---------------- kernel 0: per-batch texture mean -> temps, zero accums ----
__global__ void prep_kernel(const float* __restrict__ mask,
                            const float* __restrict__ det,
                            const float* __restrict__ smo) {
    const int b = blockIdx.x, t = threadIdx.x;
    for (int i = t; i < HEADS * CPH * CPH; i += 256) g_S[b * HEADS * CPH * CPH + i] = 0.f;
    for (int i = t; i < 2 * CH; i += 256) g_sumsq[b * 2 * CH + i] = 0.f;

    __shared__ float red[256];
    const float4* m4 = (const float4*)(mask + (size_t)b * HW);
    float s = 0.f;
    for (int i = t; i < HW / 4; i += 256) {
        float4 v = m4[i];
        s += v.x + v.y + v.z + v.w;
    }
    red[t] = s;
    __syncthreads();
    for (int o = 128; o > 0; o >>= 1) {
        if (t < o) red[t] += red[t + o];
        __syncthreads();
    }
    if (t < HEADS) {
        float tl = red[0] / (float)HW;
        g_temp[b * HEADS + t] = det[t] * tl + smo[t] * (1.f - tl);
    }
}

// ---------------- fp32 -> fp16 hi/lo weight convert: W[M,192] -> Wb[M,384]
__global__ void convert_w(const float* __restrict__ W, __half* __restrict__ Wb) {
    int m = blockIdx.x, k = threadIdx.x;   // 192 threads
    float f = W[(size_t)m * CH + k];
    __half hi = __float2half_rn(f);
    float fr = f - __half2float(hi);
    Wb[(size_t)m * WGK + k] = hi;
    Wb[(size_t)m * WGK + 192 + k] = __float2half_rn(fr);
}

// ---------------- fp32 [B,192,HW] -> transposed fp16 [B,HW,192]
__global__ void __launch_bounds__(256) convert_x(const float* __restrict__ X,
                                                 __half* __restrict__ Xf) {
    __shared__ __align__(16) float tile[96][68];
    const int b = blockIdx.y, n0 = blockIdx.x * 64, t = threadIdx.x;
    for (int phase = 0; phase < 2; phase++) {
        __syncthreads();
#pragma unroll
        for (int i = 0; i < 6; i++) {
            int idx = t + i * 256;                 // 0..1535 : 96 rows x 16 float4
            int r = idx >> 4, c4 = (idx & 15) * 4;
            *(float4*)&tile[r][c4] =
                *(const float4*)&X[((size_t)b * CH + phase * 96 + r) * HW + n0 + c4];
        }
        __syncthreads();
        int n = t & 63, part = t >> 6;
        __half* rowp = Xf + ((size_t)b * HW + n0 + n) * 192 + phase * 96 + part * 24;
#pragma unroll
        for (int g2 = 0; g2 < 3; g2++) {
            __align__(16) __half h8[8];
#pragma unroll
            for (int j = 0; j < 8; j++)
                h8[j] = __float2half_rn(tile[part * 24 + g2 * 8 + j][n]);
            *(uint4*)(rowp + g2 * 8) = *(const uint4*)h8;
        }
    }
}

// ---------------- split-fp16 GEMM via mma.sync: Y[b,m,n] = W·X + bias
// A = Wb [Mtot,384] fp16 (hi|lo), all 6 chunks smem-resident
// B = Xf [B][HW,192] fp16 single, 3 chunks double-buffered via cp.async
// Per B chunk j: products (Ahi_j · B_j), (Alo_j · B_j)   -> 24 k16-steps total
#define SM_A 0
#define SM_B (6 * 16384)
#define SMEM_GEMM (1024 + SM_B + 2 * 32768)

__global__ void __launch_bounds__(256, 1)
gemm_mma(const __half* __restrict__ Xf, const __half* __restrict__ Wb,
         const float* __restrict__ bias, float* __restrict__ Y, int Mtot) {
    extern __shared__ __align__(16) char smraw[];
    uint32_t sbr = smem_u32(smraw);
    uint32_t sb = (sbr + 1023) & ~1023u;
    const int t = threadIdx.x;
    const int warp = t >> 5, lane = t & 31;
    const int wm = warp >> 2, wn = warp & 3;      // 2 x 4 warps, 64x64 each
    const int b = blockIdx.z;
    const int M0 = blockIdx.x * 128;              // m fastest -> B-tile L2 reuse
    const int N0 = blockIdx.y * 256;

    // A: all 6 chunks (96KB). Zero-pad m>=Mtot.
#pragma unroll
    for (int i = 0; i < 24; i++) {
        int u = t + i * 256;
        int ca = u >> 10, v = u & 1023;
        int row = v >> 3, q = v & 7;
        const void* src = Wb + (size_t)(M0 + row) * WGK + ca * 64 + q * 8;
        cp16(sb + SM_A + ca * 16384 + SWZ(row * 128 + q * 16), src,
             (M0 + row < Mtot) ? 16 : 0);
    }
    const __half* xbase = Xf + ((size_t)b * HW + N0) * 192;
#pragma unroll
    for (int i = 0; i < 8; i++) {
        int u = t + i * 256;
        int row = u >> 3, q = u & 7;
        cp16(sb + SM_B + SWZ(row * 128 + q * 16), xbase + (size_t)row * 192 + q * 8, 16);
    }
    CP_COMMIT();
#pragma unroll
    for (int i = 0; i < 8; i++) {
        int u = t + i * 256;
        int row = u >> 3, q = u & 7;
        cp16(sb + SM_B + 32768 + SWZ(row * 128 + q * 16),
             xbase + (size_t)row * 192 + 64 + q * 8, 16);
    }
    CP_COMMIT();

    float acc[4][8][4];
#pragma unroll
    for (int i = 0; i < 4; i++)
#pragma unroll
        for (int j = 0; j < 8; j++)
#pragma unroll
            for (int k = 0; k < 4; k++) acc[i][j][k] = 0.f;

    for (int bi = 0; bi < 3; bi++) {
        if (bi < 2) asm volatile("cp.async.wait_group 1;" ::: "memory");
        else        asm volatile("cp.async.wait_group 0;" ::: "memory");
        __syncthreads();

        const uint32_t bbuf = sb + SM_B + (uint32_t)(bi & 1) * 32768;
#pragma unroll
        for (int ai = 0; ai < 2; ai++) {
            const int ca = bi + ai * 3;           // hi chunk, then lo chunk
            const uint32_t abuf = sb + SM_A + (uint32_t)ca * 16384;
#pragma unroll
            for (int kk = 0; kk < 4; kk++) {
                uint32_t af[4][4];
#pragma unroll
                for (int mf = 0; mf < 4; mf++) {
                    int row = wm * 64 + mf * 16 + (lane & 7) + ((lane & 8) ? 8 : 0);
                    int cb = kk * 32 + ((lane & 16) ? 16 : 0);
                    LDSM4(af[mf][0], af[mf][1], af[mf][2], af[mf][3],
                          abuf + SWZ(row * 128 + cb));
                }
#pragma unroll
                for (int nf2 = 0; nf2 < 4; nf2++) {
                    int row = wn * 64 + nf2 * 16 + (lane & 7) + ((lane & 16) ? 8 : 0);
                    int cb = kk * 32 + ((lane & 8) ? 16 : 0);
                    uint32_t b0, b1, b2, b3;
                    LDSM4(b0, b1, b2, b3, bbuf + SWZ(row * 128 + cb));
#pragma unroll
                    for (int mf = 0; mf < 4; mf++) {
                        MMA16816(acc[mf][nf2 * 2 + 0], af[mf], b0, b1);
                        MMA16816(acc[mf][nf2 * 2 + 1], af[mf], b2, b3);
                    }
                }
            }
        }
        __syncthreads();
        if (bi + 2 < 3) {                          // prefetch chunk 2 (only at bi=0)
            const int c = bi + 2;
#pragma unroll
            for (int i = 0; i < 8; i++) {
                int u = t + i * 256;
                int row = u >> 3, q = u & 7;
                cp16(sb + SM_B + (uint32_t)(c & 1) * 32768 + SWZ(row * 128 + q * 16),
                     xbase + (size_t)row * 192 + c * 64 + q * 8, 16);
            }
            CP_COMMIT();
        }
    }

    const int g = lane >> 2, tg = lane & 3;
#pragma unroll
    for (int mf = 0; mf < 4; mf++) {
#pragma unroll
        for (int half = 0; half < 2; half++) {
            int m = M0 + wm * 64 + mf * 16 + g + half * 8;
            if (m < Mtot) {
                float bs = bias[m];
                float* yrow = Y + ((size_t)b * Mtot + m) * HW + N0 + wn * 64 + tg * 2;
#pragma unroll
                for (int nf = 0; nf < 8; nf++) {
                    float2 v = make_float2(acc[mf][nf][half * 2 + 0] + bs,
                                           acc[mf][nf][half * 2 + 1] + bs);
                    *(float2*)(yrow + nf * 8) = v;
                }
            }
        }
    }
}

// ---------------- 3x3 depthwise conv (groups=576), smem-tiled, fused q/k sumsq
__global__ void __launch_bounds__(256) dwconv_kernel(const float* __restrict__ in,
                                                     const float* __restrict__ w,
                                                     const float* __restrict__ bias) {
    const int b = blockIdx.z, ch = blockIdx.y;
    const int t = threadIdx.x;
    const int r0 = blockIdx.x * 16;
    __shared__ __align__(16) float sm[18][132];
    const float* src = in + ((size_t)b * QKVC + ch) * HW;

#pragma unroll
    for (int i = 0; i < 3; i++) {
        int idx = t + i * 256;
        if (idx < 576) {                          // 18 rows x 32 float4
            int rr = idx >> 5, c4 = (idx & 31) * 4;
            int gr = r0 - 1 + rr;
            float4 v = (gr >= 0 && gr < 128)
                           ? *(const float4*)(src + gr * 128 + c4)
                           : make_float4(0, 0, 0, 0);
            *(float4*)&sm[rr][c4] = v;
        }
    }
    float wv[9];
#pragma unroll
    for (int i = 0; i < 9; i++) wv[i] = w[ch * 9 + i];
    const float bsv = bias[ch];
    __syncthreads();

    const int lr = t >> 4;                        // output row within tile (0..15)
    const int xo = (t & 15) * 8;
    float R[3][16];
#pragma unroll
    for (int dy = 0; dy < 3; dy++) {
        const float* row = sm[lr + dy];
        float4 v;
        v = (xo > 0) ? *(const float4*)(row + xo - 4) : make_float4(0, 0, 0, 0);
        R[dy][0] = v.x; R[dy][1] = v.y; R[dy][2] = v.z; R[dy][3] = v.w;
        v = *(const float4*)(row + xo);
        R[dy][4] = v.x; R[dy][5] = v.y; R[dy][6] = v.z; R[dy][7] = v.w;
        v = *(const float4*)(row + xo + 4);
        R[dy][8] = v.x; R[dy][9] = v.y; R[dy][10] = v.z; R[dy][11] = v.w;
        v = (xo < 120) ? *(const float4*)(row + xo + 8) : make_float4(0, 0, 0, 0);
        R[dy][12] = v.x; R[dy][13] = v.y; R[dy][14] = v.z; R[dy][15] = v.w;
    }
    float o[8], ss = 0.f;
#pragma unroll
    for (int i = 0; i < 8; i++) {
        float a = bsv;
#pragma unroll
        for (int dy = 0; dy < 3; dy++)
            a += wv[dy * 3 + 0] * R[dy][3 + i] + wv[dy * 3 + 1] * R[dy][4 + i] +
                 wv[dy * 3 + 2] * R[dy][5 + i];
        o[i] = a; ss += a * a;
    }
    float* dst = g_qkv1 + ((size_t)b * QKVC + ch) * HW + (r0 + lr) * 128 + xo;
    *(float4*)dst = make_float4(o[0], o[1], o[2], o[3]);
    *(float4*)(dst + 4) = make_float4(o[4], o[5], o[6], o[7]);

    if (ch < 2 * CH) {
#pragma unroll
        for (int off = 16; off > 0; off >>= 1)
            ss += __shfl_xor_sync(0xFFFFFFFFu, ss, off);
        if ((t & 31) == 0) atomicAdd(&g_sumsq[b * 2 * CH + ch], ss);
    }
}

// ---------------- attention scores: S[bh,c,d] += sum_n q[c,n] k[d,n]
// 4 slabs of 64 threads; 6x6 micro-tile; split-K over grid.x + slabs
#define AT_STRIDE 68
#define AT_SLABF (2 * CPH * AT_STRIDE)            // floats per slab (q + k)
#define AT_SMEM  (4 * AT_SLABF * 4)               // 104448 bytes

__global__ void __launch_bounds__(256) attn_acc_kernel() {
    extern __shared__ __align__(16) float atsm[];
    const int bh = blockIdx.y, b = bh >> 2, h = bh & 3;
    const int t = threadIdx.x;
    const int slab = t >> 6, s = t & 63;
    const int tx = s & 7, ty = s >> 3;
    float* qs = atsm + slab * AT_SLABF;           // [48][68]
    float* ks = qs + CPH * AT_STRIDE;
    const float* qbase = g_qkv1 + ((size_t)b * QKVC + h * CPH) * HW;
    const float* kbase = qbase + (size_t)CH * HW;
    const int nslab = blockIdx.x * 2048 + slab * 512;

    float acc[6][6] = {};
    for (int it = 0; it < 8; it++) {
        const int nw = nslab + it * 64;
        __syncthreads();
#pragma unroll
        for (int i = 0; i < 24; i++) {
            int u = s + i * 64;                   // 0..1535
            int v = (u >= 768) ? (u - 768) : u;
            int r = v >> 4, c4 = (v & 15) * 4;
            const float* gsrc = ((u < 768) ? qbase : kbase) + (size_t)r * HW + nw + c4;
            float* dst = ((u < 768) ? qs : ks) + r * AT_STRIDE + c4;
            *(float4*)dst = *(const float4*)gsrc;
        }
        __syncthreads();
#pragma unroll 2
        for (int j = 0; j < 64; j += 4) {
            float4 qv[6], kv[6];
#pragma unroll
            for (int i = 0; i < 6; i++) {
                qv[i] = *(const float4*)(qs + (ty * 6 + i) * AT_STRIDE + j);
                kv[i] = *(const float4*)(ks + (tx * 6 + i) * AT_STRIDE + j);
            }
#pragma unroll
            for (int i = 0; i < 6; i++)
#pragma unroll
                for (int jj = 0; jj < 6; jj++)
                    acc[i][jj] += qv[i].x * kv[jj].x + qv[i].y * kv[jj].y +
                                  qv[i].z * kv[jj].z + qv[i].w * kv[jj].w;
        }
    }
    float* Sb = g_S + (size_t)bh * CPH * CPH;
#pragma unroll
    for (int i = 0; i < 6; i++)
#pragma unroll
        for (int jj = 0; jj < 6; jj++)
            atomicAdd(&Sb[(ty * 6 + i) * CPH + tx * 6 + jj], acc[i][jj]);
}

// ---------------- softmax with L2-norm + temperature folded in
__global__ void softmax_kernel() {
    const int bh = blockIdx.x;
    const int b = bh >> 2, h = bh & 3;
    const int r = threadIdx.x;
    if (r >= CPH) return;
    const float temp = g_temp[bh];
    const float invq = 1.f / fmaxf(sqrtf(g_sumsq[b * 2 * CH + h * CPH + r]), 1e-12f);
    const float* Srow = g_S + (size_t)bh * CPH * CPH + r * CPH;

    float vals[CPH];
    float mx = -1e30f;
#pragma unroll
    for (int d = 0; d < CPH; d++) {
        float invk = 1.f / fmaxf(sqrtf(g_sumsq[b * 2 * CH + CH + h * CPH + d]), 1e-12f);
        float v = Srow[d] * invq * invk * temp;
        vals[d] = v;
        mx = fmaxf(mx, v);
    }
    float sum = 0.f;
#pragma unroll
    for (int d = 0; d < CPH; d++) { vals[d] = expf(vals[d] - mx); sum += vals[d]; }
    float inv = 1.f / sum;
    float* Arow = g_A + (size_t)bh * CPH * CPH + r * CPH;
#pragma unroll
    for (int d = 0; d < CPH; d++) Arow[d] = vals[d] * inv;
}

// ---------------- fused: ctx = s(n) * (A @ v) -> fp16 directly into Xf
__global__ void __launch_bounds__(256) out_attn_kernel(const float* __restrict__ mask,
                                                       const float* __restrict__ tbp,
                                                       __half* __restrict__ Xf) {
    const int bh = blockIdx.y;
    const int b = bh >> 2, h = bh & 3;
    const int tx = threadIdx.x & 63;
    const int ty = threadIdx.x >> 6;
    const int n = blockIdx.x * 256 + tx * 4;

    __shared__ float As[CPH][52];
    for (int e = threadIdx.x; e < CPH * CPH; e += 256)
        As[e / CPH][e % CPH] = g_A[(size_t)bh * CPH * CPH + e];
    __syncthreads();

    const float* vbase = g_qkv1 + ((size_t)b * QKVC + 2 * CH + h * CPH) * HW;
    float acc[12][4] = {};
#pragma unroll 8
    for (int d = 0; d < CPH; d++) {
        float4 v4 = *(const float4*)&vbase[(size_t)d * HW + n];
#pragma unroll
        for (int ci = 0; ci < 12; ci++) {
            float a = As[ty * 12 + ci][d];
            acc[ci][0] += a * v4.x; acc[ci][1] += a * v4.y;
            acc[ci][2] += a * v4.z; acc[ci][3] += a * v4.w;
        }
    }
    const float tb = fminf(fmaxf(*tbp, 0.1f), 0.5f);
    float4 m4 = *(const float4*)&mask[(size_t)b * HW + n];
    float sp[4] = {1.f + m4.x * tb, 1.f + m4.y * tb, 1.f + m4.z * tb, 1.f + m4.w * tb};

#pragma unroll
    for (int p = 0; p < 4; p++) {
        __align__(8) __half h12[12];
#pragma unroll
        for (int ci = 0; ci < 12; ci++)
            h12[ci] = __float2half_rn(acc[ci][p] * sp[p]);
        __half* dst = Xf + ((size_t)b * HW + n + p) * 192 + h * 48 + ty * 12;
#pragma unroll
        for (int u = 0; u < 3; u++) ((uint2*)dst)[u] = ((const uint2*)h12)[u];
    }
}

// ---------------- host launcher ----------------
extern "C" void kernel_launch(void* const* d_in, const int* in_sizes, int n_in,
                              void* d_out, int out_size) {
    const float* x    = (const float*)d_in[0];
    const float* mask = (const float*)d_in[1];
    const float* qkvw = (const float*)d_in[2];
    const float* qkvb = (const float*)d_in[3];
    const float* dww  = (const float*)d_in[4];
    const float* dwb  = (const float*)d_in[5];
    const float* outw = (const float*)d_in[6];
    const float* outb = (const float*)d_in[7];
    const float* det  = (const float*)d_in[8];
    const float* smo  = (const float*)d_in[9];
    const float* tbp  = (const float*)d_in[10];
    float* y = (float*)d_out;

    void *p_qkv0 = nullptr, *p_xf = nullptr, *p_wb = nullptr, *p_wb2 = nullptr;
    cudaGetSymbolAddress(&p_qkv0, g_qkv0);
    cudaGetSymbolAddress(&p_xf, g_xf4);
    cudaGetSymbolAddress(&p_wb, g_wb4);
    cudaGetSymbolAddress(&p_wb2, g_wb24);

    cudaFuncSetAttribute(gemm_mma, cudaFuncAttributeMaxDynamicSharedMemorySize, SMEM_GEMM);
    cudaFuncSetAttribute(attn_acc_kernel, cudaFuncAttributeMaxDynamicSharedMemorySize, AT_SMEM);

    prep_kernel<<<BATCH, 256>>>(mask, det, smo);
    convert_w<<<QKVC, 192>>>(qkvw, (__half*)p_wb);
    convert_w<<<CH, 192>>>(outw, (__half*)p_wb2);
    convert_x<<<dim3(HW / 64, BATCH), 256>>>(x, (__half*)p_xf);
    // qkv 1x1 conv: split-fp16 mma.sync GEMM (2 products)
    gemm_mma<<<dim3(5, HW / 256, BATCH), 256, SMEM_GEMM>>>(
        (const __half*)p_xf, (const __half*)p_wb, qkvb, (float*)p_qkv0, QKVC);
    // 3x3 depthwise (+ fused q/k sum-of-squares), smem-tiled
    dwconv_kernel<<<dim3(8, QKVC, BATCH), 256>>>((const float*)p_qkv0, dww, dwb);
    // channel attention scores (6x6 micro-tile)
    attn_acc_kernel<<<dim3(8, BATCH * HEADS), 256, AT_SMEM>>>();
    softmax_kernel<<<BATCH * HEADS, 64>>>();
    // attention output, fused v-scale + fp16 conversion into Xf
    out_attn_kernel<<<dim3(HW / 256, BATCH * HEADS), 256>>>(mask, tbp, (__half*)p_xf);
    // final 1x1 projection
    gemm_mma<<<dim3(2, HW / 256, BATCH), 256, SMEM_GEMM>>>(
        (const __half*)p_xf, (const __half*)p_wb2, outb, y, CH);
}

// round 6
// speedup vs baseline: 3.7397x; 1.0655x over previous
#include <cuda_runtime.h>
#include <cuda_fp16.h>
#include <math.h>
#include <stdint.h>

// Problem constants
#define BATCH 8
#define CH    192
#define QKVC  576
#define HW    16384
#define HEADS 4
#define CPH   48
#define WGK   384          // weight split-fp16 K: 192 hi | 192 lo

// ---------------- scratch (static device memory; no allocs) ----------------
__device__ uint4 g_q0h[(size_t)BATCH * QKVC * HW * 2 / 16];   // fp16 qkv after 1x1
__device__ uint4 g_q1h[(size_t)BATCH * QKVC * HW * 2 / 16];   // fp16 qkv after dw
__device__ float g_sumsq[BATCH * 2 * CH];
__device__ float g_S[BATCH * HEADS * CPH * CPH];
__device__ float g_A[BATCH * HEADS * CPH * CPH];
__device__ float g_temp[BATCH * HEADS];
__device__ uint4 g_xf4[(size_t)BATCH * HW * 192 * 2 / 16];    // [B][HW][192] fp16
__device__ uint4 g_wb4[(size_t)(QKVC + 64) * WGK * 2 / 16];   // [576(+pad)][384] fp16
__device__ uint4 g_wb24[(size_t)(CH + 64) * WGK * 2 / 16];    // [192(+pad)][384] fp16

// ---------------- helpers ----------------
__device__ __forceinline__ uint32_t smem_u32(const void* p) {
    uint32_t a;
    asm("{ .reg .u64 t; cvta.to.shared.u64 t, %1; cvt.u32.u64 %0, t; }" : "=r"(a) : "l"(p));
    return a;
}
#define SWZ(off) ((off) ^ (((off) >> 3) & 0x70))

__device__ __forceinline__ void cp16(uint32_t dst, const void* src, int srcsz) {
    asm volatile("cp.async.cg.shared.global [%0], [%1], 16, %2;"
                 :: "r"(dst), "l"(src), "r"(srcsz) : "memory");
}
#define CP_COMMIT() asm volatile("cp.async.commit_group;" ::: "memory")

#define LDSM4(r0, r1, r2, r3, addr)                                            \
    asm volatile("ldmatrix.sync.aligned.m8n8.x4.shared.b16 {%0,%1,%2,%3}, [%4];" \
                 : "=r"(r0), "=r"(r1), "=r"(r2), "=r"(r3) : "r"(addr))

#define MMA16816(c, a, b0, b1)                                                 \
    asm volatile("mma.sync.aligned.m16n8k16.row.col.f32.f16.f16.f32 "          \
                 "{%0,%1,%2,%3},{%4,%5,%6,%7},{%8,%9},{%0,%1,%2,%3};"          \
                 : "+f"((c)[0]), "+f"((c)[1]), "+f"((c)[2]), "+f"((c)[3])      \
                 : "r"((a)[0]), "r"((a)[1]), "r"((a)[2]), "r"((a)[3]),         \
                   "r"(b0), "r"(b1))

__device__ __forceinline__ void h8_to_f(const uint4 v, float* f) {
    const __half2* h2 = (const __half2*)&v;
#pragma unroll
    for (int i = 0; i < 4; i++) {
        float2 x = __half22float2(h2[i]);
        f[i * 2 + 0] = x.x;
        f[i * 2 + 1] = x.y;
    }
}

// ---------------- kernel 0: per-batch texture mean -> temps, zero accums ----
__global__ void prep_kernel(const float* __restrict__ mask,
                            const float* __restrict__ det,
                            const float* __restrict__ smo) {
    const int b = blockIdx.x, t = threadIdx.x;
    for (int i = t; i < HEADS * CPH * CPH; i += 256) g_S[b * HEADS * CPH * CPH + i] = 0.f;
    for (int i = t; i < 2 * CH; i += 256) g_sumsq[b * 2 * CH + i] = 0.f;

    __shared__ float red[256];
    const float4* m4 = (const float4*)(mask + (size_t)b * HW);
    float s = 0.f;
    for (int i = t; i < HW / 4; i += 256) {
        float4 v = m4[i];
        s += v.x + v.y + v.z + v.w;
    }
    red[t] = s;
    __syncthreads();
    for (int o = 128; o > 0; o >>= 1) {
        if (t < o) red[t] += red[t + o];
        __syncthreads();
    }
    if (t < HEADS) {
        float tl = red[0] / (float)HW;
        g_temp[b * HEADS + t] = det[t] * tl + smo[t] * (1.f - tl);
    }
}

// ---------------- fp32 -> fp16 hi/lo weight convert: W[M,192] -> Wb[M,384]
__global__ void convert_w(const float* __restrict__ W, __half* __restrict__ Wb) {
    int m = blockIdx.x, k = threadIdx.x;   // 192 threads
    float f = W[(size_t)m * CH + k];
    __half hi = __float2half_rn(f);
    float fr = f - __half2float(hi);
    Wb[(size_t)m * WGK + k] = hi;
    Wb[(size_t)m * WGK + 192 + k] = __float2half_rn(fr);
}

// ---------------- fp32 [B,192,HW] -> transposed fp16 [B,HW,192]
__global__ void __launch_bounds__(256) convert_x(const float* __restrict__ X,
                                                 __half* __restrict__ Xf) {
    __shared__ __align__(16) float tile[96][68];
    const int b = blockIdx.y, n0 = blockIdx.x * 64, t = threadIdx.x;
    for (int phase = 0; phase < 2; phase++) {
        __syncthreads();
#pragma unroll
        for (int i = 0; i < 6; i++) {
            int idx = t + i * 256;                 // 0..1535 : 96 rows x 16 float4
            int r = idx >> 4, c4 = (idx & 15) * 4;
            *(float4*)&tile[r][c4] =
                *(const float4*)&X[((size_t)b * CH + phase * 96 + r) * HW + n0 + c4];
        }
        __syncthreads();
        int n = t & 63, part = t >> 6;
        __half* rowp = Xf + ((size_t)b * HW + n0 + n) * 192 + phase * 96 + part * 24;
#pragma unroll
        for (int g2 = 0; g2 < 3; g2++) {
            __align__(16) __half h8[8];
#pragma unroll
            for (int j = 0; j < 8; j++)
                h8[j] = __float2half_rn(tile[part * 24 + g2 * 8 + j][n]);
            *(uint4*)(rowp + g2 * 8) = *(const uint4*)h8;
        }
    }
}

// ---------------- split-fp16 GEMM via mma.sync: Y[b,m,n] = W·X + bias
// OT = __half (qkv intermediate) or float (final output)
#define SM_A 0
#define SM_B (6 * 16384)
#define SMEM_GEMM (1024 + SM_B + 2 * 32768)

template <typename OT>
__global__ void __launch_bounds__(256, 1)
gemm_mma(const __half* __restrict__ Xf, const __half* __restrict__ Wb,
         const float* __restrict__ bias, OT* __restrict__ Y, int Mtot) {
    extern __shared__ __align__(16) char smraw[];
    uint32_t sbr = smem_u32(smraw);
    uint32_t sb = (sbr + 1023) & ~1023u;
    const int t = threadIdx.x;
    const int warp = t >> 5, lane = t & 31;
    const int wm = warp >> 2, wn = warp & 3;      // 2 x 4 warps, 64x64 each
    const int b = blockIdx.z;
    const int M0 = blockIdx.x * 128;              // m fastest -> B-tile L2 reuse
    const int N0 = blockIdx.y * 256;

    // A: all 6 chunks (96KB). Zero-pad m>=Mtot.
#pragma unroll
    for (int i = 0; i < 24; i++) {
        int u = t + i * 256;
        int ca = u >> 10, v = u & 1023;
        int row = v >> 3, q = v & 7;
        const void* src = Wb + (size_t)(M0 + row) * WGK + ca * 64 + q * 8;
        cp16(sb + SM_A + ca * 16384 + SWZ(row * 128 + q * 16), src,
             (M0 + row < Mtot) ? 16 : 0);
    }
    const __half* xbase = Xf + ((size_t)b * HW + N0) * 192;
#pragma unroll
    for (int i = 0; i < 8; i++) {
        int u = t + i * 256;
        int row = u >> 3, q = u & 7;
        cp16(sb + SM_B + SWZ(row * 128 + q * 16), xbase + (size_t)row * 192 + q * 8, 16);
    }
    CP_COMMIT();
#pragma unroll
    for (int i = 0; i < 8; i++) {
        int u = t + i * 256;
        int row = u >> 3, q = u & 7;
        cp16(sb + SM_B + 32768 + SWZ(row * 128 + q * 16),
             xbase + (size_t)row * 192 + 64 + q * 8, 16);
    }
    CP_COMMIT();

    float acc[4][8][4];
#pragma unroll
    for (int i = 0; i < 4; i++)
#pragma unroll
        for (int j = 0; j < 8; j++)
#pragma unroll
            for (int k = 0; k < 4; k++) acc[i][j][k] = 0.f;

    for (int bi = 0; bi < 3; bi++) {
        if (bi < 2) asm volatile("cp.async.wait_group 1;" ::: "memory");
        else        asm volatile("cp.async.wait_group 0;" ::: "memory");
        __syncthreads();

        const uint32_t bbuf = sb + SM_B + (uint32_t)(bi & 1) * 32768;
#pragma unroll
        for (int ai = 0; ai < 2; ai++) {
            const int ca = bi + ai * 3;           // hi chunk, then lo chunk
            const uint32_t abuf = sb + SM_A + (uint32_t)ca * 16384;
#pragma unroll
            for (int kk = 0; kk < 4; kk++) {
                uint32_t af[4][4];
#pragma unroll
                for (int mf = 0; mf < 4; mf++) {
                    int row = wm * 64 + mf * 16 + (lane & 7) + ((lane & 8) ? 8 : 0);
                    int cb = kk * 32 + ((lane & 16) ? 16 : 0);
                    LDSM4(af[mf][0], af[mf][1], af[mf][2], af[mf][3],
                          abuf + SWZ(row * 128 + cb));
                }
#pragma unroll
                for (int nf2 = 0; nf2 < 4; nf2++) {
                    int row = wn * 64 + nf2 * 16 + (lane & 7) + ((lane & 16) ? 8 : 0);
                    int cb = kk * 32 + ((lane & 8) ? 16 : 0);
                    uint32_t b0, b1, b2, b3;
                    LDSM4(b0, b1, b2, b3, bbuf + SWZ(row * 128 + cb));
#pragma unroll
                    for (int mf = 0; mf < 4; mf++) {
                        MMA16816(acc[mf][nf2 * 2 + 0], af[mf], b0, b1);
                        MMA16816(acc[mf][nf2 * 2 + 1], af[mf], b2, b3);
                    }
                }
            }
        }
        __syncthreads();
        if (bi + 2 < 3) {                          // prefetch chunk 2 (only at bi=0)
            const int c = bi + 2;
#pragma unroll
            for (int i = 0; i < 8; i++) {
                int u = t + i * 256;
                int row = u >> 3, q = u & 7;
                cp16(sb + SM_B + (uint32_t)(c & 1) * 32768 + SWZ(row * 128 + q * 16),
                     xbase + (size_t)row * 192 + c * 64 + q * 8, 16);
            }
            CP_COMMIT();
        }
    }

    const int g = lane >> 2, tg = lane & 3;
#pragma unroll
    for (int mf = 0; mf < 4; mf++) {
#pragma unroll
        for (int half = 0; half < 2; half++) {
            int m = M0 + wm * 64 + mf * 16 + g + half * 8;
            if (m < Mtot) {
                float bs = bias[m];
                OT* yrow = Y + ((size_t)b * Mtot + m) * HW + N0 + wn * 64 + tg * 2;
#pragma unroll
                for (int nf = 0; nf < 8; nf++) {
                    float v0 = acc[mf][nf][half * 2 + 0] + bs;
                    float v1 = acc[mf][nf][half * 2 + 1] + bs;
                    if constexpr (sizeof(OT) == 4) {
                        *(float2*)(yrow + nf * 8) = make_float2(v0, v1);
                    } else {
                        *(__half2*)(yrow + nf * 8) =
                            __floats2half2_rn(v0, v1);
                    }
                }
            }
        }
    }
}

// ---------------- 3x3 depthwise conv (groups=576), fp16 in/out, fp32 math
__global__ void __launch_bounds__(256) dwconv_kernel(const __half* __restrict__ in,
                                                     const float* __restrict__ w,
                                                     const float* __restrict__ bias,
                                                     __half* __restrict__ out) {
    const int b = blockIdx.z, ch = blockIdx.y;
    const int t = threadIdx.x;
    const int r0 = blockIdx.x * 16;
    __shared__ __align__(16) float sm[18][132];
    const __half* src = in + ((size_t)b * QKVC + ch) * HW;

#pragma unroll
    for (int i = 0; i < 2; i++) {
        int idx = t + i * 256;
        if (idx < 288) {                          // 18 rows x 16 uint4 (8 halves)
            int rr = idx >> 4, c8 = (idx & 15) * 8;
            int gr = r0 - 1 + rr;
            float f8[8] = {};
            if (gr >= 0 && gr < 128) {
                uint4 v = *(const uint4*)(src + gr * 128 + c8);
                h8_to_f(v, f8);
            }
#pragma unroll
            for (int j = 0; j < 8; j++) sm[rr][c8 + j] = f8[j];
        }
    }
    float wv[9];
#pragma unroll
    for (int i = 0; i < 9; i++) wv[i] = w[ch * 9 + i];
    const float bsv = bias[ch];
    __syncthreads();

    const int lr = t >> 4;                        // output row within tile (0..15)
    const int xo = (t & 15) * 8;
    float R[3][16];
#pragma unroll
    for (int dy = 0; dy < 3; dy++) {
        const float* row = sm[lr + dy];
        float4 v;
        v = (xo > 0) ? *(const float4*)(row + xo - 4) : make_float4(0, 0, 0, 0);
        R[dy][0] = v.x; R[dy][1] = v.y; R[dy][2] = v.z; R[dy][3] = v.w;
        v = *(const float4*)(row + xo);
        R[dy][4] = v.x; R[dy][5] = v.y; R[dy][6] = v.z; R[dy][7] = v.w;
        v = *(const float4*)(row + xo + 4);
        R[dy][8] = v.x; R[dy][9] = v.y; R[dy][10] = v.z; R[dy][11] = v.w;
        v = (xo < 120) ? *(const float4*)(row + xo + 8) : make_float4(0, 0, 0, 0);
        R[dy][12] = v.x; R[dy][13] = v.y; R[dy][14] = v.z; R[dy][15] = v.w;
    }
    float o[8], ss = 0.f;
#pragma unroll
    for (int i = 0; i < 8; i++) {
        float a = bsv;
#pragma unroll
        for (int dy = 0; dy < 3; dy++)
            a += wv[dy * 3 + 0] * R[dy][3 + i] + wv[dy * 3 + 1] * R[dy][4 + i] +
                 wv[dy * 3 + 2] * R[dy][5 + i];
        o[i] = a; ss += a * a;
    }
    __align__(16) __half oh[8];
#pragma unroll
    for (int i = 0; i < 8; i++) oh[i] = __float2half_rn(o[i]);
    *(uint4*)(out + ((size_t)b * QKVC + ch) * HW + (r0 + lr) * 128 + xo) =
        *(const uint4*)oh;

    if (ch < 2 * CH) {
#pragma unroll
        for (int off = 16; off > 0; off >>= 1)
            ss += __shfl_xor_sync(0xFFFFFFFFu, ss, off);
        if ((t & 31) == 0) atomicAdd(&g_sumsq[b * 2 * CH + ch], ss);
    }
}

// ---------------- attention scores: S[bh,c,d] += sum_n q[c,n] k[d,n]
// 4 slabs of 64 threads; 6x6 micro-tile; fp16 input, fp32 math
#define AT_STRIDE 68
#define AT_SLABF (2 * CPH * AT_STRIDE)            // floats per slab (q + k)
#define AT_SMEM  (4 * AT_SLABF * 4)               // 104448 bytes

__global__ void __launch_bounds__(256) attn_acc_kernel(const __half* __restrict__ qkv) {
    extern __shared__ __align__(16) float atsm[];
    const int bh = blockIdx.y, b = bh >> 2, h = bh & 3;
    const int t = threadIdx.x;
    const int slab = t >> 6, s = t & 63;
    const int tx = s & 7, ty = s >> 3;
    float* qs = atsm + slab * AT_SLABF;           // [48][68]
    float* ks = qs + CPH * AT_STRIDE;
    const __half* qbase = qkv + ((size_t)b * QKVC + h * CPH) * HW;
    const __half* kbase = qbase + (size_t)CH * HW;
    const int nslab = blockIdx.x * 2048 + slab * 512;

    float acc[6][6] = {};
    for (int it = 0; it < 8; it++) {
        const int nw = nslab + it * 64;
        __syncthreads();
#pragma unroll
        for (int i = 0; i < 12; i++) {
            int u = s + i * 64;                   // 0..767 : 2 x (48 rows x 8 uint4)
            int v = (u >= 384) ? (u - 384) : u;
            int r = v >> 3, c8 = (v & 7) * 8;
            const __half* gsrc = ((u < 384) ? qbase : kbase) + (size_t)r * HW + nw + c8;
            float* dst = ((u < 384) ? qs : ks) + r * AT_STRIDE + c8;
            float f8[8];
            h8_to_f(*(const uint4*)gsrc, f8);
#pragma unroll
            for (int j = 0; j < 8; j++) dst[j] = f8[j];
        }
        __syncthreads();
#pragma unroll 2
        for (int j = 0; j < 64; j += 4) {
            float4 qv[6], kv[6];
#pragma unroll
            for (int i = 0; i < 6; i++) {
                qv[i] = *(const float4*)(qs + (ty * 6 + i) * AT_STRIDE + j);
                kv[i] = *(const float4*)(ks + (tx * 6 + i) * AT_STRIDE + j);
            }
#pragma unroll
            for (int i = 0; i < 6; i++)
#pragma unroll
                for (int jj = 0; jj < 6; jj++)
                    acc[i][jj] += qv[i].x * kv[jj].x + qv[i].y * kv[jj].y +
                                  qv[i].z * kv[jj].z + qv[i].w * kv[jj].w;
        }
    }
    float* Sb = g_S + (size_t)bh * CPH * CPH;
#pragma unroll
    for (int i = 0; i < 6; i++)
#pragma unroll
        for (int jj = 0; jj < 6; jj++)
            atomicAdd(&Sb[(ty * 6 + i) * CPH + tx * 6 + jj], acc[i][jj]);
}

// ---------------- softmax with L2-norm + temperature folded in
__global__ void softmax_kernel() {
    const int bh = blockIdx.x;
    const int b = bh >> 2, h = bh & 3;
    const int r = threadIdx.x;
    if (r >= CPH) return;
    const float temp = g_temp[bh];
    const float invq = 1.f / fmaxf(sqrtf(g_sumsq[b * 2 * CH + h * CPH + r]), 1e-12f);
    const float* Srow = g_S + (size_t)bh * CPH * CPH + r * CPH;

    float vals[CPH];
    float mx = -1e30f;
#pragma unroll
    for (int d = 0; d < CPH; d++) {
        float invk = 1.f / fmaxf(sqrtf(g_sumsq[b * 2 * CH + CH + h * CPH + d]), 1e-12f);
        float v = Srow[d] * invq * invk * temp;
        vals[d] = v;
        mx = fmaxf(mx, v);
    }
    float sum = 0.f;
#pragma unroll
    for (int d = 0; d < CPH; d++) { vals[d] = expf(vals[d] - mx); sum += vals[d]; }
    float inv = 1.f / sum;
    float* Arow = g_A + (size_t)bh * CPH * CPH + r * CPH;
#pragma unroll
    for (int d = 0; d < CPH; d++) Arow[d] = vals[d] * inv;
}

// ---------------- fused: ctx = s(n) * (A @ v) -> fp16 directly into Xf
__global__ void __launch_bounds__(256) out_attn_kernel(const __half* __restrict__ qkv,
                                                       const float* __restrict__ mask,
                                                       const float* __restrict__ tbp,
                                                       __half* __restrict__ Xf) {
    const int bh = blockIdx.y;
    const int b = bh >> 2, h = bh & 3;
    const int tx = threadIdx.x & 63;
    const int ty = threadIdx.x >> 6;
    const int n = blockIdx.x * 256 + tx * 4;

    __shared__ float As[CPH][52];
    for (int e = threadIdx.x; e < CPH * CPH; e += 256)
        As[e / CPH][e % CPH] = g_A[(size_t)bh * CPH * CPH + e];
    __syncthreads();

    const __half* vbase = qkv + ((size_t)b * QKVC + 2 * CH + h * CPH) * HW;
    float acc[12][4] = {};
#pragma unroll 8
    for (int d = 0; d < CPH; d++) {
        float2 p0 = __half22float2(*(const __half2*)&vbase[(size_t)d * HW + n]);
        float2 p1 = __half22float2(*(const __half2*)&vbase[(size_t)d * HW + n + 2]);
#pragma unroll
        for (int ci = 0; ci < 12; ci++) {
            float a = As[ty * 12 + ci][d];
            acc[ci][0] += a * p0.x; acc[ci][1] += a * p0.y;
            acc[ci][2] += a * p1.x; acc[ci][3] += a * p1.y;
        }
    }
    const float tb = fminf(fmaxf(*tbp, 0.1f), 0.5f);
    float4 m4 = *(const float4*)&mask[(size_t)b * HW + n];
    float sp[4] = {1.f + m4.x * tb, 1.f + m4.y * tb, 1.f + m4.z * tb, 1.f + m4.w * tb};

#pragma unroll
    for (int p = 0; p < 4; p++) {
        __align__(8) __half h12[12];
#pragma unroll
        for (int ci = 0; ci < 12; ci++)
            h12[ci] = __float2half_rn(acc[ci][p] * sp[p]);
        __half* dst = Xf + ((size_t)b * HW + n + p) * 192 + h * 48 + ty * 12;
#pragma unroll
        for (int u = 0; u < 3; u++) ((uint2*)dst)[u] = ((const uint2*)h12)[u];
    }
}

// ---------------- host launcher ----------------
extern "C" void kernel_launch(void* const* d_in, const int* in_sizes, int n_in,
                              void* d_out, int out_size) {
    const float* x    = (const float*)d_in[0];
    const float* mask = (const float*)d_in[1];
    const float* qkvw = (const float*)d_in[2];
    const float* qkvb = (const float*)d_in[3];
    const float* dww  = (const float*)d_in[4];
    const float* dwb  = (const float*)d_in[5];
    const float* outw = (const float*)d_in[6];
    const float* outb = (const float*)d_in[7];
    const float* det  = (const float*)d_in[8];
    const float* smo  = (const float*)d_in[9];
    const float* tbp  = (const float*)d_in[10];
    float* y = (float*)d_out;

    void *p_q0 = nullptr, *p_q1 = nullptr, *p_xf = nullptr, *p_wb = nullptr, *p_wb2 = nullptr;
    cudaGetSymbolAddress(&p_q0, g_q0h);
    cudaGetSymbolAddress(&p_q1, g_q1h);
    cudaGetSymbolAddress(&p_xf, g_xf4);
    cudaGetSymbolAddress(&p_wb, g_wb4);
    cudaGetSymbolAddress(&p_wb2, g_wb24);

    cudaFuncSetAttribute(gemm_mma<__half>, cudaFuncAttributeMaxDynamicSharedMemorySize, SMEM_GEMM);
    cudaFuncSetAttribute(gemm_mma<float>, cudaFuncAttributeMaxDynamicSharedMemorySize, SMEM_GEMM);
    cudaFuncSetAttribute(attn_acc_kernel, cudaFuncAttributeMaxDynamicSharedMemorySize, AT_SMEM);

    prep_kernel<<<BATCH, 256>>>(mask, det, smo);
    convert_w<<<QKVC, 192>>>(qkvw, (__half*)p_wb);
    convert_w<<<CH, 192>>>(outw, (__half*)p_wb2);
    convert_x<<<dim3(HW / 64, BATCH), 256>>>(x, (__half*)p_xf);
    // qkv 1x1 conv: split-fp16 mma.sync GEMM -> fp16 output
    gemm_mma<__half><<<dim3(5, HW / 256, BATCH), 256, SMEM_GEMM>>>(
        (const __half*)p_xf, (const __half*)p_wb, qkvb, (__half*)p_q0, QKVC);
    // 3x3 depthwise (+ fused q/k sum-of-squares), fp16 in/out
    dwconv_kernel<<<dim3(8, QKVC, BATCH), 256>>>(
        (const __half*)p_q0, dww, dwb, (__half*)p_q1);
    // channel attention scores (6x6 micro-tile), fp16 input
    attn_acc_kernel<<<dim3(8, BATCH * HEADS), 256, AT_SMEM>>>((const __half*)p_q1);
    softmax_kernel<<<BATCH * HEADS, 64>>>();
    // attention output, fused v-scale + fp16 conversion into Xf
    out_attn_kernel<<<dim3(HW / 256, BATCH * HEADS), 256>>>(
        (const __half*)p_q1, mask, tbp, (__half*)p_xf);
    // final 1x1 projection -> fp32 into d_out
    gemm_mma<float><<<dim3(2, HW / 256, BATCH), 256, SMEM_GEMM>>>(
        (const __half*)p_xf, (const __half*)p_wb2, outb, y, CH);
}

// round 7
// speedup vs baseline: 4.4029x; 1.1773x over previous
#include <cuda_runtime.h>
#include <cuda_fp16.h>
#include <math.h>
#include <stdint.h>

// Problem constants
#define BATCH 8
#define CH    192
#define QKVC  576
#define HW    16384
#define HEADS 4
#define CPH   48
#define WGK   384          // weight split-fp16 K: 192 hi | 192 lo

// ---------------- scratch (static device memory; no allocs) ----------------
__device__ uint4 g_q0h[(size_t)BATCH * QKVC * HW * 2 / 16];   // fp16 qkv after 1x1
__device__ uint4 g_q1h[(size_t)BATCH * QKVC * HW * 2 / 16];   // fp16 qkv after dw
__device__ float g_sumsq[BATCH * 2 * CH];
__device__ float g_S[BATCH * HEADS * CPH * CPH];
__device__ float g_A[BATCH * HEADS * CPH * CPH];
__device__ float g_temp[BATCH * HEADS];
__device__ uint4 g_xf4[(size_t)BATCH * HW * 192 * 2 / 16];    // [B][HW][192] fp16
__device__ uint4 g_wb4[(size_t)(QKVC + 64) * WGK * 2 / 16];   // [576(+pad)][384] fp16
__device__ uint4 g_wb24[(size_t)(CH + 64) * WGK * 2 / 16];    // [192(+pad)][384] fp16

// ---------------- helpers ----------------
__device__ __forceinline__ uint32_t smem_u32(const void* p) {
    uint32_t a;
    asm("{ .reg .u64 t; cvta.to.shared.u64 t, %1; cvt.u32.u64 %0, t; }" : "=r"(a) : "l"(p));
    return a;
}
#define SWZ(off) ((off) ^ (((off) >> 3) & 0x70))

__device__ __forceinline__ void cp16(uint32_t dst, const void* src, int srcsz) {
    asm volatile("cp.async.cg.shared.global [%0], [%1], 16, %2;"
                 :: "r"(dst), "l"(src), "r"(srcsz) : "memory");
}
#define CP_COMMIT() asm volatile("cp.async.commit_group;" ::: "memory")

#define LDSM4(r0, r1, r2, r3, addr)                                            \
    asm volatile("ldmatrix.sync.aligned.m8n8.x4.shared.b16 {%0,%1,%2,%3}, [%4];" \
                 : "=r"(r0), "=r"(r1), "=r"(r2), "=r"(r3) : "r"(addr))

#define MMA16816(c, a, b0, b1)                                                 \
    asm volatile("mma.sync.aligned.m16n8k16.row.col.f32.f16.f16.f32 "          \
                 "{%0,%1,%2,%3},{%4,%5,%6,%7},{%8,%9},{%0,%1,%2,%3};"          \
                 : "+f"((c)[0]), "+f"((c)[1]), "+f"((c)[2]), "+f"((c)[3])      \
                 : "r"((a)[0]), "r"((a)[1]), "r"((a)[2]), "r"((a)[3]),         \
                   "r"(b0), "r"(b1))

__device__ __forceinline__ void h8_to_f(const uint4 v, float* f) {
    const __half2* h2 = (const __half2*)&v;
#pragma unroll
    for (int i = 0; i < 4; i++) {
        float2 x = __half22float2(h2[i]);
        f[i * 2 + 0] = x.x;
        f[i * 2 + 1] = x.y;
    }
}

// ---------------- kernel 0: per-batch texture mean -> temps, zero accums ----
__global__ void prep_kernel(const float* __restrict__ mask,
                            const float* __restrict__ det,
                            const float* __restrict__ smo) {
    const int b = blockIdx.x, t = threadIdx.x;
    for (int i = t; i < HEADS * CPH * CPH; i += 256) g_S[b * HEADS * CPH * CPH + i] = 0.f;
    for (int i = t; i < 2 * CH; i += 256) g_sumsq[b * 2 * CH + i] = 0.f;

    __shared__ float red[256];
    const float4* m4 = (const float4*)(mask + (size_t)b * HW);
    float s = 0.f;
    for (int i = t; i < HW / 4; i += 256) {
        float4 v = m4[i];
        s += v.x + v.y + v.z + v.w;
    }
    red[t] = s;
    __syncthreads();
    for (int o = 128; o > 0; o >>= 1) {
        if (t < o) red[t] += red[t + o];
        __syncthreads();
    }
    if (t < HEADS) {
        float tl = red[0] / (float)HW;
        g_temp[b * HEADS + t] = det[t] * tl + smo[t] * (1.f - tl);
    }
}

// ---------------- fp32 -> fp16 hi/lo weight convert: W[M,192] -> Wb[M,384]
__global__ void convert_w(const float* __restrict__ W, __half* __restrict__ Wb) {
    int m = blockIdx.x, k = threadIdx.x;   // 192 threads
    float f = W[(size_t)m * CH + k];
    __half hi = __float2half_rn(f);
    float fr = f - __half2float(hi);
    Wb[(size_t)m * WGK + k] = hi;
    Wb[(size_t)m * WGK + 192 + k] = __float2half_rn(fr);
}

// ---------------- fp32 [B,192,HW] -> transposed fp16 [B,HW,192]
__global__ void __launch_bounds__(256) convert_x(const float* __restrict__ X,
                                                 __half* __restrict__ Xf) {
    __shared__ __align__(16) float tile[96][68];
    const int b = blockIdx.y, n0 = blockIdx.x * 64, t = threadIdx.x;
    for (int phase = 0; phase < 2; phase++) {
        __syncthreads();
#pragma unroll
        for (int i = 0; i < 6; i++) {
            int idx = t + i * 256;                 // 0..1535 : 96 rows x 16 float4
            int r = idx >> 4, c4 = (idx & 15) * 4;
            *(float4*)&tile[r][c4] =
                *(const float4*)&X[((size_t)b * CH + phase * 96 + r) * HW + n0 + c4];
        }
        __syncthreads();
        int n = t & 63, part = t >> 6;
        __half* rowp = Xf + ((size_t)b * HW + n0 + n) * 192 + phase * 96 + part * 24;
#pragma unroll
        for (int g2 = 0; g2 < 3; g2++) {
            __align__(16) __half h8[8];
#pragma unroll
            for (int j = 0; j < 8; j++)
                h8[j] = __float2half_rn(tile[part * 24 + g2 * 8 + j][n]);
            *(uint4*)(rowp + g2 * 8) = *(const uint4*)h8;
        }
    }
}

// ---------------- split-fp16 GEMM via mma.sync: Y[b,m,n] = W·X + bias
#define SM_A 0
#define SM_B (6 * 16384)
#define SMEM_GEMM (1024 + SM_B + 2 * 32768)

template <typename OT>
__global__ void __launch_bounds__(256, 1)
gemm_mma(const __half* __restrict__ Xf, const __half* __restrict__ Wb,
         const float* __restrict__ bias, OT* __restrict__ Y, int Mtot) {
    extern __shared__ __align__(16) char smraw[];
    uint32_t sbr = smem_u32(smraw);
    uint32_t sb = (sbr + 1023) & ~1023u;
    const int t = threadIdx.x;
    const int warp = t >> 5, lane = t & 31;
    const int wm = warp >> 2, wn = warp & 3;      // 2 x 4 warps, 64x64 each
    const int b = blockIdx.z;
    const int M0 = blockIdx.x * 128;              // m fastest -> B-tile L2 reuse
    const int N0 = blockIdx.y * 256;

    // A: all 6 chunks (96KB). Zero-pad m>=Mtot.
#pragma unroll
    for (int i = 0; i < 24; i++) {
        int u = t + i * 256;
        int ca = u >> 10, v = u & 1023;
        int row = v >> 3, q = v & 7;
        const void* src = Wb + (size_t)(M0 + row) * WGK + ca * 64 + q * 8;
        cp16(sb + SM_A + ca * 16384 + SWZ(row * 128 + q * 16), src,
             (M0 + row < Mtot) ? 16 : 0);
    }
    const __half* xbase = Xf + ((size_t)b * HW + N0) * 192;
#pragma unroll
    for (int i = 0; i < 8; i++) {
        int u = t + i * 256;
        int row = u >> 3, q = u & 7;
        cp16(sb + SM_B + SWZ(row * 128 + q * 16), xbase + (size_t)row * 192 + q * 8, 16);
    }
    CP_COMMIT();
#pragma unroll
    for (int i = 0; i < 8; i++) {
        int u = t + i * 256;
        int row = u >> 3, q = u & 7;
        cp16(sb + SM_B + 32768 + SWZ(row * 128 + q * 16),
             xbase + (size_t)row * 192 + 64 + q * 8, 16);
    }
    CP_COMMIT();

    float acc[4][8][4];
#pragma unroll
    for (int i = 0; i < 4; i++)
#pragma unroll
        for (int j = 0; j < 8; j++)
#pragma unroll
            for (int k = 0; k < 4; k++) acc[i][j][k] = 0.f;

    for (int bi = 0; bi < 3; bi++) {
        if (bi < 2) asm volatile("cp.async.wait_group 1;" ::: "memory");
        else        asm volatile("cp.async.wait_group 0;" ::: "memory");
        __syncthreads();

        const uint32_t bbuf = sb + SM_B + (uint32_t)(bi & 1) * 32768;
#pragma unroll
        for (int ai = 0; ai < 2; ai++) {
            const int ca = bi + ai * 3;           // hi chunk, then lo chunk
            const uint32_t abuf = sb + SM_A + (uint32_t)ca * 16384;
#pragma unroll
            for (int kk = 0; kk < 4; kk++) {
                uint32_t af[4][4];
#pragma unroll
                for (int mf = 0; mf < 4; mf++) {
                    int row = wm * 64 + mf * 16 + (lane & 7) + ((lane & 8) ? 8 : 0);
                    int cb = kk * 32 + ((lane & 16) ? 16 : 0);
                    LDSM4(af[mf][0], af[mf][1], af[mf][2], af[mf][3],
                          abuf + SWZ(row * 128 + cb));
                }
#pragma unroll
                for (int nf2 = 0; nf2 < 4; nf2++) {
                    int row = wn * 64 + nf2 * 16 + (lane & 7) + ((lane & 16) ? 8 : 0);
                    int cb = kk * 32 + ((lane & 8) ? 16 : 0);
                    uint32_t b0, b1, b2, b3;
                    LDSM4(b0, b1, b2, b3, bbuf + SWZ(row * 128 + cb));
#pragma unroll
                    for (int mf = 0; mf < 4; mf++) {
                        MMA16816(acc[mf][nf2 * 2 + 0], af[mf], b0, b1);
                        MMA16816(acc[mf][nf2 * 2 + 1], af[mf], b2, b3);
                    }
                }
            }
        }
        __syncthreads();
        if (bi + 2 < 3) {                          // prefetch chunk 2 (only at bi=0)
            const int c = bi + 2;
#pragma unroll
            for (int i = 0; i < 8; i++) {
                int u = t + i * 256;
                int row = u >> 3, q = u & 7;
                cp16(sb + SM_B + (uint32_t)(c & 1) * 32768 + SWZ(row * 128 + q * 16),
                     xbase + (size_t)row * 192 + c * 64 + q * 8, 16);
            }
            CP_COMMIT();
        }
    }

    const int g = lane >> 2, tg = lane & 3;
#pragma unroll
    for (int mf = 0; mf < 4; mf++) {
#pragma unroll
        for (int half = 0; half < 2; half++) {
            int m = M0 + wm * 64 + mf * 16 + g + half * 8;
            if (m < Mtot) {
                float bs = bias[m];
                OT* yrow = Y + ((size_t)b * Mtot + m) * HW + N0 + wn * 64 + tg * 2;
#pragma unroll
                for (int nf = 0; nf < 8; nf++) {
                    float v0 = acc[mf][nf][half * 2 + 0] + bs;
                    float v1 = acc[mf][nf][half * 2 + 1] + bs;
                    if constexpr (sizeof(OT) == 4) {
                        *(float2*)(yrow + nf * 8) = make_float2(v0, v1);
                    } else {
                        *(__half2*)(yrow + nf * 8) = __floats2half2_rn(v0, v1);
                    }
                }
            }
        }
    }
}

// ---------------- 3x3 depthwise conv (groups=576), 32-row tiles, fp16 in/out
__global__ void __launch_bounds__(256) dwconv_kernel(const __half* __restrict__ in,
                                                     const float* __restrict__ w,
                                                     const float* __restrict__ bias,
                                                     __half* __restrict__ out) {
    const int b = blockIdx.z, ch = blockIdx.y;
    const int t = threadIdx.x;
    const int r0 = blockIdx.x * 32;
    __shared__ __align__(16) float sm[34][132];
    const __half* src = in + ((size_t)b * QKVC + ch) * HW;

#pragma unroll
    for (int i = 0; i < 3; i++) {
        int idx = t + i * 256;
        if (idx < 544) {                          // 34 rows x 16 uint4 (8 halves)
            int rr = idx >> 4, c8 = (idx & 15) * 8;
            int gr = r0 - 1 + rr;
            float f8[8] = {};
            if (gr >= 0 && gr < 128) {
                uint4 v = *(const uint4*)(src + gr * 128 + c8);
                h8_to_f(v, f8);
            }
#pragma unroll
            for (int j = 0; j < 8; j++) sm[rr][c8 + j] = f8[j];
        }
    }
    float wv[9];
#pragma unroll
    for (int i = 0; i < 9; i++) wv[i] = w[ch * 9 + i];
    const float bsv = bias[ch];
    __syncthreads();

    const int lr = (t >> 4) * 2;                  // output row pair within tile
    const int xo = (t & 15) * 8;
    float R[4][16];
#pragma unroll
    for (int dy = 0; dy < 4; dy++) {
        const float* row = sm[lr + dy];
        float4 v;
        v = (xo > 0) ? *(const float4*)(row + xo - 4) : make_float4(0, 0, 0, 0);
        R[dy][0] = v.x; R[dy][1] = v.y; R[dy][2] = v.z; R[dy][3] = v.w;
        v = *(const float4*)(row + xo);
        R[dy][4] = v.x; R[dy][5] = v.y; R[dy][6] = v.z; R[dy][7] = v.w;
        v = *(const float4*)(row + xo + 4);
        R[dy][8] = v.x; R[dy][9] = v.y; R[dy][10] = v.z; R[dy][11] = v.w;
        v = (xo < 120) ? *(const float4*)(row + xo + 8) : make_float4(0, 0, 0, 0);
        R[dy][12] = v.x; R[dy][13] = v.y; R[dy][14] = v.z; R[dy][15] = v.w;
    }
    float ss = 0.f;
#pragma unroll
    for (int rr2 = 0; rr2 < 2; rr2++) {
        float o[8];
#pragma unroll
        for (int i = 0; i < 8; i++) {
            float a = bsv;
#pragma unroll
            for (int dy = 0; dy < 3; dy++)
                a += wv[dy * 3 + 0] * R[rr2 + dy][3 + i] +
                     wv[dy * 3 + 1] * R[rr2 + dy][4 + i] +
                     wv[dy * 3 + 2] * R[rr2 + dy][5 + i];
            o[i] = a; ss += a * a;
        }
        __align__(16) __half oh[8];
#pragma unroll
        for (int i = 0; i < 8; i++) oh[i] = __float2half_rn(o[i]);
        *(uint4*)(out + ((size_t)b * QKVC + ch) * HW + (r0 + lr + rr2) * 128 + xo) =
            *(const uint4*)oh;
    }

    if (ch < 2 * CH) {
#pragma unroll
        for (int off = 16; off > 0; off >>= 1)
            ss += __shfl_xor_sync(0xFFFFFFFFu, ss, off);
        if ((t & 31) == 0) atomicAdd(&g_sumsq[b * 2 * CH + ch], ss);
    }
}

// ---------------- attention scores via mma.sync: S[bh] += q·k^T over split-K
// 64x64 padded output (rows >=48 zero-filled), 8 warps in 2m x 4n grid
#define ATM_SMEM (1024 + 2 * 16384)

__global__ void __launch_bounds__(256) attn_mma(const __half* __restrict__ qkv) {
    extern __shared__ __align__(16) char atraw[];
    uint32_t sbr = smem_u32(atraw);
    uint32_t sb = (sbr + 1023) & ~1023u;
    const int bh = blockIdx.y, b = bh >> 2, h = bh & 3;
    const int t = threadIdx.x;
    const int warp = t >> 5, lane = t & 31;
    const int wm = warp >> 2, wn = warp & 3;      // warp tile m32 x n16
    const __half* qbase = qkv + ((size_t)b * QKVC + h * CPH) * HW;
    const __half* kbase = qbase + (size_t)CH * HW;
    const int n0 = blockIdx.x * 2048;             // 32 iterations of k64

    // loader: iteration `it` -> buffer it&1 (q at +0, k at +8192)
#define ATM_LOAD(it) do {                                                          \
        const int _nw = n0 + (it) * 64;                                            \
        _Pragma("unroll")                                                          \
        for (int _i = 0; _i < 4; _i++) {                                           \
            int _u = t + _i * 256;                                                 \
            int _isK = _u >= 512;                                                  \
            int _v = _u & 511;                                                     \
            int _row = _v >> 3, _q8 = _v & 7;                                      \
            const __half* _src = (_isK ? kbase : qbase) + (size_t)_row * HW + _nw + _q8 * 8; \
            cp16(sb + (uint32_t)((it) & 1) * 16384 + (_isK ? 8192 : 0) +           \
                     SWZ(_row * 128 + _q8 * 16),                                   \
                 _src, (_row < CPH) ? 16 : 0);                                     \
        }                                                                          \
        CP_COMMIT();                                                               \
    } while (0)

    ATM_LOAD(0);
    ATM_LOAD(1);

    float acc[2][2][4];
#pragma unroll
    for (int i = 0; i < 2; i++)
#pragma unroll
        for (int j = 0; j < 2; j++)
#pragma unroll
            for (int k = 0; k < 4; k++) acc[i][j][k] = 0.f;

    for (int bi = 0; bi < 32; bi++) {
        if (bi < 31) asm volatile("cp.async.wait_group 1;" ::: "memory");
        else         asm volatile("cp.async.wait_group 0;" ::: "memory");
        __syncthreads();
        const uint32_t qbuf = sb + (uint32_t)(bi & 1) * 16384;
        const uint32_t kbuf = qbuf + 8192;
#pragma unroll
        for (int kk = 0; kk < 4; kk++) {
            uint32_t af[2][4];
#pragma unroll
            for (int mf = 0; mf < 2; mf++) {
                int row = wm * 32 + mf * 16 + (lane & 7) + ((lane & 8) ? 8 : 0);
                int cb = kk * 32 + ((lane & 16) ? 16 : 0);
                LDSM4(af[mf][0], af[mf][1], af[mf][2], af[mf][3],
                      qbuf + SWZ(row * 128 + cb));
            }
            int rowb = wn * 16 + (lane & 7) + ((lane & 16) ? 8 : 0);
            int cbb = kk * 32 + ((lane & 8) ? 16 : 0);
            uint32_t b0, b1, b2, b3;
            LDSM4(b0, b1, b2, b3, kbuf + SWZ(rowb * 128 + cbb));
#pragma unroll
            for (int mf = 0; mf < 2; mf++) {
                MMA16816(acc[mf][0], af[mf], b0, b1);
                MMA16816(acc[mf][1], af[mf], b2, b3);
            }
        }
        __syncthreads();
        if (bi + 2 < 32) ATM_LOAD(bi + 2);
    }
#undef ATM_LOAD

    float* Sb = g_S + (size_t)bh * CPH * CPH;
    const int g = lane >> 2, tg = lane & 3;
#pragma unroll
    for (int mf = 0; mf < 2; mf++)
#pragma unroll
        for (int half = 0; half < 2; half++) {
            int m = wm * 32 + mf * 16 + g + half * 8;
            if (m < CPH) {
#pragma unroll
                for (int nf = 0; nf < 2; nf++)
#pragma unroll
                    for (int j = 0; j < 2; j++) {
                        int d = wn * 16 + nf * 8 + tg * 2 + j;
                        if (d < CPH)
                            atomicAdd(&Sb[m * CPH + d], acc[mf][nf][half * 2 + j]);
                    }
            }
        }
}

// ---------------- softmax with L2-norm + temperature folded in
__global__ void softmax_kernel() {
    const int bh = blockIdx.x;
    const int b = bh >> 2, h = bh & 3;
    const int r = threadIdx.x;
    if (r >= CPH) return;
    const float temp = g_temp[bh];
    const float invq = 1.f / fmaxf(sqrtf(g_sumsq[b * 2 * CH + h * CPH + r]), 1e-12f);
    const float* Srow = g_S + (size_t)bh * CPH * CPH + r * CPH;

    float vals[CPH];
    float mx = -1e30f;
#pragma unroll
    for (int d = 0; d < CPH; d++) {
        float invk = 1.f / fmaxf(sqrtf(g_sumsq[b * 2 * CH + CH + h * CPH + d]), 1e-12f);
        float v = Srow[d] * invq * invk * temp;
        vals[d] = v;
        mx = fmaxf(mx, v);
    }
    float sum = 0.f;
#pragma unroll
    for (int d = 0; d < CPH; d++) { vals[d] = expf(vals[d] - mx); sum += vals[d]; }
    float inv = 1.f / sum;
    float* Arow = g_A + (size_t)bh * CPH * CPH + r * CPH;
#pragma unroll
    for (int d = 0; d < CPH; d++) Arow[d] = vals[d] * inv;
}

// ---------------- fused: ctx = s(n) * (A @ v) -> fp16 directly into Xf
__global__ void __launch_bounds__(256) out_attn_kernel(const __half* __restrict__ qkv,
                                                       const float* __restrict__ mask,
                                                       const float* __restrict__ tbp,
                                                       __half* __restrict__ Xf) {
    const int bh = blockIdx.y;
    const int b = bh >> 2, h = bh & 3;
    const int tx = threadIdx.x & 63;
    const int ty = threadIdx.x >> 6;
    const int n = blockIdx.x * 256 + tx * 4;

    __shared__ float As[CPH][52];
    for (int e = threadIdx.x; e < CPH * CPH; e += 256)
        As[e / CPH][e % CPH] = g_A[(size_t)bh * CPH * CPH + e];
    __syncthreads();

    const __half* vbase = qkv + ((size_t)b * QKVC + 2 * CH + h * CPH) * HW;
    float acc[12][4] = {};
#pragma unroll 8
    for (int d = 0; d < CPH; d++) {
        float2 p0 = __half22float2(*(const __half2*)&vbase[(size_t)d * HW + n]);
        float2 p1 = __half22float2(*(const __half2*)&vbase[(size_t)d * HW + n + 2]);
#pragma unroll
        for (int ci = 0; ci < 12; ci++) {
            float a = As[ty * 12 + ci][d];
            acc[ci][0] += a * p0.x; acc[ci][1] += a * p0.y;
            acc[ci][2] += a * p1.x; acc[ci][3] += a * p1.y;
        }
    }
    const float tb = fminf(fmaxf(*tbp, 0.1f), 0.5f);
    float4 m4 = *(const float4*)&mask[(size_t)b * HW + n];
    float sp[4] = {1.f + m4.x * tb, 1.f + m4.y * tb, 1.f + m4.z * tb, 1.f + m4.w * tb};

#pragma unroll
    for (int p = 0; p < 4; p++) {
        __align__(8) __half h12[12];
#pragma unroll
        for (int ci = 0; ci < 12; ci++)
            h12[ci] = __float2half_rn(acc[ci][p] * sp[p]);
        __half* dst = Xf + ((size_t)b * HW + n + p) * 192 + h * 48 + ty * 12;
#pragma unroll
        for (int u = 0; u < 3; u++) ((uint2*)dst)[u] = ((const uint2*)h12)[u];
    }
}

// ---------------- host launcher ----------------
extern "C" void kernel_launch(void* const* d_in, const int* in_sizes, int n_in,
                              void* d_out, int out_size) {
    const float* x    = (const float*)d_in[0];
    const float* mask = (const float*)d_in[1];
    const float* qkvw = (const float*)d_in[2];
    const float* qkvb = (const float*)d_in[3];
    const float* dww  = (const float*)d_in[4];
    const float* dwb  = (const float*)d_in[5];
    const float* outw = (const float*)d_in[6];
    const float* outb = (const float*)d_in[7];
    const float* det  = (const float*)d_in[8];
    const float* smo  = (const float*)d_in[9];
    const float* tbp  = (const float*)d_in[10];
    float* y = (float*)d_out;

    void *p_q0 = nullptr, *p_q1 = nullptr, *p_xf = nullptr, *p_wb = nullptr, *p_wb2 = nullptr;
    cudaGetSymbolAddress(&p_q0, g_q0h);
    cudaGetSymbolAddress(&p_q1, g_q1h);
    cudaGetSymbolAddress(&p_xf, g_xf4);
    cudaGetSymbolAddress(&p_wb, g_wb4);
    cudaGetSymbolAddress(&p_wb2, g_wb24);

    cudaFuncSetAttribute(gemm_mma<__half>, cudaFuncAttributeMaxDynamicSharedMemorySize, SMEM_GEMM);
    cudaFuncSetAttribute(gemm_mma<float>, cudaFuncAttributeMaxDynamicSharedMemorySize, SMEM_GEMM);
    cudaFuncSetAttribute(attn_mma, cudaFuncAttributeMaxDynamicSharedMemorySize, ATM_SMEM);

    prep_kernel<<<BATCH, 256>>>(mask, det, smo);
    convert_w<<<QKVC, 192>>>(qkvw, (__half*)p_wb);
    convert_w<<<CH, 192>>>(outw, (__half*)p_wb2);
    convert_x<<<dim3(HW / 64, BATCH), 256>>>(x, (__half*)p_xf);
    // qkv 1x1 conv: split-fp16 mma.sync GEMM -> fp16 output
    gemm_mma<__half><<<dim3(5, HW / 256, BATCH), 256, SMEM_GEMM>>>(
        (const __half*)p_xf, (const __half*)p_wb, qkvb, (__half*)p_q0, QKVC);
    // 3x3 depthwise (+ fused q/k sum-of-squares), 32-row tiles
    dwconv_kernel<<<dim3(4, QKVC, BATCH), 256>>>(
        (const __half*)p_q0, dww, dwb, (__half*)p_q1);
    // channel attention scores via tensor cores
    attn_mma<<<dim3(8, BATCH * HEADS), 256, ATM_SMEM>>>((const __half*)p_q1);
    softmax_kernel<<<BATCH * HEADS, 64>>>();
    // attention output, fused v-scale + fp16 conversion into Xf
    out_attn_kernel<<<dim3(HW / 256, BATCH * HEADS), 256>>>(
        (const __half*)p_q1, mask, tbp, (__half*)p_xf);
    // final 1x1 projection -> fp32 into d_out
    gemm_mma<float><<<dim3(2, HW / 256, BATCH), 256, SMEM_GEMM>>>(
        (const __half*)p_xf, (const __half*)p_wb2, outb, y, CH);
}

// round 8
// speedup vs baseline: 5.7746x; 1.3115x over previous
#include <cuda_runtime.h>
#include <cuda_fp16.h>
#include <math.h>
#include <stdint.h>

// Problem constants
#define BATCH 8
#define CH    192
#define QKVC  576
#define HW    16384
#define HEADS 4
#define CPH   48

// ---------------- scratch (static device memory; no allocs) ----------------
__device__ uint4 g_q0h[(size_t)BATCH * QKVC * HW * 2 / 16];   // fp16 qkv after 1x1
__device__ uint4 g_q1h[(size_t)BATCH * QKVC * HW * 2 / 16];   // fp16 qkv after dw
__device__ float g_sumsq[BATCH * 2 * CH];
__device__ float g_S[BATCH * HEADS * CPH * CPH];
__device__ float g_A[BATCH * HEADS * CPH * CPH];
__device__ float g_temp[BATCH * HEADS];
__device__ uint4 g_xf4[(size_t)BATCH * HW * 192 * 2 / 16];    // [B][HW][192] fp16
__device__ uint4 g_wb4[(size_t)(QKVC + 64) * CH * 2 / 16];    // [576(+pad)][192] fp16
__device__ uint4 g_weff[(size_t)BATCH * 256 * CH * 2 / 16];   // [B][192(+pad)][192] fp16

// ---------------- helpers ----------------
__device__ __forceinline__ uint32_t smem_u32(const void* p) {
    uint32_t a;
    asm("{ .reg .u64 t; cvta.to.shared.u64 t, %1; cvt.u32.u64 %0, t; }" : "=r"(a) : "l"(p));
    return a;
}
#define SWZ(off) ((off) ^ (((off) >> 3) & 0x70))

__device__ __forceinline__ void cp16(uint32_t dst, const void* src, int srcsz) {
    asm volatile("cp.async.cg.shared.global [%0], [%1], 16, %2;"
                 :: "r"(dst), "l"(src), "r"(srcsz) : "memory");
}
#define CP_COMMIT() asm volatile("cp.async.commit_group;" ::: "memory")

#define LDSM4(r0, r1, r2, r3, addr)                                            \
    asm volatile("ldmatrix.sync.aligned.m8n8.x4.shared.b16 {%0,%1,%2,%3}, [%4];" \
                 : "=r"(r0), "=r"(r1), "=r"(r2), "=r"(r3) : "r"(addr))

#define LDSM4T(r0, r1, r2, r3, addr)                                           \
    asm volatile("ldmatrix.sync.aligned.m8n8.x4.trans.shared.b16 {%0,%1,%2,%3}, [%4];" \
                 : "=r"(r0), "=r"(r1), "=r"(r2), "=r"(r3) : "r"(addr))

#define MMA16816(c, a, b0, b1)                                                 \
    asm volatile("mma.sync.aligned.m16n8k16.row.col.f32.f16.f16.f32 "          \
                 "{%0,%1,%2,%3},{%4,%5,%6,%7},{%8,%9},{%0,%1,%2,%3};"          \
                 : "+f"((c)[0]), "+f"((c)[1]), "+f"((c)[2]), "+f"((c)[3])      \
                 : "r"((a)[0]), "r"((a)[1]), "r"((a)[2]), "r"((a)[3]),         \
                   "r"(b0), "r"(b1))

__device__ __forceinline__ void h8_to_f(const uint4 v, float* f) {
    const __half2* h2 = (const __half2*)&v;
#pragma unroll
    for (int i = 0; i < 4; i++) {
        float2 x = __half22float2(h2[i]);
        f[i * 2 + 0] = x.x;
        f[i * 2 + 1] = x.y;
    }
}

// ---------------- kernel 0: per-batch texture mean -> temps, zero accums ----
__global__ void prep_kernel(const float* __restrict__ mask,
                            const float* __restrict__ det,
                            const float* __restrict__ smo) {
    const int b = blockIdx.x, t = threadIdx.x;
    for (int i = t; i < HEADS * CPH * CPH; i += 256) g_S[b * HEADS * CPH * CPH + i] = 0.f;
    for (int i = t; i < 2 * CH; i += 256) g_sumsq[b * 2 * CH + i] = 0.f;

    __shared__ float red[256];
    const float4* m4 = (const float4*)(mask + (size_t)b * HW);
    float s = 0.f;
    for (int i = t; i < HW / 4; i += 256) {
        float4 v = m4[i];
        s += v.x + v.y + v.z + v.w;
    }
    red[t] = s;
    __syncthreads();
    for (int o = 128; o > 0; o >>= 1) {
        if (t < o) red[t] += red[t + o];
        __syncthreads();
    }
    if (t < HEADS) {
        float tl = red[0] / (float)HW;
        g_temp[b * HEADS + t] = det[t] * tl + smo[t] * (1.f - tl);
    }
}

// ---------------- fp32 -> fp16 weight convert: W[M,192] -> Wb[M,192]
__global__ void convert_w(const float* __restrict__ W, __half* __restrict__ Wb) {
    int m = blockIdx.x, k = threadIdx.x;   // 192 threads
    Wb[(size_t)m * CH + k] = __float2half_rn(W[(size_t)m * CH + k]);
}

// ---------------- fp32 [B,192,HW] -> transposed fp16 [B,HW,192]
__global__ void __launch_bounds__(256) convert_x(const float* __restrict__ X,
                                                 __half* __restrict__ Xf) {
    __shared__ __align__(16) float tile[96][68];
    const int b = blockIdx.y, n0 = blockIdx.x * 64, t = threadIdx.x;
    for (int phase = 0; phase < 2; phase++) {
        __syncthreads();
#pragma unroll
        for (int i = 0; i < 6; i++) {
            int idx = t + i * 256;                 // 96 rows x 16 float4
            int r = idx >> 4, c4 = (idx & 15) * 4;
            *(float4*)&tile[r][c4] =
                *(const float4*)&X[((size_t)b * CH + phase * 96 + r) * HW + n0 + c4];
        }
        __syncthreads();
        int n = t & 63, part = t >> 6;
        __half* rowp = Xf + ((size_t)b * HW + n0 + n) * 192 + phase * 96 + part * 24;
#pragma unroll
        for (int g2 = 0; g2 < 3; g2++) {
            __align__(16) __half h8[8];
#pragma unroll
            for (int j = 0; j < 8; j++)
                h8[j] = __float2half_rn(tile[part * 24 + g2 * 8 + j][n]);
            *(uint4*)(rowp + g2 * 8) = *(const uint4*)h8;
        }
    }
}

// ---------------- fp16 GEMM via mma.sync: Y[b,m,n] = W·X + bias (fp16 out)
// A = Wb [Mtot,192] k-major, 3 chunks smem-resident
// B = Xf [B][HW,192] k-major pixel rows, 3 chunks double-buffered
#define SM_A 0
#define SM_B (3 * 16384)
#define SMEM_GEMM (1024 + SM_B + 2 * 32768)

__global__ void __launch_bounds__(256, 1)
gemm_mma(const __half* __restrict__ Xf, const __half* __restrict__ Wb,
         const float* __restrict__ bias, __half* __restrict__ Y, int Mtot) {
    extern __shared__ __align__(16) char smraw[];
    uint32_t sbr = smem_u32(smraw);
    uint32_t sb = (sbr + 1023) & ~1023u;
    const int t = threadIdx.x;
    const int warp = t >> 5, lane = t & 31;
    const int wm = warp >> 2, wn = warp & 3;      // 2 x 4 warps, 64x64 each
    const int b = blockIdx.z;
    const int M0 = blockIdx.x * 128;              // m fastest -> B-tile L2 reuse
    const int N0 = blockIdx.y * 256;

    // A: 3 chunks (48KB). Zero-pad m>=Mtot.
#pragma unroll
    for (int i = 0; i < 12; i++) {
        int u = t + i * 256;
        int ca = u >> 10, v = u & 1023;
        int row = v >> 3, q = v & 7;
        const void* src = Wb + (size_t)(M0 + row) * CH + ca * 64 + q * 8;
        cp16(sb + SM_A + ca * 16384 + SWZ(row * 128 + q * 16), src,
             (M0 + row < Mtot) ? 16 : 0);
    }
    const __half* xbase = Xf + ((size_t)b * HW + N0) * 192;
#pragma unroll
    for (int i = 0; i < 8; i++) {
        int u = t + i * 256;
        int row = u >> 3, q = u & 7;
        cp16(sb + SM_B + SWZ(row * 128 + q * 16), xbase + (size_t)row * 192 + q * 8, 16);
    }
    CP_COMMIT();
#pragma unroll
    for (int i = 0; i < 8; i++) {
        int u = t + i * 256;
        int row = u >> 3, q = u & 7;
        cp16(sb + SM_B + 32768 + SWZ(row * 128 + q * 16),
             xbase + (size_t)row * 192 + 64 + q * 8, 16);
    }
    CP_COMMIT();

    float acc[4][8][4];
#pragma unroll
    for (int i = 0; i < 4; i++)
#pragma unroll
        for (int j = 0; j < 8; j++)
#pragma unroll
            for (int k = 0; k < 4; k++) acc[i][j][k] = 0.f;

    for (int bi = 0; bi < 3; bi++) {
        if (bi < 2) asm volatile("cp.async.wait_group 1;" ::: "memory");
        else        asm volatile("cp.async.wait_group 0;" ::: "memory");
        __syncthreads();

        const uint32_t bbuf = sb + SM_B + (uint32_t)(bi & 1) * 32768;
        const uint32_t abuf = sb + SM_A + (uint32_t)bi * 16384;
#pragma unroll
        for (int kk = 0; kk < 4; kk++) {
            uint32_t af[4][4];
#pragma unroll
            for (int mf = 0; mf < 4; mf++) {
                int row = wm * 64 + mf * 16 + (lane & 7) + ((lane & 8) ? 8 : 0);
                int cb = kk * 32 + ((lane & 16) ? 16 : 0);
                LDSM4(af[mf][0], af[mf][1], af[mf][2], af[mf][3],
                      abuf + SWZ(row * 128 + cb));
            }
#pragma unroll
            for (int nf2 = 0; nf2 < 4; nf2++) {
                int row = wn * 64 + nf2 * 16 + (lane & 7) + ((lane & 16) ? 8 : 0);
                int cb = kk * 32 + ((lane & 8) ? 16 : 0);
                uint32_t b0, b1, b2, b3;
                LDSM4(b0, b1, b2, b3, bbuf + SWZ(row * 128 + cb));
#pragma unroll
                for (int mf = 0; mf < 4; mf++) {
                    MMA16816(acc[mf][nf2 * 2 + 0], af[mf], b0, b1);
                    MMA16816(acc[mf][nf2 * 2 + 1], af[mf], b2, b3);
                }
            }
        }
        __syncthreads();
        if (bi + 2 < 3) {
            const int c = bi + 2;
#pragma unroll
            for (int i = 0; i < 8; i++) {
                int u = t + i * 256;
                int row = u >> 3, q = u & 7;
                cp16(sb + SM_B + (uint32_t)(c & 1) * 32768 + SWZ(row * 128 + q * 16),
                     xbase + (size_t)row * 192 + c * 64 + q * 8, 16);
            }
            CP_COMMIT();
        }
    }

    const int g = lane >> 2, tg = lane & 3;
#pragma unroll
    for (int mf = 0; mf < 4; mf++) {
#pragma unroll
        for (int half = 0; half < 2; half++) {
            int m = M0 + wm * 64 + mf * 16 + g + half * 8;
            if (m < Mtot) {
                float bs = bias[m];
                __half* yrow = Y + ((size_t)b * Mtot + m) * HW + N0 + wn * 64 + tg * 2;
#pragma unroll
                for (int nf = 0; nf < 8; nf++)
                    *(__half2*)(yrow + nf * 8) =
                        __floats2half2_rn(acc[mf][nf][half * 2 + 0] + bs,
                                          acc[mf][nf][half * 2 + 1] + bs);
            }
        }
    }
}

// ---------------- 3x3 depthwise conv (groups=576), 32-row tiles, fp16 in/out
__global__ void __launch_bounds__(256) dwconv_kernel(const __half* __restrict__ in,
                                                     const float* __restrict__ w,
                                                     const float* __restrict__ bias,
                                                     __half* __restrict__ out) {
    const int b = blockIdx.z, ch = blockIdx.y;
    const int t = threadIdx.x;
    const int r0 = blockIdx.x * 32;
    __shared__ __align__(16) float sm[34][132];
    const __half* src = in + ((size_t)b * QKVC + ch) * HW;

#pragma unroll
    for (int i = 0; i < 3; i++) {
        int idx = t + i * 256;
        if (idx < 544) {                          // 34 rows x 16 uint4 (8 halves)
            int rr = idx >> 4, c8 = (idx & 15) * 8;
            int gr = r0 - 1 + rr;
            float f8[8] = {};
            if (gr >= 0 && gr < 128) {
                uint4 v = *(const uint4*)(src + gr * 128 + c8);
                h8_to_f(v, f8);
            }
#pragma unroll
            for (int j = 0; j < 8; j++) sm[rr][c8 + j] = f8[j];
        }
    }
    float wv[9];
#pragma unroll
    for (int i = 0; i < 9; i++) wv[i] = w[ch * 9 + i];
    const float bsv = bias[ch];
    __syncthreads();

    const int lr = (t >> 4) * 2;                  // output row pair within tile
    const int xo = (t & 15) * 8;
    float R[4][16];
#pragma unroll
    for (int dy = 0; dy < 4; dy++) {
        const float* row = sm[lr + dy];
        float4 v;
        v = (xo > 0) ? *(const float4*)(row + xo - 4) : make_float4(0, 0, 0, 0);
        R[dy][0] = v.x; R[dy][1] = v.y; R[dy][2] = v.z; R[dy][3] = v.w;
        v = *(const float4*)(row + xo);
        R[dy][4] = v.x; R[dy][5] = v.y; R[dy][6] = v.z; R[dy][7] = v.w;
        v = *(const float4*)(row + xo + 4);
        R[dy][8] = v.x; R[dy][9] = v.y; R[dy][10] = v.z; R[dy][11] = v.w;
        v = (xo < 120) ? *(const float4*)(row + xo + 8) : make_float4(0, 0, 0, 0);
        R[dy][12] = v.x; R[dy][13] = v.y; R[dy][14] = v.z; R[dy][15] = v.w;
    }
    float ss = 0.f;
#pragma unroll
    for (int rr2 = 0; rr2 < 2; rr2++) {
        float o[8];
#pragma unroll
        for (int i = 0; i < 8; i++) {
            float a = bsv;
#pragma unroll
            for (int dy = 0; dy < 3; dy++)
                a += wv[dy * 3 + 0] * R[rr2 + dy][3 + i] +
                     wv[dy * 3 + 1] * R[rr2 + dy][4 + i] +
                     wv[dy * 3 + 2] * R[rr2 + dy][5 + i];
            o[i] = a; ss += a * a;
        }
        __align__(16) __half oh[8];
#pragma unroll
        for (int i = 0; i < 8; i++) oh[i] = __float2half_rn(o[i]);
        *(uint4*)(out + ((size_t)b * QKVC + ch) * HW + (r0 + lr + rr2) * 128 + xo) =
            *(const uint4*)oh;
    }

    if (ch < 2 * CH) {
#pragma unroll
        for (int off = 16; off > 0; off >>= 1)
            ss += __shfl_xor_sync(0xFFFFFFFFu, ss, off);
        if ((t & 31) == 0) atomicAdd(&g_sumsq[b * 2 * CH + ch], ss);
    }
}

// ---------------- attention scores via mma.sync: S[bh] += q·k^T over split-K
#define ATM_SMEM (1024 + 2 * 16384)

__global__ void __launch_bounds__(256) attn_mma(const __half* __restrict__ qkv) {
    extern __shared__ __align__(16) char atraw[];
    uint32_t sbr = smem_u32(atraw);
    uint32_t sb = (sbr + 1023) & ~1023u;
    const int bh = blockIdx.y, b = bh >> 2, h = bh & 3;
    const int t = threadIdx.x;
    const int warp = t >> 5, lane = t & 31;
    const int wm = warp >> 2, wn = warp & 3;      // warp tile m32 x n16
    const __half* qbase = qkv + ((size_t)b * QKVC + h * CPH) * HW;
    const __half* kbase = qbase + (size_t)CH * HW;
    const int n0 = blockIdx.x * 2048;             // 32 iterations of k64

#define ATM_LOAD(it) do {                                                          \
        const int _nw = n0 + (it) * 64;                                            \
        _Pragma("unroll")                                                          \
        for (int _i = 0; _i < 4; _i++) {                                           \
            int _u = t + _i * 256;                                                 \
            int _isK = _u >= 512;                                                  \
            int _v = _u & 511;                                                     \
            int _row = _v >> 3, _q8 = _v & 7;                                      \
            const __half* _src = (_isK ? kbase : qbase) + (size_t)_row * HW + _nw + _q8 * 8; \
            cp16(sb + (uint32_t)((it) & 1) * 16384 + (_isK ? 8192 : 0) +           \
                     SWZ(_row * 128 + _q8 * 16),                                   \
                 _src, (_row < CPH) ? 16 : 0);                                     \
        }                                                                          \
        CP_COMMIT();                                                               \
    } while (0)

    ATM_LOAD(0);
    ATM_LOAD(1);

    float acc[2][2][4];
#pragma unroll
    for (int i = 0; i < 2; i++)
#pragma unroll
        for (int j = 0; j < 2; j++)
#pragma unroll
            for (int k = 0; k < 4; k++) acc[i][j][k] = 0.f;

    for (int bi = 0; bi < 32; bi++) {
        if (bi < 31) asm volatile("cp.async.wait_group 1;" ::: "memory");
        else         asm volatile("cp.async.wait_group 0;" ::: "memory");
        __syncthreads();
        const uint32_t qbuf = sb + (uint32_t)(bi & 1) * 16384;
        const uint32_t kbuf = qbuf + 8192;
#pragma unroll
        for (int kk = 0; kk < 4; kk++) {
            uint32_t af[2][4];
#pragma unroll
            for (int mf = 0; mf < 2; mf++) {
                int row = wm * 32 + mf * 16 + (lane & 7) + ((lane & 8) ? 8 : 0);
                int cb = kk * 32 + ((lane & 16) ? 16 : 0);
                LDSM4(af[mf][0], af[mf][1], af[mf][2], af[mf][3],
                      qbuf + SWZ(row * 128 + cb));
            }
            int rowb = wn * 16 + (lane & 7) + ((lane & 16) ? 8 : 0);
            int cbb = kk * 32 + ((lane & 8) ? 16 : 0);
            uint32_t b0, b1, b2, b3;
            LDSM4(b0, b1, b2, b3, kbuf + SWZ(rowb * 128 + cbb));
#pragma unroll
            for (int mf = 0; mf < 2; mf++) {
                MMA16816(acc[mf][0], af[mf], b0, b1);
                MMA16816(acc[mf][1], af[mf], b2, b3);
            }
        }
        __syncthreads();
        if (bi + 2 < 32) ATM_LOAD(bi + 2);
    }
#undef ATM_LOAD

    float* Sb = g_S + (size_t)bh * CPH * CPH;
    const int g = lane >> 2, tg = lane & 3;
#pragma unroll
    for (int mf = 0; mf < 2; mf++)
#pragma unroll
        for (int half = 0; half < 2; half++) {
            int m = wm * 32 + mf * 16 + g + half * 8;
            if (m < CPH) {
#pragma unroll
                for (int nf = 0; nf < 2; nf++)
#pragma unroll
                    for (int j = 0; j < 2; j++) {
                        int d = wn * 16 + nf * 8 + tg * 2 + j;
                        if (d < CPH)
                            atomicAdd(&Sb[m * CPH + d], acc[mf][nf][half * 2 + j]);
                    }
            }
        }
}

// ---------------- softmax with L2-norm + temperature folded in
__global__ void softmax_kernel() {
    const int bh = blockIdx.x;
    const int b = bh >> 2, h = bh & 3;
    const int r = threadIdx.x;
    if (r >= CPH) return;
    const float temp = g_temp[bh];
    const float invq = 1.f / fmaxf(sqrtf(g_sumsq[b * 2 * CH + h * CPH + r]), 1e-12f);
    const float* Srow = g_S + (size_t)bh * CPH * CPH + r * CPH;

    float vals[CPH];
    float mx = -1e30f;
#pragma unroll
    for (int d = 0; d < CPH; d++) {
        float invk = 1.f / fmaxf(sqrtf(g_sumsq[b * 2 * CH + CH + h * CPH + d]), 1e-12f);
        float v = Srow[d] * invq * invk * temp;
        vals[d] = v;
        mx = fmaxf(mx, v);
    }
    float sum = 0.f;
#pragma unroll
    for (int d = 0; d < CPH; d++) { vals[d] = expf(vals[d] - mx); sum += vals[d]; }
    float inv = 1.f / sum;
    float* Arow = g_A + (size_t)bh * CPH * CPH + r * CPH;
#pragma unroll
    for (int d = 0; d < CPH; d++) Arow[d] = vals[d] * inv;
}

// ---------------- Weff[b][m][h*48+d] = sum_cc W2[m][h*48+cc] * A[b][h][cc][d]
__global__ void __launch_bounds__(192) weff_kernel(const float* __restrict__ W2,
                                                   __half* __restrict__ Weff) {
    const int b = blockIdx.x, m = threadIdx.x;   // 192 threads
    __shared__ float As[HEADS * CPH * CPH];       // 36.8KB
    for (int e = m; e < HEADS * CPH * CPH; e += 192)
        As[e] = g_A[(size_t)b * HEADS * CPH * CPH + e];
    __syncthreads();

    __half* wrow_out = Weff + ((size_t)b * 256 + m) * CH;
#pragma unroll
    for (int h = 0; h < HEADS; h++) {
        float wr[CPH];
#pragma unroll
        for (int cc = 0; cc < CPH; cc++) wr[cc] = W2[(size_t)m * CH + h * CPH + cc];
        const float* Ah = As + h * CPH * CPH;
        for (int d0 = 0; d0 < CPH; d0 += 4) {
            float s0 = 0.f, s1 = 0.f, s2 = 0.f, s3 = 0.f;
#pragma unroll
            for (int cc = 0; cc < CPH; cc++) {
                float w = wr[cc];
                const float* ar = Ah + cc * CPH + d0;
                s0 += w * ar[0]; s1 += w * ar[1];
                s2 += w * ar[2]; s3 += w * ar[3];
            }
            wrow_out[h * CPH + d0 + 0] = __float2half_rn(s0);
            wrow_out[h * CPH + d0 + 1] = __float2half_rn(s1);
            wrow_out[h * CPH + d0 + 2] = __float2half_rn(s2);
            wrow_out[h * CPH + d0 + 3] = __float2half_rn(s3);
        }
    }
}

// ---------------- final GEMM: y[b,m,n] = (Weff[b]·v)[m,n] * s(b,n) + outb[m]
// A = Weff [b][192(+pad)][192] fp16; B = v channel-planar rows of q1 (k-major
// across pixels) read via 528B-padded [k][n] tiles + ldmatrix.trans
#define VB_ROW 528
#define VB_BYTES (64 * VB_ROW)
#define SM_VB (3 * 16384)
#define SMEM_OUTV (1024 + SM_VB + 2 * VB_BYTES)

__global__ void __launch_bounds__(256, 1)
gemm_out_v(const __half* __restrict__ qkv, const __half* __restrict__ Weff,
           const float* __restrict__ mask, const float* __restrict__ tbp,
           const float* __restrict__ outb, float* __restrict__ Y) {
    extern __shared__ __align__(16) char smraw[];
    uint32_t sbr = smem_u32(smraw);
    uint32_t sb = (sbr + 1023) & ~1023u;
    const int t = threadIdx.x;
    const int warp = t >> 5, lane = t & 31;
    const int wm = warp >> 2, wn = warp & 3;
    const int b = blockIdx.z;
    const int M0 = blockIdx.x * 128;
    const int N0 = blockIdx.y * 256;
    const __half* vbase = qkv + ((size_t)b * QKVC + 2 * CH) * HW;
    const __half* Wb = Weff + (size_t)b * 256 * CH;

    // A: 3 chunks of [128 m][64 k]
#pragma unroll
    for (int i = 0; i < 12; i++) {
        int u = t + i * 256;
        int ca = u >> 10, v = u & 1023;
        int row = v >> 3, q = v & 7;
        const void* src = Wb + (size_t)(M0 + row) * CH + ca * 64 + q * 8;
        cp16(sb + ca * 16384 + SWZ(row * 128 + q * 16), src,
             (M0 + row < CH) ? 16 : 0);
    }
    // B chunk loader: 64 k-rows x 512B from v[ca*64+kr][N0..N0+255]
#define VB_LOAD(ca) do {                                                           \
        uint32_t _dst = sb + SM_VB + (uint32_t)((ca) & 1) * VB_BYTES;              \
        _Pragma("unroll")                                                          \
        for (int _i = 0; _i < 8; _i++) {                                           \
            int _u = t + _i * 256;                                                 \
            int _kr = _u >> 5, _q = _u & 31;                                       \
            cp16(_dst + _kr * VB_ROW + _q * 16,                                    \
                 vbase + (size_t)((ca) * 64 + _kr) * HW + N0 + _q * 8, 16);        \
        }                                                                          \
        CP_COMMIT();                                                               \
    } while (0)

    VB_LOAD(0);
    VB_LOAD(1);

    float acc[4][8][4];
#pragma unroll
    for (int i = 0; i < 4; i++)
#pragma unroll
        for (int j = 0; j < 8; j++)
#pragma unroll
            for (int k = 0; k < 4; k++) acc[i][j][k] = 0.f;

    for (int bi = 0; bi < 3; bi++) {
        if (bi < 2) asm volatile("cp.async.wait_group 1;" ::: "memory");
        else        asm volatile("cp.async.wait_group 0;" ::: "memory");
        __syncthreads();

        const uint32_t abuf = sb + (uint32_t)bi * 16384;
        const uint32_t vbuf = sb + SM_VB + (uint32_t)(bi & 1) * VB_BYTES;
#pragma unroll
        for (int kk = 0; kk < 4; kk++) {
            uint32_t af[4][4];
#pragma unroll
            for (int mf = 0; mf < 4; mf++) {
                int row = wm * 64 + mf * 16 + (lane & 7) + ((lane & 8) ? 8 : 0);
                int cb = kk * 32 + ((lane & 16) ? 16 : 0);
                LDSM4(af[mf][0], af[mf][1], af[mf][2], af[mf][3],
                      abuf + SWZ(row * 128 + cb));
            }
#pragma unroll
            for (int nf2 = 0; nf2 < 4; nf2++) {
                // trans load from [k][n]: rows kk*16.., cols wn*64+nf2*16..
                int krow = kk * 16 + (lane & 7) + ((lane & 8) ? 8 : 0);
                int ncol = wn * 64 + nf2 * 16 + ((lane & 16) ? 8 : 0);
                uint32_t b0, b1, b2, b3;
                LDSM4T(b0, b1, b2, b3, vbuf + krow * VB_ROW + ncol * 2);
#pragma unroll
                for (int mf = 0; mf < 4; mf++) {
                    MMA16816(acc[mf][nf2 * 2 + 0], af[mf], b0, b1);
                    MMA16816(acc[mf][nf2 * 2 + 1], af[mf], b2, b3);
                }
            }
        }
        __syncthreads();
        if (bi + 2 < 3) VB_LOAD(bi + 2);
    }
#undef VB_LOAD

    // Epilogue: y = acc * s(n) + bias, fp32 out
    const int g = lane >> 2, tg = lane & 3;
    const float tb = fminf(fmaxf(*tbp, 0.1f), 0.5f);
    const float* mrow = mask + (size_t)b * HW;
    const int nbase = N0 + wn * 64 + tg * 2;
    float2 sp[8];
#pragma unroll
    for (int nf = 0; nf < 8; nf++) {
        sp[nf].x = 1.f + tb * mrow[nbase + nf * 8];
        sp[nf].y = 1.f + tb * mrow[nbase + nf * 8 + 1];
    }
#pragma unroll
    for (int mf = 0; mf < 4; mf++) {
#pragma unroll
        for (int half = 0; half < 2; half++) {
            int m = M0 + wm * 64 + mf * 16 + g + half * 8;
            if (m < CH) {
                float bs = outb[m];
                float* yrow = Y + ((size_t)b * CH + m) * HW + nbase;
#pragma unroll
                for (int nf = 0; nf < 8; nf++)
                    *(float2*)(yrow + nf * 8) =
                        make_float2(acc[mf][nf][half * 2 + 0] * sp[nf].x + bs,
                                    acc[mf][nf][half * 2 + 1] * sp[nf].y + bs);
            }
        }
    }
}

// ---------------- host launcher ----------------
extern "C" void kernel_launch(void* const* d_in, const int* in_sizes, int n_in,
                              void* d_out, int out_size) {
    const float* x    = (const float*)d_in[0];
    const float* mask = (const float*)d_in[1];
    const float* qkvw = (const float*)d_in[2];
    const float* qkvb = (const float*)d_in[3];
    const float* dww  = (const float*)d_in[4];
    const float* dwb  = (const float*)d_in[5];
    const float* outw = (const float*)d_in[6];
    const float* outb = (const float*)d_in[7];
    const float* det  = (const float*)d_in[8];
    const float* smo  = (const float*)d_in[9];
    const float* tbp  = (const float*)d_in[10];
    float* y = (float*)d_out;

    void *p_q0 = nullptr, *p_q1 = nullptr, *p_xf = nullptr, *p_wb = nullptr, *p_we = nullptr;
    cudaGetSymbolAddress(&p_q0, g_q0h);
    cudaGetSymbolAddress(&p_q1, g_q1h);
    cudaGetSymbolAddress(&p_xf, g_xf4);
    cudaGetSymbolAddress(&p_wb, g_wb4);
    cudaGetSymbolAddress(&p_we, g_weff);

    cudaFuncSetAttribute(gemm_mma, cudaFuncAttributeMaxDynamicSharedMemorySize, SMEM_GEMM);
    cudaFuncSetAttribute(gemm_out_v, cudaFuncAttributeMaxDynamicSharedMemorySize, SMEM_OUTV);
    cudaFuncSetAttribute(attn_mma, cudaFuncAttributeMaxDynamicSharedMemorySize, ATM_SMEM);

    prep_kernel<<<BATCH, 256>>>(mask, det, smo);
    convert_w<<<QKVC, 192>>>(qkvw, (__half*)p_wb);
    convert_x<<<dim3(HW / 64, BATCH), 256>>>(x, (__half*)p_xf);
    // qkv 1x1 conv: fp16 mma.sync GEMM -> fp16 output
    gemm_mma<<<dim3(5, HW / 256, BATCH), 256, SMEM_GEMM>>>(
        (const __half*)p_xf, (const __half*)p_wb, qkvb, (__half*)p_q0, QKVC);
    // 3x3 depthwise (+ fused q/k sum-of-squares)
    dwconv_kernel<<<dim3(4, QKVC, BATCH), 256>>>(
        (const __half*)p_q0, dww, dwb, (__half*)p_q1);
    // channel attention scores via tensor cores
    attn_mma<<<dim3(8, BATCH * HEADS), 256, ATM_SMEM>>>((const __half*)p_q1);
    softmax_kernel<<<BATCH * HEADS, 64>>>();
    // fold attention into projection: Weff = W2 · blockdiag(A)
    weff_kernel<<<BATCH, 192>>>(outw, (__half*)p_we);
    // y = (Weff @ v) * s(n) + outb
    gemm_out_v<<<dim3(2, HW / 256, BATCH), 256, SMEM_OUTV>>>(
        (const __half*)p_q1, (const __half*)p_we, mask, tbp, outb, y);
}

// round 9
// speedup vs baseline: 6.2748x; 1.0866x over previous
#include <cuda_runtime.h>
#include <cuda_fp16.h>
#include <math.h>
#include <stdint.h>

// Problem constants
#define BATCH 8
#define CH    192
#define QKVC  576
#define HW    16384
#define HEADS 4
#define CPH   48

// ---------------- scratch (static device memory; no allocs) ----------------
__device__ uint4 g_q0h[(size_t)BATCH * QKVC * HW * 2 / 16];   // fp16 qkv after 1x1
__device__ uint4 g_q1h[(size_t)BATCH * QKVC * HW * 2 / 16];   // fp16 qkv after dw
__device__ float g_sumsq[BATCH * 2 * CH];
__device__ float g_S[BATCH * HEADS * CPH * CPH];
__device__ float g_A[BATCH * HEADS * CPH * CPH];
__device__ float g_masksum[BATCH];
__device__ uint4 g_xf4[(size_t)BATCH * HW * 192 * 2 / 16];    // [B][HW][192] fp16
__device__ uint4 g_wb4[(size_t)(QKVC + 64) * CH * 2 / 16];    // [576(+pad)][192] fp16
__device__ uint4 g_weff[(size_t)BATCH * 256 * CH * 2 / 16];   // [B][192(+pad)][192] fp16

// ---------------- helpers ----------------
__device__ __forceinline__ uint32_t smem_u32(const void* p) {
    uint32_t a;
    asm("{ .reg .u64 t; cvta.to.shared.u64 t, %1; cvt.u32.u64 %0, t; }" : "=r"(a) : "l"(p));
    return a;
}
#define SWZ(off) ((off) ^ (((off) >> 3) & 0x70))

__device__ __forceinline__ void cp16(uint32_t dst, const void* src, int srcsz) {
    asm volatile("cp.async.cg.shared.global [%0], [%1], 16, %2;"
                 :: "r"(dst), "l"(src), "r"(srcsz) : "memory");
}
#define CP_COMMIT() asm volatile("cp.async.commit_group;" ::: "memory")

#define LDSM4(r0, r1, r2, r3, addr)                                            \
    asm volatile("ldmatrix.sync.aligned.m8n8.x4.shared.b16 {%0,%1,%2,%3}, [%4];" \
                 : "=r"(r0), "=r"(r1), "=r"(r2), "=r"(r3) : "r"(addr))

#define LDSM4T(r0, r1, r2, r3, addr)                                           \
    asm volatile("ldmatrix.sync.aligned.m8n8.x4.trans.shared.b16 {%0,%1,%2,%3}, [%4];" \
                 : "=r"(r0), "=r"(r1), "=r"(r2), "=r"(r3) : "r"(addr))

#define MMA16816(c, a, b0, b1)                                                 \
    asm volatile("mma.sync.aligned.m16n8k16.row.col.f32.f16.f16.f32 "          \
                 "{%0,%1,%2,%3},{%4,%5,%6,%7},{%8,%9},{%0,%1,%2,%3};"          \
                 : "+f"((c)[0]), "+f"((c)[1]), "+f"((c)[2]), "+f"((c)[3])      \
                 : "r"((a)[0]), "r"((a)[1]), "r"((a)[2]), "r"((a)[3]),         \
                   "r"(b0), "r"(b1))

__device__ __forceinline__ void h8_to_f(const uint4 v, float* f) {
    const __half2* h2 = (const __half2*)&v;
#pragma unroll
    for (int i = 0; i < 4; i++) {
        float2 x = __half22float2(h2[i]);
        f[i * 2 + 0] = x.x;
        f[i * 2 + 1] = x.y;
    }
}

// ---------------- zero accumulators ----------------
__global__ void prep_zero() {
    const int idx = blockIdx.x * 256 + threadIdx.x;   // 32 blocks
    for (int i = idx; i < BATCH * HEADS * CPH * CPH; i += 32 * 256) g_S[i] = 0.f;
    for (int i = idx; i < BATCH * 2 * CH; i += 32 * 256) g_sumsq[i] = 0.f;
    if (idx < BATCH) g_masksum[idx] = 0.f;
}

// ---------------- mask partial sums ----------------
__global__ void mask_sum(const float* __restrict__ mask) {
    const int b = blockIdx.y, t = threadIdx.x;
    const float4* m4 = (const float4*)(mask + (size_t)b * HW) + blockIdx.x * 512;
    float s = 0.f;
    for (int i = t; i < 512; i += 256) {
        float4 v = m4[i];
        s += v.x + v.y + v.z + v.w;
    }
#pragma unroll
    for (int o = 16; o > 0; o >>= 1) s += __shfl_xor_sync(0xFFFFFFFFu, s, o);
    __shared__ float red[8];
    if ((t & 31) == 0) red[t >> 5] = s;
    __syncthreads();
    if (t == 0) {
        float tot = 0.f;
#pragma unroll
        for (int i = 0; i < 8; i++) tot += red[i];
        atomicAdd(&g_masksum[b], tot);
    }
}

// ---------------- fp32 -> fp16 weight convert: W[M,192] -> Wb[M,192]
__global__ void convert_w(const float* __restrict__ W, __half* __restrict__ Wb) {
    int m = blockIdx.x, k = threadIdx.x;   // 192 threads
    Wb[(size_t)m * CH + k] = __float2half_rn(W[(size_t)m * CH + k]);
}

// ---------------- fp32 [B,192,HW] -> transposed fp16 [B,HW,192]
__global__ void __launch_bounds__(256) convert_x(const float* __restrict__ X,
                                                 __half* __restrict__ Xf) {
    __shared__ __align__(16) float tile[96][68];
    const int b = blockIdx.y, n0 = blockIdx.x * 64, t = threadIdx.x;
    for (int phase = 0; phase < 2; phase++) {
        __syncthreads();
#pragma unroll
        for (int i = 0; i < 6; i++) {
            int idx = t + i * 256;                 // 96 rows x 16 float4
            int r = idx >> 4, c4 = (idx & 15) * 4;
            *(float4*)&tile[r][c4] =
                *(const float4*)&X[((size_t)b * CH + phase * 96 + r) * HW + n0 + c4];
        }
        __syncthreads();
        int n = t & 63, part = t >> 6;
        __half* rowp = Xf + ((size_t)b * HW + n0 + n) * 192 + phase * 96 + part * 24;
#pragma unroll
        for (int g2 = 0; g2 < 3; g2++) {
            __align__(16) __half h8[8];
#pragma unroll
            for (int j = 0; j < 8; j++)
                h8[j] = __float2half_rn(tile[part * 24 + g2 * 8 + j][n]);
            *(uint4*)(rowp + g2 * 8) = *(const uint4*)h8;
        }
    }
}

// ---------------- fp16 GEMM via mma.sync: Y[b,m,n] = W·X + bias (fp16 out)
// CTA tile 128x128, warp tile 64x32 (8 warps 2m x 4n), 2 CTAs/SM
#define SM_A 0
#define SM_B (3 * 16384)
#define SMEM_GEMM (1024 + SM_B + 2 * 16384)

__global__ void __launch_bounds__(256, 2)
gemm_mma(const __half* __restrict__ Xf, const __half* __restrict__ Wb,
         const float* __restrict__ bias, __half* __restrict__ Y, int Mtot) {
    extern __shared__ __align__(16) char smraw[];
    uint32_t sbr = smem_u32(smraw);
    uint32_t sb = (sbr + 1023) & ~1023u;
    const int t = threadIdx.x;
    const int warp = t >> 5, lane = t & 31;
    const int wm = warp >> 2, wn = warp & 3;      // warp tile m64 x n32
    const int b = blockIdx.z;
    const int M0 = blockIdx.x * 128;              // m fastest -> B-tile L2 reuse
    const int N0 = blockIdx.y * 128;

    // A: 3 chunks (48KB). Zero-pad m>=Mtot.
#pragma unroll
    for (int i = 0; i < 12; i++) {
        int u = t + i * 256;
        int ca = u >> 10, v = u & 1023;
        int row = v >> 3, q = v & 7;
        const void* src = Wb + (size_t)(M0 + row) * CH + ca * 64 + q * 8;
        cp16(sb + SM_A + ca * 16384 + SWZ(row * 128 + q * 16), src,
             (M0 + row < Mtot) ? 16 : 0);
    }
    const __half* xbase = Xf + ((size_t)b * HW + N0) * 192;
    // B chunk loader: 128 pixel rows x 128B
#define XB_LOAD(ca) do {                                                           \
        uint32_t _dst = sb + SM_B + (uint32_t)((ca) & 1) * 16384;                  \
        _Pragma("unroll")                                                          \
        for (int _i = 0; _i < 4; _i++) {                                           \
            int _u = t + _i * 256;                                                 \
            int _row = _u >> 3, _q = _u & 7;                                       \
            cp16(_dst + SWZ(_row * 128 + _q * 16),                                 \
                 xbase + (size_t)_row * 192 + (ca) * 64 + _q * 8, 16);             \
        }                                                                          \
        CP_COMMIT();                                                               \
    } while (0)

    XB_LOAD(0);
    XB_LOAD(1);

    float acc[4][4][4];
#pragma unroll
    for (int i = 0; i < 4; i++)
#pragma unroll
        for (int j = 0; j < 4; j++)
#pragma unroll
            for (int k = 0; k < 4; k++) acc[i][j][k] = 0.f;

    for (int bi = 0; bi < 3; bi++) {
        if (bi < 2) asm volatile("cp.async.wait_group 1;" ::: "memory");
        else        asm volatile("cp.async.wait_group 0;" ::: "memory");
        __syncthreads();

        const uint32_t bbuf = sb + SM_B + (uint32_t)(bi & 1) * 16384;
        const uint32_t abuf = sb + SM_A + (uint32_t)bi * 16384;
#pragma unroll
        for (int kk = 0; kk < 4; kk++) {
            uint32_t af[4][4];
#pragma unroll
            for (int mf = 0; mf < 4; mf++) {
                int row = wm * 64 + mf * 16 + (lane & 7) + ((lane & 8) ? 8 : 0);
                int cb = kk * 32 + ((lane & 16) ? 16 : 0);
                LDSM4(af[mf][0], af[mf][1], af[mf][2], af[mf][3],
                      abuf + SWZ(row * 128 + cb));
            }
#pragma unroll
            for (int nf2 = 0; nf2 < 2; nf2++) {
                int row = wn * 32 + nf2 * 16 + (lane & 7) + ((lane & 16) ? 8 : 0);
                int cb = kk * 32 + ((lane & 8) ? 16 : 0);
                uint32_t b0, b1, b2, b3;
                LDSM4(b0, b1, b2, b3, bbuf + SWZ(row * 128 + cb));
#pragma unroll
                for (int mf = 0; mf < 4; mf++) {
                    MMA16816(acc[mf][nf2 * 2 + 0], af[mf], b0, b1);
                    MMA16816(acc[mf][nf2 * 2 + 1], af[mf], b2, b3);
                }
            }
        }
        __syncthreads();
        if (bi + 2 < 3) XB_LOAD(bi + 2);
    }
#undef XB_LOAD

    const int g = lane >> 2, tg = lane & 3;
#pragma unroll
    for (int mf = 0; mf < 4; mf++) {
#pragma unroll
        for (int half = 0; half < 2; half++) {
            int m = M0 + wm * 64 + mf * 16 + g + half * 8;
            if (m < Mtot) {
                float bs = bias[m];
                __half* yrow = Y + ((size_t)b * Mtot + m) * HW + N0 + wn * 32 + tg * 2;
#pragma unroll
                for (int nf = 0; nf < 4; nf++)
                    *(__half2*)(yrow + nf * 8) =
                        __floats2half2_rn(acc[mf][nf][half * 2 + 0] + bs,
                                          acc[mf][nf][half * 2 + 1] + bs);
            }
        }
    }
}

// ---------------- 3x3 depthwise conv (groups=576), 32-row tiles, fp16 in/out
__global__ void __launch_bounds__(256) dwconv_kernel(const __half* __restrict__ in,
                                                     const float* __restrict__ w,
                                                     const float* __restrict__ bias,
                                                     __half* __restrict__ out) {
    const int b = blockIdx.z, ch = blockIdx.y;
    const int t = threadIdx.x;
    const int r0 = blockIdx.x * 32;
    __shared__ __align__(16) float sm[34][132];
    const __half* src = in + ((size_t)b * QKVC + ch) * HW;

#pragma unroll
    for (int i = 0; i < 3; i++) {
        int idx = t + i * 256;
        if (idx < 544) {                          // 34 rows x 16 uint4 (8 halves)
            int rr = idx >> 4, c8 = (idx & 15) * 8;
            int gr = r0 - 1 + rr;
            float f8[8] = {};
            if (gr >= 0 && gr < 128) {
                uint4 v = *(const uint4*)(src + gr * 128 + c8);
                h8_to_f(v, f8);
            }
#pragma unroll
            for (int j = 0; j < 8; j++) sm[rr][c8 + j] = f8[j];
        }
    }
    float wv[9];
#pragma unroll
    for (int i = 0; i < 9; i++) wv[i] = w[ch * 9 + i];
    const float bsv = bias[ch];
    __syncthreads();

    const int lr = (t >> 4) * 2;                  // output row pair within tile
    const int xo = (t & 15) * 8;
    float R[4][16];
#pragma unroll
    for (int dy = 0; dy < 4; dy++) {
        const float* row = sm[lr + dy];
        float4 v;
        v = (xo > 0) ? *(const float4*)(row + xo - 4) : make_float4(0, 0, 0, 0);
        R[dy][0] = v.x; R[dy][1] = v.y; R[dy][2] = v.z; R[dy][3] = v.w;
        v = *(const float4*)(row + xo);
        R[dy][4] = v.x; R[dy][5] = v.y; R[dy][6] = v.z; R[dy][7] = v.w;
        v = *(const float4*)(row + xo + 4);
        R[dy][8] = v.x; R[dy][9] = v.y; R[dy][10] = v.z; R[dy][11] = v.w;
        v = (xo < 120) ? *(const float4*)(row + xo + 8) : make_float4(0, 0, 0, 0);
        R[dy][12] = v.x; R[dy][13] = v.y; R[dy][14] = v.z; R[dy][15] = v.w;
    }
    float ss = 0.f;
#pragma unroll
    for (int rr2 = 0; rr2 < 2; rr2++) {
        float o[8];
#pragma unroll
        for (int i = 0; i < 8; i++) {
            float a = bsv;
#pragma unroll
            for (int dy = 0; dy < 3; dy++)
                a += wv[dy * 3 + 0] * R[rr2 + dy][3 + i] +
                     wv[dy * 3 + 1] * R[rr2 + dy][4 + i] +
                     wv[dy * 3 + 2] * R[rr2 + dy][5 + i];
            o[i] = a; ss += a * a;
        }
        __align__(16) __half oh[8];
#pragma unroll
        for (int i = 0; i < 8; i++) oh[i] = __float2half_rn(o[i]);
        *(uint4*)(out + ((size_t)b * QKVC + ch) * HW + (r0 + lr + rr2) * 128 + xo) =
            *(const uint4*)oh;
    }

    if (ch < 2 * CH) {
#pragma unroll
        for (int off = 16; off > 0; off >>= 1)
            ss += __shfl_xor_sync(0xFFFFFFFFu, ss, off);
        if ((t & 31) == 0) atomicAdd(&g_sumsq[b * 2 * CH + ch], ss);
    }
}

// ---------------- attention scores via mma.sync: S[bh] += q·k^T over split-K
#define ATM_SMEM (1024 + 2 * 16384)

__global__ void __launch_bounds__(256) attn_mma(const __half* __restrict__ qkv) {
    extern __shared__ __align__(16) char atraw[];
    uint32_t sbr = smem_u32(atraw);
    uint32_t sb = (sbr + 1023) & ~1023u;
    const int bh = blockIdx.y, b = bh >> 2, h = bh & 3;
    const int t = threadIdx.x;
    const int warp = t >> 5, lane = t & 31;
    const int wm = warp >> 2, wn = warp & 3;      // warp tile m32 x n16
    const __half* qbase = qkv + ((size_t)b * QKVC + h * CPH) * HW;
    const __half* kbase = qbase + (size_t)CH * HW;
    const int n0 = blockIdx.x * 2048;             // 32 iterations of k64

#define ATM_LOAD(it) do {                                                          \
        const int _nw = n0 + (it) * 64;                                            \
        _Pragma("unroll")                                                          \
        for (int _i = 0; _i < 4; _i++) {                                           \
            int _u = t + _i * 256;                                                 \
            int _isK = _u >= 512;                                                  \
            int _v = _u & 511;                                                     \
            int _row = _v >> 3, _q8 = _v & 7;                                      \
            const __half* _src = (_isK ? kbase : qbase) + (size_t)_row * HW + _nw + _q8 * 8; \
            cp16(sb + (uint32_t)((it) & 1) * 16384 + (_isK ? 8192 : 0) +           \
                     SWZ(_row * 128 + _q8 * 16),                                   \
                 _src, (_row < CPH) ? 16 : 0);                                     \
        }                                                                          \
        CP_COMMIT();                                                               \
    } while (0)

    ATM_LOAD(0);
    ATM_LOAD(1);

    float acc[2][2][4];
#pragma unroll
    for (int i = 0; i < 2; i++)
#pragma unroll
        for (int j = 0; j < 2; j++)
#pragma unroll
            for (int k = 0; k < 4; k++) acc[i][j][k] = 0.f;

    for (int bi = 0; bi < 32; bi++) {
        if (bi < 31) asm volatile("cp.async.wait_group 1;" ::: "memory");
        else         asm volatile("cp.async.wait_group 0;" ::: "memory");
        __syncthreads();
        const uint32_t qbuf = sb + (uint32_t)(bi & 1) * 16384;
        const uint32_t kbuf = qbuf + 8192;
#pragma unroll
        for (int kk = 0; kk < 4; kk++) {
            uint32_t af[2][4];
#pragma unroll
            for (int mf = 0; mf < 2; mf++) {
                int row = wm * 32 + mf * 16 + (lane & 7) + ((lane & 8) ? 8 : 0);
                int cb = kk * 32 + ((lane & 16) ? 16 : 0);
                LDSM4(af[mf][0], af[mf][1], af[mf][2], af[mf][3],
                      qbuf + SWZ(row * 128 + cb));
            }
            int rowb = wn * 16 + (lane & 7) + ((lane & 16) ? 8 : 0);
            int cbb = kk * 32 + ((lane & 8) ? 16 : 0);
            uint32_t b0, b1, b2, b3;
            LDSM4(b0, b1, b2, b3, kbuf + SWZ(rowb * 128 + cbb));
#pragma unroll
            for (int mf = 0; mf < 2; mf++) {
                MMA16816(acc[mf][0], af[mf], b0, b1);
                MMA16816(acc[mf][1], af[mf], b2, b3);
            }
        }
        __syncthreads();
        if (bi + 2 < 32) ATM_LOAD(bi + 2);
    }
#undef ATM_LOAD

    float* Sb = g_S + (size_t)bh * CPH * CPH;
    const int g = lane >> 2, tg = lane & 3;
#pragma unroll
    for (int mf = 0; mf < 2; mf++)
#pragma unroll
        for (int half = 0; half < 2; half++) {
            int m = wm * 32 + mf * 16 + g + half * 8;
            if (m < CPH) {
#pragma unroll
                for (int nf = 0; nf < 2; nf++)
#pragma unroll
                    for (int j = 0; j < 2; j++) {
                        int d = wn * 16 + nf * 8 + tg * 2 + j;
                        if (d < CPH)
                            atomicAdd(&Sb[m * CPH + d], acc[mf][nf][half * 2 + j]);
                    }
            }
        }
}

// ---------------- softmax with L2-norm + temperature folded in
__global__ void softmax_kernel(const float* __restrict__ det,
                               const float* __restrict__ smo) {
    const int bh = blockIdx.x;
    const int b = bh >> 2, h = bh & 3;
    const int r = threadIdx.x;
    if (r >= CPH) return;
    const float tl = g_masksum[b] / (float)HW;
    const float temp = det[h] * tl + smo[h] * (1.f - tl);
    const float invq = 1.f / fmaxf(sqrtf(g_sumsq[b * 2 * CH + h * CPH + r]), 1e-12f);
    const float* Srow = g_S + (size_t)bh * CPH * CPH + r * CPH;

    float vals[CPH];
    float mx = -1e30f;
#pragma unroll
    for (int d = 0; d < CPH; d++) {
        float invk = 1.f / fmaxf(sqrtf(g_sumsq[b * 2 * CH + CH + h * CPH + d]), 1e-12f);
        float v = Srow[d] * invq * invk * temp;
        vals[d] = v;
        mx = fmaxf(mx, v);
    }
    float sum = 0.f;
#pragma unroll
    for (int d = 0; d < CPH; d++) { vals[d] = expf(vals[d] - mx); sum += vals[d]; }
    float inv = 1.f / sum;
    float* Arow = g_A + (size_t)bh * CPH * CPH + r * CPH;
#pragma unroll
    for (int d = 0; d < CPH; d++) Arow[d] = vals[d] * inv;
}

// ---------------- Weff[b][m][h*48+d] = sum_cc W2[m][h*48+cc] * A[b][h][cc][d]
__global__ void __launch_bounds__(192) weff_kernel(const float* __restrict__ W2,
                                                   __half* __restrict__ Weff) {
    const int b = blockIdx.x, m = threadIdx.x;   // 192 threads
    __shared__ float As[HEADS * CPH * CPH];
    for (int e = m; e < HEADS * CPH * CPH; e += 192)
        As[e] = g_A[(size_t)b * HEADS * CPH * CPH + e];
    __syncthreads();

    __half* wrow_out = Weff + ((size_t)b * 256 + m) * CH;
#pragma unroll
    for (int h = 0; h < HEADS; h++) {
        float wr[CPH];
#pragma unroll
        for (int cc = 0; cc < CPH; cc++) wr[cc] = W2[(size_t)m * CH + h * CPH + cc];
        const float* Ah = As + h * CPH * CPH;
        for (int d0 = 0; d0 < CPH; d0 += 4) {
            float s0 = 0.f, s1 = 0.f, s2 = 0.f, s3 = 0.f;
#pragma unroll
            for (int cc = 0; cc < CPH; cc++) {
                float w = wr[cc];
                const float* ar = Ah + cc * CPH + d0;
                s0 += w * ar[0]; s1 += w * ar[1];
                s2 += w * ar[2]; s3 += w * ar[3];
            }
            wrow_out[h * CPH + d0 + 0] = __float2half_rn(s0);
            wrow_out[h * CPH + d0 + 1] = __float2half_rn(s1);
            wrow_out[h * CPH + d0 + 2] = __float2half_rn(s2);
            wrow_out[h * CPH + d0 + 3] = __float2half_rn(s3);
        }
    }
}

// ---------------- final GEMM: y[b,m,n] = (Weff[b]·v)[m,n] * s(b,n) + outb[m]
// CTA tile 128x128, warp tile 64x32, 2 CTAs/SM; v read via 272B-padded [k][n]
#define VB_ROW 272
#define VB_BYTES (64 * VB_ROW)
#define SM_VB (3 * 16384)
#define SMEM_OUTV (1024 + SM_VB + 2 * VB_BYTES)

__global__ void __launch_bounds__(256, 2)
gemm_out_v(const __half* __restrict__ qkv, const __half* __restrict__ Weff,
           const float* __restrict__ mask, const float* __restrict__ tbp,
           const float* __restrict__ outb, float* __restrict__ Y) {
    extern __shared__ __align__(16) char smraw[];
    uint32_t sbr = smem_u32(smraw);
    uint32_t sb = (sbr + 1023) & ~1023u;
    const int t = threadIdx.x;
    const int warp = t >> 5, lane = t & 31;
    const int wm = warp >> 2, wn = warp & 3;      // warp tile m64 x n32
    const int b = blockIdx.z;
    const int M0 = blockIdx.x * 128;
    const int N0 = blockIdx.y * 128;
    const __half* vbase = qkv + ((size_t)b * QKVC + 2 * CH) * HW;
    const __half* Wb = Weff + (size_t)b * 256 * CH;

    // A: 3 chunks of [128 m][64 k]
#pragma unroll
    for (int i = 0; i < 12; i++) {
        int u = t + i * 256;
        int ca = u >> 10, v = u & 1023;
        int row = v >> 3, q = v & 7;
        const void* src = Wb + (size_t)(M0 + row) * CH + ca * 64 + q * 8;
        cp16(sb + ca * 16384 + SWZ(row * 128 + q * 16), src,
             (M0 + row < CH) ? 16 : 0);
    }
    // B chunk loader: 64 k-rows x 256B from v[ca*64+kr][N0..N0+127]
#define VB_LOAD(ca) do {                                                           \
        uint32_t _dst = sb + SM_VB + (uint32_t)((ca) & 1) * VB_BYTES;              \
        _Pragma("unroll")                                                          \
        for (int _i = 0; _i < 4; _i++) {                                           \
            int _u = t + _i * 256;                                                 \
            int _kr = _u >> 4, _q = _u & 15;                                       \
            cp16(_dst + _kr * VB_ROW + _q * 16,                                    \
                 vbase + (size_t)((ca) * 64 + _kr) * HW + N0 + _q * 8, 16);        \
        }                                                                          \
        CP_COMMIT();                                                               \
    } while (0)

    VB_LOAD(0);
    VB_LOAD(1);

    float acc[4][4][4];
#pragma unroll
    for (int i = 0; i < 4; i++)
#pragma unroll
        for (int j = 0; j < 4; j++)
#pragma unroll
            for (int k = 0; k < 4; k++) acc[i][j][k] = 0.f;

    for (int bi = 0; bi < 3; bi++) {
        if (bi < 2) asm volatile("cp.async.wait_group 1;" ::: "memory");
        else        asm volatile("cp.async.wait_group 0;" ::: "memory");
        __syncthreads();

        const uint32_t abuf = sb + (uint32_t)bi * 16384;
        const uint32_t vbuf = sb + SM_VB + (uint32_t)(bi & 1) * VB_BYTES;
#pragma unroll
        for (int kk = 0; kk < 4; kk++) {
            uint32_t af[4][4];
#pragma unroll
            for (int mf = 0; mf < 4; mf++) {
                int row = wm * 64 + mf * 16 + (lane & 7) + ((lane & 8) ? 8 : 0);
                int cb = kk * 32 + ((lane & 16) ? 16 : 0);
                LDSM4(af[mf][0], af[mf][1], af[mf][2], af[mf][3],
                      abuf + SWZ(row * 128 + cb));
            }
#pragma unroll
            for (int nf2 = 0; nf2 < 2; nf2++) {
                int krow = kk * 16 + (lane & 7) + ((lane & 8) ? 8 : 0);
                int ncol = wn * 32 + nf2 * 16 + ((lane & 16) ? 8 : 0);
                uint32_t b0, b1, b2, b3;
                LDSM4T(b0, b1, b2, b3, vbuf + krow * VB_ROW + ncol * 2);
#pragma unroll
                for (int mf = 0; mf < 4; mf++) {
                    MMA16816(acc[mf][nf2 * 2 + 0], af[mf], b0, b1);
                    MMA16816(acc[mf][nf2 * 2 + 1], af[mf], b2, b3);
                }
            }
        }
        __syncthreads();
        if (bi + 2 < 3) VB_LOAD(bi + 2);
    }
#undef VB_LOAD

    // Epilogue: y = acc * s(n) + bias, fp32 out
    const int g = lane >> 2, tg = lane & 3;
    const float tb = fminf(fmaxf(*tbp, 0.1f), 0.5f);
    const float* mrow = mask + (size_t)b * HW;
    const int nbase = N0 + wn * 32 + tg * 2;
    float2 sp[4];
#pragma unroll
    for (int nf = 0; nf < 4; nf++) {
        sp[nf].x = 1.f + tb * mrow[nbase + nf * 8];
        sp[nf].y = 1.f + tb * mrow[nbase + nf * 8 + 1];
    }
#pragma unroll
    for (int mf = 0; mf < 4; mf++) {
#pragma unroll
        for (int half = 0; half < 2; half++) {
            int m = M0 + wm * 64 + mf * 16 + g + half * 8;
            if (m < CH) {
                float bs = outb[m];
                float* yrow = Y + ((size_t)b * CH + m) * HW + nbase;
#pragma unroll
                for (int nf = 0; nf < 4; nf++)
                    *(float2*)(yrow + nf * 8) =
                        make_float2(acc[mf][nf][half * 2 + 0] * sp[nf].x + bs,
                                    acc[mf][nf][half * 2 + 1] * sp[nf].y + bs);
            }
        }
    }
}

// ---------------- host launcher ----------------
extern "C" void kernel_launch(void* const* d_in, const int* in_sizes, int n_in,
                              void* d_out, int out_size) {
    const float* x    = (const float*)d_in[0];
    const float* mask = (const float*)d_in[1];
    const float* qkvw = (const float*)d_in[2];
    const float* qkvb = (const float*)d_in[3];
    const float* dww  = (const float*)d_in[4];
    const float* dwb  = (const float*)d_in[5];
    const float* outw = (const float*)d_in[6];
    const float* outb = (const float*)d_in[7];
    const float* det  = (const float*)d_in[8];
    const float* smo  = (const float*)d_in[9];
    const float* tbp  = (const float*)d_in[10];
    float* y = (float*)d_out;

    void *p_q0 = nullptr, *p_q1 = nullptr, *p_xf = nullptr, *p_wb = nullptr, *p_we = nullptr;
    cudaGetSymbolAddress(&p_q0, g_q0h);
    cudaGetSymbolAddress(&p_q1, g_q1h);
    cudaGetSymbolAddress(&p_xf, g_xf4);
    cudaGetSymbolAddress(&p_wb, g_wb4);
    cudaGetSymbolAddress(&p_we, g_weff);

    cudaFuncSetAttribute(gemm_mma, cudaFuncAttributeMaxDynamicSharedMemorySize, SMEM_GEMM);
    cudaFuncSetAttribute(gemm_out_v, cudaFuncAttributeMaxDynamicSharedMemorySize, SMEM_OUTV);
    cudaFuncSetAttribute(attn_mma, cudaFuncAttributeMaxDynamicSharedMemorySize, ATM_SMEM);

    prep_zero<<<32, 256>>>();
    mask_sum<<<dim3(8, BATCH), 256>>>(mask);
    convert_w<<<QKVC, 192>>>(qkvw, (__half*)p_wb);
    convert_x<<<dim3(HW / 64, BATCH), 256>>>(x, (__half*)p_xf);
    // qkv 1x1 conv: fp16 mma.sync GEMM -> fp16 output (2 CTAs/SM)
    gemm_mma<<<dim3(5, HW / 128, BATCH), 256, SMEM_GEMM>>>(
        (const __half*)p_xf, (const __half*)p_wb, qkvb, (__half*)p_q0, QKVC);
    // 3x3 depthwise (+ fused q/k sum-of-squares)
    dwconv_kernel<<<dim3(4, QKVC, BATCH), 256>>>(
        (const __half*)p_q0, dww, dwb, (__half*)p_q1);
    // channel attention scores via tensor cores
    attn_mma<<<dim3(8, BATCH * HEADS), 256, ATM_SMEM>>>((const __half*)p_q1);
    softmax_kernel<<<BATCH * HEADS, 64>>>(det, smo);
    // fold attention into projection: Weff = W2 · blockdiag(A)
    weff_kernel<<<BATCH, 192>>>(outw, (__half*)p_we);
    // y = (Weff @ v) * s(n) + outb (2 CTAs/SM)
    gemm_out_v<<<dim3(2, HW / 128, BATCH), 256, SMEM_OUTV>>>(
        (const __half*)p_q1, (const __half*)p_we, mask, tbp, outb, y);
}

// round 10
// speedup vs baseline: 6.4667x; 1.0306x over previous
#include <cuda_runtime.h>
#include <cuda_fp16.h>
#include <math.h>
#include <stdint.h>

// Problem constants
#define BATCH 8
#define CH    192
#define QKVC  576
#define HW    16384
#define HEADS 4
#define CPH   48

// ---------------- scratch (static device memory; no allocs) ----------------
__device__ uint4 g_q0h[(size_t)BATCH * QKVC * HW * 2 / 16];   // fp16 qkv after 1x1 (planar)
__device__ uint4 g_q1h[(size_t)BATCH * QKVC * HW * 2 / 16];   // fp16 qkv after dw (planar)
__device__ float g_sumsq[BATCH * 2 * CH];
__device__ float g_S[BATCH * HEADS * CPH * CPH];
__device__ float g_masksum[BATCH];
__device__ uint4 g_xh4[(size_t)BATCH * CH * HW * 2 / 16];     // [B][192][HW] fp16 planar
__device__ uint4 g_wb4[(size_t)(QKVC + 64) * CH * 2 / 16];    // [576(+pad)][192] fp16
__device__ uint4 g_weff[(size_t)BATCH * 256 * CH * 2 / 16];   // [B][192(+pad)][192] fp16

// ---------------- helpers ----------------
__device__ __forceinline__ uint32_t smem_u32(const void* p) {
    uint32_t a;
    asm("{ .reg .u64 t; cvta.to.shared.u64 t, %1; cvt.u32.u64 %0, t; }" : "=r"(a) : "l"(p));
    return a;
}
#define SWZ(off) ((off) ^ (((off) >> 3) & 0x70))

__device__ __forceinline__ void cp16(uint32_t dst, const void* src, int srcsz) {
    asm volatile("cp.async.cg.shared.global [%0], [%1], 16, %2;"
                 :: "r"(dst), "l"(src), "r"(srcsz) : "memory");
}
#define CP_COMMIT() asm volatile("cp.async.commit_group;" ::: "memory")

#define LDSM4(r0, r1, r2, r3, addr)                                            \
    asm volatile("ldmatrix.sync.aligned.m8n8.x4.shared.b16 {%0,%1,%2,%3}, [%4];" \
                 : "=r"(r0), "=r"(r1), "=r"(r2), "=r"(r3) : "r"(addr))

#define LDSM4T(r0, r1, r2, r3, addr)                                           \
    asm volatile("ldmatrix.sync.aligned.m8n8.x4.trans.shared.b16 {%0,%1,%2,%3}, [%4];" \
                 : "=r"(r0), "=r"(r1), "=r"(r2), "=r"(r3) : "r"(addr))

#define MMA16816(c, a, b0, b1)                                                 \
    asm volatile("mma.sync.aligned.m16n8k16.row.col.f32.f16.f16.f32 "          \
                 "{%0,%1,%2,%3},{%4,%5,%6,%7},{%8,%9},{%0,%1,%2,%3};"          \
                 : "+f"((c)[0]), "+f"((c)[1]), "+f"((c)[2]), "+f"((c)[3])      \
                 : "r"((a)[0]), "r"((a)[1]), "r"((a)[2]), "r"((a)[3]),         \
                   "r"(b0), "r"(b1))

__device__ __forceinline__ void h8_to_f(const uint4 v, float* f) {
    const __half2* h2 = (const __half2*)&v;
#pragma unroll
    for (int i = 0; i < 4; i++) {
        float2 x = __half22float2(h2[i]);
        f[i * 2 + 0] = x.x;
        f[i * 2 + 1] = x.y;
    }
}

// ---------------- setup: zero accumulators, mask sums, weight convert ------
// blocks [0,8): per-batch full mask sum; [8,72): zero g_S/g_sumsq;
// [72, 72+576): qkv weight fp32->fp16 row convert
__global__ void __launch_bounds__(256) setup_kernel(const float* __restrict__ mask,
                                                    const float* __restrict__ qkvw,
                                                    __half* __restrict__ Wb) {
    const int bid = blockIdx.x, t = threadIdx.x;
    if (bid < 8) {
        const int b = bid;
        const float4* m4 = (const float4*)(mask + (size_t)b * HW);
        float s = 0.f;
        for (int i = t; i < HW / 4; i += 256) {
            float4 v = m4[i];
            s += v.x + v.y + v.z + v.w;
        }
#pragma unroll
        for (int o = 16; o > 0; o >>= 1) s += __shfl_xor_sync(0xFFFFFFFFu, s, o);
        __shared__ float red[8];
        if ((t & 31) == 0) red[t >> 5] = s;
        __syncthreads();
        if (t == 0) {
            float tot = 0.f;
#pragma unroll
            for (int i = 0; i < 8; i++) tot += red[i];
            g_masksum[b] = tot;
        }
    } else if (bid < 72) {
        const int idx = (bid - 8) * 256 + t;
        for (int i = idx; i < BATCH * HEADS * CPH * CPH; i += 64 * 256) g_S[i] = 0.f;
        for (int i = idx; i < BATCH * 2 * CH; i += 64 * 256) g_sumsq[i] = 0.f;
    } else {
        const int m = bid - 72;
        if (t < CH)
            Wb[(size_t)m * CH + t] = __float2half_rn(qkvw[(size_t)m * CH + t]);
    }
}

// ---------------- pure streaming fp32 -> fp16 convert (planar, coalesced) --
__global__ void __launch_bounds__(256) convert_x(const float* __restrict__ X,
                                                 __half* __restrict__ Xh) {
    const size_t total4 = (size_t)BATCH * CH * HW / 4;
    for (size_t i = blockIdx.x * 256 + threadIdx.x; i < total4; i += (size_t)gridDim.x * 256) {
        float4 v = ((const float4*)X)[i];
        __half2 lo = __floats2half2_rn(v.x, v.y);
        __half2 hi = __floats2half2_rn(v.z, v.w);
        uint2 o;
        o.x = *(uint32_t*)&lo;
        o.y = *(uint32_t*)&hi;
        ((uint2*)Xh)[i] = o;
    }
}

// ---------------- unified planar-B fp16 GEMM via mma.sync ------------------
// Y[b,m,n] = A[m,:]·B[b,chanOff+ :,n] + bias[m]  (optionally * (1+tb*mask))
// A k-major [Mtot,192]; B channel-planar fp16 [(b*chanPB + chanOff + k)][HW]
// CTA tile 128x128, warp 64x32, 2 CTAs/SM. B via 272B-padded [k][n] + ldsm.trans
#define VB_ROW 272
#define VB_BYTES (64 * VB_ROW)
#define SM_VB (3 * 16384)
#define SMEM_GEMM (1024 + SM_VB + 2 * VB_BYTES)

template <typename OT, bool SCALE, bool ABATCH>
__global__ void __launch_bounds__(256, 2)
gemm_planar(const __half* __restrict__ Ball, const __half* __restrict__ A,
            const float* __restrict__ bias, OT* __restrict__ Y, int Mtot,
            int chanPB, int chanOff,
            const float* __restrict__ mask, const float* __restrict__ tbp) {
    extern __shared__ __align__(16) char smraw[];
    uint32_t sbr = smem_u32(smraw);
    uint32_t sb = (sbr + 1023) & ~1023u;
    const int t = threadIdx.x;
    const int warp = t >> 5, lane = t & 31;
    const int wm = warp >> 2, wn = warp & 3;      // warp tile m64 x n32
    const int b = blockIdx.z;
    const int M0 = blockIdx.x * 128;
    const int N0 = blockIdx.y * 128;
    const __half* vbase = Ball + (size_t)(b * chanPB + chanOff) * HW;
    const __half* Ab = A + (ABATCH ? (size_t)b * 256 * CH : 0);

    // A: 3 chunks of [128 m][64 k], SW128
#pragma unroll
    for (int i = 0; i < 12; i++) {
        int u = t + i * 256;
        int ca = u >> 10, v = u & 1023;
        int row = v >> 3, q = v & 7;
        const void* src = Ab + (size_t)(M0 + row) * CH + ca * 64 + q * 8;
        cp16(sb + ca * 16384 + SWZ(row * 128 + q * 16), src,
             (M0 + row < Mtot) ? 16 : 0);
    }
#define VB_LOAD(ca) do {                                                           \
        uint32_t _dst = sb + SM_VB + (uint32_t)((ca) & 1) * VB_BYTES;              \
        _Pragma("unroll")                                                          \
        for (int _i = 0; _i < 4; _i++) {                                           \
            int _u = t + _i * 256;                                                 \
            int _kr = _u >> 4, _q = _u & 15;                                       \
            cp16(_dst + _kr * VB_ROW + _q * 16,                                    \
                 vbase + (size_t)((ca) * 64 + _kr) * HW + N0 + _q * 8, 16);        \
        }                                                                          \
        CP_COMMIT();                                                               \
    } while (0)

    VB_LOAD(0);
    VB_LOAD(1);

    float acc[4][4][4];
#pragma unroll
    for (int i = 0; i < 4; i++)
#pragma unroll
        for (int j = 0; j < 4; j++)
#pragma unroll
            for (int k = 0; k < 4; k++) acc[i][j][k] = 0.f;

    for (int bi = 0; bi < 3; bi++) {
        if (bi < 2) asm volatile("cp.async.wait_group 1;" ::: "memory");
        else        asm volatile("cp.async.wait_group 0;" ::: "memory");
        __syncthreads();

        const uint32_t abuf = sb + (uint32_t)bi * 16384;
        const uint32_t vbuf = sb + SM_VB + (uint32_t)(bi & 1) * VB_BYTES;
#pragma unroll
        for (int kk = 0; kk < 4; kk++) {
            uint32_t af[4][4];
#pragma unroll
            for (int mf = 0; mf < 4; mf++) {
                int row = wm * 64 + mf * 16 + (lane & 7) + ((lane & 8) ? 8 : 0);
                int cb = kk * 32 + ((lane & 16) ? 16 : 0);
                LDSM4(af[mf][0], af[mf][1], af[mf][2], af[mf][3],
                      abuf + SWZ(row * 128 + cb));
            }
#pragma unroll
            for (int nf2 = 0; nf2 < 2; nf2++) {
                int krow = kk * 16 + (lane & 7) + ((lane & 8) ? 8 : 0);
                int ncol = wn * 32 + nf2 * 16 + ((lane & 16) ? 8 : 0);
                uint32_t b0, b1, b2, b3;
                LDSM4T(b0, b1, b2, b3, vbuf + krow * VB_ROW + ncol * 2);
#pragma unroll
                for (int mf = 0; mf < 4; mf++) {
                    MMA16816(acc[mf][nf2 * 2 + 0], af[mf], b0, b1);
                    MMA16816(acc[mf][nf2 * 2 + 1], af[mf], b2, b3);
                }
            }
        }
        __syncthreads();
        if (bi + 2 < 3) VB_LOAD(bi + 2);
    }
#undef VB_LOAD

    const int g = lane >> 2, tg = lane & 3;
    const int nbase = N0 + wn * 32 + tg * 2;
    float2 sp[4];
    if (SCALE) {
        const float tb = fminf(fmaxf(*tbp, 0.1f), 0.5f);
        const float* mrow = mask + (size_t)b * HW;
#pragma unroll
        for (int nf = 0; nf < 4; nf++) {
            sp[nf].x = 1.f + tb * mrow[nbase + nf * 8];
            sp[nf].y = 1.f + tb * mrow[nbase + nf * 8 + 1];
        }
    }
#pragma unroll
    for (int mf = 0; mf < 4; mf++) {
#pragma unroll
        for (int half = 0; half < 2; half++) {
            int m = M0 + wm * 64 + mf * 16 + g + half * 8;
            if (m < Mtot) {
                float bs = bias[m];
                OT* yrow = Y + ((size_t)b * Mtot + m) * HW + nbase;
#pragma unroll
                for (int nf = 0; nf < 4; nf++) {
                    float v0 = acc[mf][nf][half * 2 + 0];
                    float v1 = acc[mf][nf][half * 2 + 1];
                    if (SCALE) { v0 = v0 * sp[nf].x; v1 = v1 * sp[nf].y; }
                    v0 += bs; v1 += bs;
                    if constexpr (sizeof(OT) == 4)
                        *(float2*)(yrow + nf * 8) = make_float2(v0, v1);
                    else
                        *(__half2*)(yrow + nf * 8) = __floats2half2_rn(v0, v1);
                }
            }
        }
    }
}

// ---------------- 3x3 depthwise conv (groups=576), 32-row tiles, fp16 in/out
__global__ void __launch_bounds__(256) dwconv_kernel(const __half* __restrict__ in,
                                                     const float* __restrict__ w,
                                                     const float* __restrict__ bias,
                                                     __half* __restrict__ out) {
    const int b = blockIdx.z, ch = blockIdx.y;
    const int t = threadIdx.x;
    const int r0 = blockIdx.x * 32;
    __shared__ __align__(16) float sm[34][132];
    const __half* src = in + ((size_t)b * QKVC + ch) * HW;

#pragma unroll
    for (int i = 0; i < 3; i++) {
        int idx = t + i * 256;
        if (idx < 544) {
            int rr = idx >> 4, c8 = (idx & 15) * 8;
            int gr = r0 - 1 + rr;
            float f8[8] = {};
            if (gr >= 0 && gr < 128) {
                uint4 v = *(const uint4*)(src + gr * 128 + c8);
                h8_to_f(v, f8);
            }
#pragma unroll
            for (int j = 0; j < 8; j++) sm[rr][c8 + j] = f8[j];
        }
    }
    float wv[9];
#pragma unroll
    for (int i = 0; i < 9; i++) wv[i] = w[ch * 9 + i];
    const float bsv = bias[ch];
    __syncthreads();

    const int lr = (t >> 4) * 2;
    const int xo = (t & 15) * 8;
    float R[4][16];
#pragma unroll
    for (int dy = 0; dy < 4; dy++) {
        const float* row = sm[lr + dy];
        float4 v;
        v = (xo > 0) ? *(const float4*)(row + xo - 4) : make_float4(0, 0, 0, 0);
        R[dy][0] = v.x; R[dy][1] = v.y; R[dy][2] = v.z; R[dy][3] = v.w;
        v = *(const float4*)(row + xo);
        R[dy][4] = v.x; R[dy][5] = v.y; R[dy][6] = v.z; R[dy][7] = v.w;
        v = *(const float4*)(row + xo + 4);
        R[dy][8] = v.x; R[dy][9] = v.y; R[dy][10] = v.z; R[dy][11] = v.w;
        v = (xo < 120) ? *(const float4*)(row + xo + 8) : make_float4(0, 0, 0, 0);
        R[dy][12] = v.x; R[dy][13] = v.y; R[dy][14] = v.z; R[dy][15] = v.w;
    }
    float ss = 0.f;
#pragma unroll
    for (int rr2 = 0; rr2 < 2; rr2++) {
        float o[8];
#pragma unroll
        for (int i = 0; i < 8; i++) {
            float a = bsv;
#pragma unroll
            for (int dy = 0; dy < 3; dy++)
                a += wv[dy * 3 + 0] * R[rr2 + dy][3 + i] +
                     wv[dy * 3 + 1] * R[rr2 + dy][4 + i] +
                     wv[dy * 3 + 2] * R[rr2 + dy][5 + i];
            o[i] = a; ss += a * a;
        }
        __align__(16) __half oh[8];
#pragma unroll
        for (int i = 0; i < 8; i++) oh[i] = __float2half_rn(o[i]);
        *(uint4*)(out + ((size_t)b * QKVC + ch) * HW + (r0 + lr + rr2) * 128 + xo) =
            *(const uint4*)oh;
    }

    if (ch < 2 * CH) {
#pragma unroll
        for (int off = 16; off > 0; off >>= 1)
            ss += __shfl_xor_sync(0xFFFFFFFFu, ss, off);
        if ((t & 31) == 0) atomicAdd(&g_sumsq[b * 2 * CH + ch], ss);
    }
}

// ---------------- attention scores via mma.sync: S[bh] += q·k^T over split-K
#define ATM_SMEM (1024 + 2 * 16384)

__global__ void __launch_bounds__(256) attn_mma(const __half* __restrict__ qkv) {
    extern __shared__ __align__(16) char atraw[];
    uint32_t sbr = smem_u32(atraw);
    uint32_t sb = (sbr + 1023) & ~1023u;
    const int bh = blockIdx.y, b = bh >> 2, h = bh & 3;
    const int t = threadIdx.x;
    const int warp = t >> 5, lane = t & 31;
    const int wm = warp >> 2, wn = warp & 3;      // warp tile m32 x n16
    const __half* qbase = qkv + ((size_t)b * QKVC + h * CPH) * HW;
    const __half* kbase = qbase + (size_t)CH * HW;
    const int n0 = blockIdx.x * 1024;             // 16 iterations of k64

#define ATM_LOAD(it) do {                                                          \
        const int _nw = n0 + (it) * 64;                                            \
        _Pragma("unroll")                                                          \
        for (int _i = 0; _i < 4; _i++) {                                           \
            int _u = t + _i * 256;                                                 \
            int _isK = _u >= 512;                                                  \
            int _v = _u & 511;                                                     \
            int _row = _v >> 3, _q8 = _v & 7;                                      \
            const __half* _src = (_isK ? kbase : qbase) + (size_t)_row * HW + _nw + _q8 * 8; \
            cp16(sb + (uint32_t)((it) & 1) * 16384 + (_isK ? 8192 : 0) +           \
                     SWZ(_row * 128 + _q8 * 16),                                   \
                 _src, (_row < CPH) ? 16 : 0);                                     \
        }                                                                          \
        CP_COMMIT();                                                               \
    } while (0)

    ATM_LOAD(0);
    ATM_LOAD(1);

    float acc[2][2][4];
#pragma unroll
    for (int i = 0; i < 2; i++)
#pragma unroll
        for (int j = 0; j < 2; j++)
#pragma unroll
            for (int k = 0; k < 4; k++) acc[i][j][k] = 0.f;

    for (int bi = 0; bi < 16; bi++) {
        if (bi < 15) asm volatile("cp.async.wait_group 1;" ::: "memory");
        else         asm volatile("cp.async.wait_group 0;" ::: "memory");
        __syncthreads();
        const uint32_t qbuf = sb + (uint32_t)(bi & 1) * 16384;
        const uint32_t kbuf = qbuf + 8192;
#pragma unroll
        for (int kk = 0; kk < 4; kk++) {
            uint32_t af[2][4];
#pragma unroll
            for (int mf = 0; mf < 2; mf++) {
                int row = wm * 32 + mf * 16 + (lane & 7) + ((lane & 8) ? 8 : 0);
                int cb = kk * 32 + ((lane & 16) ? 16 : 0);
                LDSM4(af[mf][0], af[mf][1], af[mf][2], af[mf][3],
                      qbuf + SWZ(row * 128 + cb));
            }
            int rowb = wn * 16 + (lane & 7) + ((lane & 16) ? 8 : 0);
            int cbb = kk * 32 + ((lane & 8) ? 16 : 0);
            uint32_t b0, b1, b2, b3;
            LDSM4(b0, b1, b2, b3, kbuf + SWZ(rowb * 128 + cbb));
#pragma unroll
            for (int mf = 0; mf < 2; mf++) {
                MMA16816(acc[mf][0], af[mf], b0, b1);
                MMA16816(acc[mf][1], af[mf], b2, b3);
            }
        }
        __syncthreads();
        if (bi + 2 < 16) ATM_LOAD(bi + 2);
    }
#undef ATM_LOAD

    float* Sb = g_S + (size_t)bh * CPH * CPH;
    const int g = lane >> 2, tg = lane & 3;
#pragma unroll
    for (int mf = 0; mf < 2; mf++)
#pragma unroll
        for (int half = 0; half < 2; half++) {
            int m = wm * 32 + mf * 16 + g + half * 8;
            if (m < CPH) {
#pragma unroll
                for (int nf = 0; nf < 2; nf++)
#pragma unroll
                    for (int j = 0; j < 2; j++) {
                        int d = wn * 16 + nf * 8 + tg * 2 + j;
                        if (d < CPH)
                            atomicAdd(&Sb[m * CPH + d], acc[mf][nf][half * 2 + j]);
                    }
            }
        }
}

// ---------------- fused softmax (norm+temp) + Weff = W2 · blockdiag(A) -----
__global__ void __launch_bounds__(192) softmax_weff(const float* __restrict__ det,
                                                    const float* __restrict__ smo,
                                                    const float* __restrict__ W2,
                                                    __half* __restrict__ Weff) {
    const int b = blockIdx.x, t = threadIdx.x;   // 192 threads
    __shared__ float As[HEADS * CPH * CPH];       // 36.8KB

    // softmax for row (h, r) = (t/48, t%48)
    {
        const int h = t / CPH, r = t % CPH;
        const float tl = g_masksum[b] / (float)HW;
        const float temp = det[h] * tl + smo[h] * (1.f - tl);
        const float invq = 1.f / fmaxf(sqrtf(g_sumsq[b * 2 * CH + h * CPH + r]), 1e-12f);
        const float* Srow = g_S + ((size_t)(b * HEADS + h) * CPH + r) * CPH;
        float vals[CPH];
        float mx = -1e30f;
#pragma unroll
        for (int d = 0; d < CPH; d++) {
            float invk = 1.f / fmaxf(sqrtf(g_sumsq[b * 2 * CH + CH + h * CPH + d]), 1e-12f);
            float v = Srow[d] * invq * invk * temp;
            vals[d] = v;
            mx = fmaxf(mx, v);
        }
        float sum = 0.f;
#pragma unroll
        for (int d = 0; d < CPH; d++) { vals[d] = expf(vals[d] - mx); sum += vals[d]; }
        float inv = 1.f / sum;
        float* Arow = As + (h * CPH + r) * CPH;
#pragma unroll
        for (int d = 0; d < CPH; d++) Arow[d] = vals[d] * inv;
    }
    __syncthreads();

    // Weff row m = t
    const int m = t;
    __half* wrow_out = Weff + ((size_t)b * 256 + m) * CH;
#pragma unroll
    for (int h = 0; h < HEADS; h++) {
        float wr[CPH];
#pragma unroll
        for (int cc = 0; cc < CPH; cc++) wr[cc] = W2[(size_t)m * CH + h * CPH + cc];
        const float* Ah = As + h * CPH * CPH;
        for (int d0 = 0; d0 < CPH; d0 += 4) {
            float s0 = 0.f, s1 = 0.f, s2 = 0.f, s3 = 0.f;
#pragma unroll
            for (int cc = 0; cc < CPH; cc++) {
                float w = wr[cc];
                const float* ar = Ah + cc * CPH + d0;
                s0 += w * ar[0]; s1 += w * ar[1];
                s2 += w * ar[2]; s3 += w * ar[3];
            }
            wrow_out[h * CPH + d0 + 0] = __float2half_rn(s0);
            wrow_out[h * CPH + d0 + 1] = __float2half_rn(s1);
            wrow_out[h * CPH + d0 + 2] = __float2half_rn(s2);
            wrow_out[h * CPH + d0 + 3] = __float2half_rn(s3);
        }
    }
}

// ---------------- host launcher ----------------
extern "C" void kernel_launch(void* const* d_in, const int* in_sizes, int n_in,
                              void* d_out, int out_size) {
    const float* x    = (const float*)d_in[0];
    const float* mask = (const float*)d_in[1];
    const float* qkvw = (const float*)d_in[2];
    const float* qkvb = (const float*)d_in[3];
    const float* dww  = (const float*)d_in[4];
    const float* dwb  = (const float*)d_in[5];
    const float* outw = (const float*)d_in[6];
    const float* outb = (const float*)d_in[7];
    const float* det  = (const float*)d_in[8];
    const float* smo  = (const float*)d_in[9];
    const float* tbp  = (const float*)d_in[10];
    float* y = (float*)d_out;

    void *p_q0 = nullptr, *p_q1 = nullptr, *p_xh = nullptr, *p_wb = nullptr, *p_we = nullptr;
    cudaGetSymbolAddress(&p_q0, g_q0h);
    cudaGetSymbolAddress(&p_q1, g_q1h);
    cudaGetSymbolAddress(&p_xh, g_xh4);
    cudaGetSymbolAddress(&p_wb, g_wb4);
    cudaGetSymbolAddress(&p_we, g_weff);

    auto gemm_qkv = gemm_planar<__half, false, false>;
    auto gemm_out = gemm_planar<float, true, true>;
    cudaFuncSetAttribute(gemm_qkv, cudaFuncAttributeMaxDynamicSharedMemorySize, SMEM_GEMM);
    cudaFuncSetAttribute(gemm_out, cudaFuncAttributeMaxDynamicSharedMemorySize, SMEM_GEMM);
    cudaFuncSetAttribute(attn_mma, cudaFuncAttributeMaxDynamicSharedMemorySize, ATM_SMEM);

    // setup: mask sums + zeroing + qkv weight convert (one launch)
    setup_kernel<<<72 + QKVC, 256>>>(mask, qkvw, (__half*)p_wb);
    // x fp32 -> fp16 planar (pure streaming)
    convert_x<<<6144, 256>>>(x, (__half*)p_xh);
    // qkv 1x1 conv: planar-B fp16 GEMM -> fp16 planar output
    gemm_qkv<<<dim3(5, HW / 128, BATCH), 256, SMEM_GEMM>>>(
        (const __half*)p_xh, (const __half*)p_wb, qkvb, (__half*)p_q0, QKVC,
        CH, 0, nullptr, nullptr);
    // 3x3 depthwise (+ fused q/k sum-of-squares)
    dwconv_kernel<<<dim3(4, QKVC, BATCH), 256>>>(
        (const __half*)p_q0, dww, dwb, (__half*)p_q1);
    // channel attention scores via tensor cores (16-way split-K)
    attn_mma<<<dim3(16, BATCH * HEADS), 256, ATM_SMEM>>>((const __half*)p_q1);
    // softmax + Weff fold (one launch)
    softmax_weff<<<BATCH, 192>>>(det, smo, outw, (__half*)p_we);
    // y = (Weff @ v) * s(n) + outb
    gemm_out<<<dim3(2, HW / 128, BATCH), 256, SMEM_GEMM>>>(
        (const __half*)p_q1, (const __half*)p_we, outb, y, CH,
        QKVC, 2 * CH, mask, tbp);
}

// round 11
// speedup vs baseline: 6.5996x; 1.0205x over previous
#include <cuda_runtime.h>
#include <cuda_fp16.h>
#include <math.h>
#include <stdint.h>

// Problem constants
#define BATCH 8
#define CH    192
#define QKVC  576
#define HW    16384
#define HEADS 4
#define CPH   48

// ---------------- scratch (static device memory; no allocs) ----------------
__device__ uint4 g_q0h[(size_t)BATCH * QKVC * HW * 2 / 16];   // fp16 qkv after 1x1 (planar)
__device__ uint4 g_q1h[(size_t)BATCH * QKVC * HW * 2 / 16];   // fp16 qkv after dw (planar)
__device__ float g_sumsq[BATCH * 2 * CH];
__device__ float g_S[BATCH * HEADS * CPH * CPH];
__device__ float g_masksum[BATCH];
__device__ uint4 g_xh4[(size_t)BATCH * CH * HW * 2 / 16];     // [B][192][HW] fp16 planar
__device__ uint4 g_wb4[(size_t)(QKVC + 64) * CH * 2 / 16];    // [576(+pad)][192] fp16
__device__ uint4 g_weff[(size_t)BATCH * 256 * CH * 2 / 16];   // [B][192(+pad)][192] fp16

// ---------------- helpers ----------------
__device__ __forceinline__ uint32_t smem_u32(const void* p) {
    uint32_t a;
    asm("{ .reg .u64 t; cvta.to.shared.u64 t, %1; cvt.u32.u64 %0, t; }" : "=r"(a) : "l"(p));
    return a;
}
#define SWZ(off) ((off) ^ (((off) >> 3) & 0x70))

__device__ __forceinline__ void cp16(uint32_t dst, const void* src, int srcsz) {
    asm volatile("cp.async.cg.shared.global [%0], [%1], 16, %2;"
                 :: "r"(dst), "l"(src), "r"(srcsz) : "memory");
}
#define CP_COMMIT() asm volatile("cp.async.commit_group;" ::: "memory")

#define LDSM4(r0, r1, r2, r3, addr)                                            \
    asm volatile("ldmatrix.sync.aligned.m8n8.x4.shared.b16 {%0,%1,%2,%3}, [%4];" \
                 : "=r"(r0), "=r"(r1), "=r"(r2), "=r"(r3) : "r"(addr))

#define LDSM4T(r0, r1, r2, r3, addr)                                           \
    asm volatile("ldmatrix.sync.aligned.m8n8.x4.trans.shared.b16 {%0,%1,%2,%3}, [%4];" \
                 : "=r"(r0), "=r"(r1), "=r"(r2), "=r"(r3) : "r"(addr))

#define MMA16816(c, a, b0, b1)                                                 \
    asm volatile("mma.sync.aligned.m16n8k16.row.col.f32.f16.f16.f32 "          \
                 "{%0,%1,%2,%3},{%4,%5,%6,%7},{%8,%9},{%0,%1,%2,%3};"          \
                 : "+f"((c)[0]), "+f"((c)[1]), "+f"((c)[2]), "+f"((c)[3])      \
                 : "r"((a)[0]), "r"((a)[1]), "r"((a)[2]), "r"((a)[3]),         \
                   "r"(b0), "r"(b1))

__device__ __forceinline__ void h8_to_f2(const uint4 v, float4* lo, float4* hi) {
    const __half2* h2 = (const __half2*)&v;
    float2 a = __half22float2(h2[0]);
    float2 b = __half22float2(h2[1]);
    float2 c = __half22float2(h2[2]);
    float2 d = __half22float2(h2[3]);
    *lo = make_float4(a.x, a.y, b.x, b.y);
    *hi = make_float4(c.x, c.y, d.x, d.y);
}

// ---------------- setup: mask sums, zeroing, weight convert, x fp32->fp16 --
// blocks [0,8): per-batch mask sum; [8,72): zero g_S/g_sumsq;
// [72, 648): qkv weight convert rows; [648, 648+6144): x convert (streaming)
__global__ void __launch_bounds__(256) setup_kernel(const float* __restrict__ mask,
                                                    const float* __restrict__ qkvw,
                                                    __half* __restrict__ Wb,
                                                    const float* __restrict__ X,
                                                    __half* __restrict__ Xh) {
    const int bid = blockIdx.x, t = threadIdx.x;
    if (bid >= 648) {
        // x fp32 -> fp16 planar convert (grid-stride over 6144 blocks)
        const size_t total4 = (size_t)BATCH * CH * HW / 4;
        for (size_t i = (size_t)(bid - 648) * 256 + t; i < total4; i += (size_t)6144 * 256) {
            float4 v = ((const float4*)X)[i];
            __half2 lo = __floats2half2_rn(v.x, v.y);
            __half2 hi = __floats2half2_rn(v.z, v.w);
            uint2 o;
            o.x = *(uint32_t*)&lo;
            o.y = *(uint32_t*)&hi;
            ((uint2*)Xh)[i] = o;
        }
    } else if (bid < 8) {
        const int b = bid;
        const float4* m4 = (const float4*)(mask + (size_t)b * HW);
        float s = 0.f;
        for (int i = t; i < HW / 4; i += 256) {
            float4 v = m4[i];
            s += v.x + v.y + v.z + v.w;
        }
#pragma unroll
        for (int o = 16; o > 0; o >>= 1) s += __shfl_xor_sync(0xFFFFFFFFu, s, o);
        __shared__ float red[8];
        if ((t & 31) == 0) red[t >> 5] = s;
        __syncthreads();
        if (t == 0) {
            float tot = 0.f;
#pragma unroll
            for (int i = 0; i < 8; i++) tot += red[i];
            g_masksum[b] = tot;
        }
    } else if (bid < 72) {
        const int idx = (bid - 8) * 256 + t;
        for (int i = idx; i < BATCH * HEADS * CPH * CPH; i += 64 * 256) g_S[i] = 0.f;
        for (int i = idx; i < BATCH * 2 * CH; i += 64 * 256) g_sumsq[i] = 0.f;
    } else {
        const int m = bid - 72;
        if (t < CH)
            Wb[(size_t)m * CH + t] = __float2half_rn(qkvw[(size_t)m * CH + t]);
    }
}

// ---------------- unified planar-B fp16 GEMM via mma.sync ------------------
#define VB_ROW 272
#define VB_BYTES (64 * VB_ROW)
#define SM_VB (3 * 16384)
#define SMEM_GEMM (1024 + SM_VB + 2 * VB_BYTES)

template <typename OT, bool SCALE, bool ABATCH>
__global__ void __launch_bounds__(256, 2)
gemm_planar(const __half* __restrict__ Ball, const __half* __restrict__ A,
            const float* __restrict__ bias, OT* __restrict__ Y, int Mtot,
            int chanPB, int chanOff,
            const float* __restrict__ mask, const float* __restrict__ tbp) {
    extern __shared__ __align__(16) char smraw[];
    uint32_t sbr = smem_u32(smraw);
    uint32_t sb = (sbr + 1023) & ~1023u;
    const int t = threadIdx.x;
    const int warp = t >> 5, lane = t & 31;
    const int wm = warp >> 2, wn = warp & 3;      // warp tile m64 x n32
    const int b = blockIdx.z;
    const int M0 = blockIdx.x * 128;
    const int N0 = blockIdx.y * 128;
    const __half* vbase = Ball + (size_t)(b * chanPB + chanOff) * HW;
    const __half* Ab = A + (ABATCH ? (size_t)b * 256 * CH : 0);

#pragma unroll
    for (int i = 0; i < 12; i++) {
        int u = t + i * 256;
        int ca = u >> 10, v = u & 1023;
        int row = v >> 3, q = v & 7;
        const void* src = Ab + (size_t)(M0 + row) * CH + ca * 64 + q * 8;
        cp16(sb + ca * 16384 + SWZ(row * 128 + q * 16), src,
             (M0 + row < Mtot) ? 16 : 0);
    }
#define VB_LOAD(ca) do {                                                           \
        uint32_t _dst = sb + SM_VB + (uint32_t)((ca) & 1) * VB_BYTES;              \
        _Pragma("unroll")                                                          \
        for (int _i = 0; _i < 4; _i++) {                                           \
            int _u = t + _i * 256;                                                 \
            int _kr = _u >> 4, _q = _u & 15;                                       \
            cp16(_dst + _kr * VB_ROW + _q * 16,                                    \
                 vbase + (size_t)((ca) * 64 + _kr) * HW + N0 + _q * 8, 16);        \
        }                                                                          \
        CP_COMMIT();                                                               \
    } while (0)

    VB_LOAD(0);
    VB_LOAD(1);

    float acc[4][4][4];
#pragma unroll
    for (int i = 0; i < 4; i++)
#pragma unroll
        for (int j = 0; j < 4; j++)
#pragma unroll
            for (int k = 0; k < 4; k++) acc[i][j][k] = 0.f;

    for (int bi = 0; bi < 3; bi++) {
        if (bi < 2) asm volatile("cp.async.wait_group 1;" ::: "memory");
        else        asm volatile("cp.async.wait_group 0;" ::: "memory");
        __syncthreads();

        const uint32_t abuf = sb + (uint32_t)bi * 16384;
        const uint32_t vbuf = sb + SM_VB + (uint32_t)(bi & 1) * VB_BYTES;
#pragma unroll
        for (int kk = 0; kk < 4; kk++) {
            uint32_t af[4][4];
#pragma unroll
            for (int mf = 0; mf < 4; mf++) {
                int row = wm * 64 + mf * 16 + (lane & 7) + ((lane & 8) ? 8 : 0);
                int cb = kk * 32 + ((lane & 16) ? 16 : 0);
                LDSM4(af[mf][0], af[mf][1], af[mf][2], af[mf][3],
                      abuf + SWZ(row * 128 + cb));
            }
#pragma unroll
            for (int nf2 = 0; nf2 < 2; nf2++) {
                int krow = kk * 16 + (lane & 7) + ((lane & 8) ? 8 : 0);
                int ncol = wn * 32 + nf2 * 16 + ((lane & 16) ? 8 : 0);
                uint32_t b0, b1, b2, b3;
                LDSM4T(b0, b1, b2, b3, vbuf + krow * VB_ROW + ncol * 2);
#pragma unroll
                for (int mf = 0; mf < 4; mf++) {
                    MMA16816(acc[mf][nf2 * 2 + 0], af[mf], b0, b1);
                    MMA16816(acc[mf][nf2 * 2 + 1], af[mf], b2, b3);
                }
            }
        }
        __syncthreads();
        if (bi + 2 < 3) VB_LOAD(bi + 2);
    }
#undef VB_LOAD

    const int g = lane >> 2, tg = lane & 3;
    const int nbase = N0 + wn * 32 + tg * 2;
    float2 sp[4];
    if (SCALE) {
        const float tb = fminf(fmaxf(*tbp, 0.1f), 0.5f);
        const float* mrow = mask + (size_t)b * HW;
#pragma unroll
        for (int nf = 0; nf < 4; nf++) {
            sp[nf].x = 1.f + tb * mrow[nbase + nf * 8];
            sp[nf].y = 1.f + tb * mrow[nbase + nf * 8 + 1];
        }
    }
#pragma unroll
    for (int mf = 0; mf < 4; mf++) {
#pragma unroll
        for (int half = 0; half < 2; half++) {
            int m = M0 + wm * 64 + mf * 16 + g + half * 8;
            if (m < Mtot) {
                float bs = bias[m];
                OT* yrow = Y + ((size_t)b * Mtot + m) * HW + nbase;
#pragma unroll
                for (int nf = 0; nf < 4; nf++) {
                    float v0 = acc[mf][nf][half * 2 + 0];
                    float v1 = acc[mf][nf][half * 2 + 1];
                    if (SCALE) { v0 = v0 * sp[nf].x; v1 = v1 * sp[nf].y; }
                    v0 += bs; v1 += bs;
                    if constexpr (sizeof(OT) == 4)
                        *(float2*)(yrow + nf * 8) = make_float2(v0, v1);
                    else
                        *(__half2*)(yrow + nf * 8) = __floats2half2_rn(v0, v1);
                }
            }
        }
    }
}

// ---------------- 3x3 depthwise conv (groups=576), 32-row tiles, fp16 in/out
// smem fill fully vectorized: each uint4 of 8 halves -> two float4 STS.128
__global__ void __launch_bounds__(256) dwconv_kernel(const __half* __restrict__ in,
                                                     const float* __restrict__ w,
                                                     const float* __restrict__ bias,
                                                     __half* __restrict__ out) {
    const int b = blockIdx.z, ch = blockIdx.y;
    const int t = threadIdx.x;
    const int r0 = blockIdx.x * 32;
    __shared__ __align__(16) float sm[34][132];
    const __half* src = in + ((size_t)b * QKVC + ch) * HW;

#pragma unroll
    for (int i = 0; i < 3; i++) {
        int idx = t + i * 256;
        if (idx < 544) {                          // 34 rows x 16 uint4 (8 halves)
            int rr = idx >> 4, c8 = (idx & 15) * 8;
            int gr = r0 - 1 + rr;
            float4 lo = make_float4(0, 0, 0, 0), hi = lo;
            if (gr >= 0 && gr < 128) {
                uint4 v = *(const uint4*)(src + gr * 128 + c8);
                h8_to_f2(v, &lo, &hi);
            }
            *(float4*)&sm[rr][c8] = lo;           // 16B-aligned (132%4==0, c8%8==0)
            *(float4*)&sm[rr][c8 + 4] = hi;
        }
    }
    float wv[9];
#pragma unroll
    for (int i = 0; i < 9; i++) wv[i] = w[ch * 9 + i];
    const float bsv = bias[ch];
    __syncthreads();

    const int lr = (t >> 4) * 2;
    const int xo = (t & 15) * 8;
    float R[4][16];
#pragma unroll
    for (int dy = 0; dy < 4; dy++) {
        const float* row = sm[lr + dy];
        float4 v;
        v = (xo > 0) ? *(const float4*)(row + xo - 4) : make_float4(0, 0, 0, 0);
        R[dy][0] = v.x; R[dy][1] = v.y; R[dy][2] = v.z; R[dy][3] = v.w;
        v = *(const float4*)(row + xo);
        R[dy][4] = v.x; R[dy][5] = v.y; R[dy][6] = v.z; R[dy][7] = v.w;
        v = *(const float4*)(row + xo + 4);
        R[dy][8] = v.x; R[dy][9] = v.y; R[dy][10] = v.z; R[dy][11] = v.w;
        v = (xo < 120) ? *(const float4*)(row + xo + 8) : make_float4(0, 0, 0, 0);
        R[dy][12] = v.x; R[dy][13] = v.y; R[dy][14] = v.z; R[dy][15] = v.w;
    }
    float ss = 0.f;
#pragma unroll
    for (int rr2 = 0; rr2 < 2; rr2++) {
        float o[8];
#pragma unroll
        for (int i = 0; i < 8; i++) {
            float a = bsv;
#pragma unroll
            for (int dy = 0; dy < 3; dy++)
                a += wv[dy * 3 + 0] * R[rr2 + dy][3 + i] +
                     wv[dy * 3 + 1] * R[rr2 + dy][4 + i] +
                     wv[dy * 3 + 2] * R[rr2 + dy][5 + i];
            o[i] = a; ss += a * a;
        }
        __align__(16) __half oh[8];
#pragma unroll
        for (int i = 0; i < 8; i++) oh[i] = __float2half_rn(o[i]);
        *(uint4*)(out + ((size_t)b * QKVC + ch) * HW + (r0 + lr + rr2) * 128 + xo) =
            *(const uint4*)oh;
    }

    if (ch < 2 * CH) {
#pragma unroll
        for (int off = 16; off > 0; off >>= 1)
            ss += __shfl_xor_sync(0xFFFFFFFFu, ss, off);
        if ((t & 31) == 0) atomicAdd(&g_sumsq[b * 2 * CH + ch], ss);
    }
}

// ---------------- attention scores via mma.sync: S[bh] += q·k^T over split-K
#define ATM_SMEM (1024 + 2 * 16384)

__global__ void __launch_bounds__(256) attn_mma(const __half* __restrict__ qkv) {
    extern __shared__ __align__(16) char atraw[];
    uint32_t sbr = smem_u32(atraw);
    uint32_t sb = (sbr + 1023) & ~1023u;
    const int bh = blockIdx.y, b = bh >> 2, h = bh & 3;
    const int t = threadIdx.x;
    const int warp = t >> 5, lane = t & 31;
    const int wm = warp >> 2, wn = warp & 3;      // warp tile m32 x n16
    const __half* qbase = qkv + ((size_t)b * QKVC + h * CPH) * HW;
    const __half* kbase = qbase + (size_t)CH * HW;
    const int n0 = blockIdx.x * 1024;             // 16 iterations of k64

#define ATM_LOAD(it) do {                                                          \
        const int _nw = n0 + (it) * 64;                                            \
        _Pragma("unroll")                                                          \
        for (int _i = 0; _i < 4; _i++) {                                           \
            int _u = t + _i * 256;                                                 \
            int _isK = _u >= 512;                                                  \
            int _v = _u & 511;                                                     \
            int _row = _v >> 3, _q8 = _v & 7;                                      \
            const __half* _src = (_isK ? kbase : qbase) + (size_t)_row * HW + _nw + _q8 * 8; \
            cp16(sb + (uint32_t)((it) & 1) * 16384 + (_isK ? 8192 : 0) +           \
                     SWZ(_row * 128 + _q8 * 16),                                   \
                 _src, (_row < CPH) ? 16 : 0);                                     \
        }                                                                          \
        CP_COMMIT();                                                               \
    } while (0)

    ATM_LOAD(0);
    ATM_LOAD(1);

    float acc[2][2][4];
#pragma unroll
    for (int i = 0; i < 2; i++)
#pragma unroll
        for (int j = 0; j < 2; j++)
#pragma unroll
            for (int k = 0; k < 4; k++) acc[i][j][k] = 0.f;

    for (int bi = 0; bi < 16; bi++) {
        if (bi < 15) asm volatile("cp.async.wait_group 1;" ::: "memory");
        else         asm volatile("cp.async.wait_group 0;" ::: "memory");
        __syncthreads();
        const uint32_t qbuf = sb + (uint32_t)(bi & 1) * 16384;
        const uint32_t kbuf = qbuf + 8192;
#pragma unroll
        for (int kk = 0; kk < 4; kk++) {
            uint32_t af[2][4];
#pragma unroll
            for (int mf = 0; mf < 2; mf++) {
                int row = wm * 32 + mf * 16 + (lane & 7) + ((lane & 8) ? 8 : 0);
                int cb = kk * 32 + ((lane & 16) ? 16 : 0);
                LDSM4(af[mf][0], af[mf][1], af[mf][2], af[mf][3],
                      qbuf + SWZ(row * 128 + cb));
            }
            int rowb = wn * 16 + (lane & 7) + ((lane & 16) ? 8 : 0);
            int cbb = kk * 32 + ((lane & 8) ? 16 : 0);
            uint32_t b0, b1, b2, b3;
            LDSM4(b0, b1, b2, b3, kbuf + SWZ(rowb * 128 + cbb));
#pragma unroll
            for (int mf = 0; mf < 2; mf++) {
                MMA16816(acc[mf][0], af[mf], b0, b1);
                MMA16816(acc[mf][1], af[mf], b2, b3);
            }
        }
        __syncthreads();
        if (bi + 2 < 16) ATM_LOAD(bi + 2);
    }
#undef ATM_LOAD

    float* Sb = g_S + (size_t)bh * CPH * CPH;
    const int g = lane >> 2, tg = lane & 3;
#pragma unroll
    for (int mf = 0; mf < 2; mf++)
#pragma unroll
        for (int half = 0; half < 2; half++) {
            int m = wm * 32 + mf * 16 + g + half * 8;
            if (m < CPH) {
#pragma unroll
                for (int nf = 0; nf < 2; nf++)
#pragma unroll
                    for (int j = 0; j < 2; j++) {
                        int d = wn * 16 + nf * 8 + tg * 2 + j;
                        if (d < CPH)
                            atomicAdd(&Sb[m * CPH + d], acc[mf][nf][half * 2 + j]);
                    }
            }
        }
}

// ---------------- fused softmax (norm+temp) + Weff = W2 · blockdiag(A) -----
__global__ void __launch_bounds__(192) softmax_weff(const float* __restrict__ det,
                                                    const float* __restrict__ smo,
                                                    const float* __restrict__ W2,
                                                    __half* __restrict__ Weff) {
    const int b = blockIdx.x, t = threadIdx.x;   // 192 threads
    __shared__ float As[HEADS * CPH * CPH];

    {
        const int h = t / CPH, r = t % CPH;
        const float tl = g_masksum[b] / (float)HW;
        const float temp = det[h] * tl + smo[h] * (1.f - tl);
        const float invq = 1.f / fmaxf(sqrtf(g_sumsq[b * 2 * CH + h * CPH + r]), 1e-12f);
        const float* Srow = g_S + ((size_t)(b * HEADS + h) * CPH + r) * CPH;
        float vals[CPH];
        float mx = -1e30f;
#pragma unroll
        for (int d = 0; d < CPH; d++) {
            float invk = 1.f / fmaxf(sqrtf(g_sumsq[b * 2 * CH + CH + h * CPH + d]), 1e-12f);
            float v = Srow[d] * invq * invk * temp;
            vals[d] = v;
            mx = fmaxf(mx, v);
        }
        float sum = 0.f;
#pragma unroll
        for (int d = 0; d < CPH; d++) { vals[d] = expf(vals[d] - mx); sum += vals[d]; }
        float inv = 1.f / sum;
        float* Arow = As + (h * CPH + r) * CPH;
#pragma unroll
        for (int d = 0; d < CPH; d++) Arow[d] = vals[d] * inv;
    }
    __syncthreads();

    const int m = t;
    __half* wrow_out = Weff + ((size_t)b * 256 + m) * CH;
#pragma unroll
    for (int h = 0; h < HEADS; h++) {
        float wr[CPH];
#pragma unroll
        for (int cc = 0; cc < CPH; cc++) wr[cc] = W2[(size_t)m * CH + h * CPH + cc];
        const float* Ah = As + h * CPH * CPH;
        for (int d0 = 0; d0 < CPH; d0 += 4) {
            float s0 = 0.f, s1 = 0.f, s2 = 0.f, s3 = 0.f;
#pragma unroll
            for (int cc = 0; cc < CPH; cc++) {
                float w = wr[cc];
                const float* ar = Ah + cc * CPH + d0;
                s0 += w * ar[0]; s1 += w * ar[1];
                s2 += w * ar[2]; s3 += w * ar[3];
            }
            wrow_out[h * CPH + d0 + 0] = __float2half_rn(s0);
            wrow_out[h * CPH + d0 + 1] = __float2half_rn(s1);
            wrow_out[h * CPH + d0 + 2] = __float2half_rn(s2);
            wrow_out[h * CPH + d0 + 3] = __float2half_rn(s3);
        }
    }
}

// ---------------- host launcher ----------------
extern "C" void kernel_launch(void* const* d_in, const int* in_sizes, int n_in,
                              void* d_out, int out_size) {
    const float* x    = (const float*)d_in[0];
    const float* mask = (const float*)d_in[1];
    const float* qkvw = (const float*)d_in[2];
    const float* qkvb = (const float*)d_in[3];
    const float* dww  = (const float*)d_in[4];
    const float* dwb  = (const float*)d_in[5];
    const float* outw = (const float*)d_in[6];
    const float* outb = (const float*)d_in[7];
    const float* det  = (const float*)d_in[8];
    const float* smo  = (const float*)d_in[9];
    const float* tbp  = (const float*)d_in[10];
    float* y = (float*)d_out;

    void *p_q0 = nullptr, *p_q1 = nullptr, *p_xh = nullptr, *p_wb = nullptr, *p_we = nullptr;
    cudaGetSymbolAddress(&p_q0, g_q0h);
    cudaGetSymbolAddress(&p_q1, g_q1h);
    cudaGetSymbolAddress(&p_xh, g_xh4);
    cudaGetSymbolAddress(&p_wb, g_wb4);
    cudaGetSymbolAddress(&p_we, g_weff);

    auto gemm_qkv = gemm_planar<__half, false, false>;
    auto gemm_out = gemm_planar<float, true, true>;
    cudaFuncSetAttribute(gemm_qkv, cudaFuncAttributeMaxDynamicSharedMemorySize, SMEM_GEMM);
    cudaFuncSetAttribute(gemm_out, cudaFuncAttributeMaxDynamicSharedMemorySize, SMEM_GEMM);
    cudaFuncSetAttribute(attn_mma, cudaFuncAttributeMaxDynamicSharedMemorySize, ATM_SMEM);

    // setup: mask sums + zeroing + weight convert + x fp32->fp16 (one launch)
    setup_kernel<<<648 + 6144, 256>>>(mask, qkvw, (__half*)p_wb, x, (__half*)p_xh);
    // qkv 1x1 conv: planar-B fp16 GEMM -> fp16 planar output
    gemm_qkv<<<dim3(5, HW / 128, BATCH), 256, SMEM_GEMM>>>(
        (const __half*)p_xh, (const __half*)p_wb, qkvb, (__half*)p_q0, QKVC,
        CH, 0, nullptr, nullptr);
    // 3x3 depthwise (+ fused q/k sum-of-squares), vectorized smem fill
    dwconv_kernel<<<dim3(4, QKVC, BATCH), 256>>>(
        (const __half*)p_q0, dww, dwb, (__half*)p_q1);
    // channel attention scores via tensor cores (16-way split-K)
    attn_mma<<<dim3(16, BATCH * HEADS), 256, ATM_SMEM>>>((const __half*)p_q1);
    // softmax + Weff fold (one launch)
    softmax_weff<<<BATCH, 192>>>(det, smo, outw, (__half*)p_we);
    // y = (Weff @ v) * s(n) + outb
    gemm_out<<<dim3(2, HW / 128, BATCH), 256, SMEM_GEMM>>>(
        (const __half*)p_q1, (const __half*)p_we, outb, y, CH,
        QKVC, 2 * CH, mask, tbp);
}